// round 9
// baseline (speedup 1.0000x reference)
#include <cuda_runtime.h>
#include <cuda_fp16.h>
#include <cstdint>
#include <math.h>

#define BATCH 2048
#define DM    1024
#define RNUM  64
#define KH    3072          // concat K in halfs
#define KT    64            // k-tile in halfs (128 B rows)
#define NKT   (KH / KT)     // 48
#define ABLK  8192          // A tile block halfs (128 x 64) = 16 KB
#define BBLK  16384         // B tile block halfs (256 x 64) = 32 KB
#define STGB  49152         // stage bytes (A+B)
#define CSTR  257
#define TIE_EPS 8e-6f
#define MAXF  16384
#define SMEMSZ (1024 + 3 * STGB)
#define SC    64.0f
#define FIXSMEM (4096 + 65536 + 2048)

// ---------------- device scratch ----------------
__device__ float  g_dv[BATCH * DM];
__device__ __half g_xc[BATCH * KH];           // tiled [mtile][kt][row128][64] swizzled
__device__ __half g_wpc[RNUM * 256 * KH];     // tiled [r][kt][row256][64]
__device__ __half g_wc[2 * DM * KH];          // tiled [nt8][kt][row256][64]
__device__ int    g_cnt;
__device__ int2   g_flags[MAXF];

// ---------------- helpers ----------------
__device__ __forceinline__ uint32_t smem_u32(const void* p) {
    uint32_t a;
    asm("{ .reg .u64 t; cvta.to.shared.u64 t, %1; cvt.u32.u64 %0, t; }" : "=r"(a) : "l"(p));
    return a;
}
// within-16 fragment permutation (logical k -> concat position)
__device__ __forceinline__ int sp16(int k) {
    return (k & ~15) | ((k & 6) << 1) | ((k & 8) >> 2) | (k & 1);
}
__device__ __forceinline__ void lds64(uint32_t& r0, uint32_t& r1, uint32_t a) {
    asm volatile("ld.shared.v2.b32 {%0,%1}, [%2];" : "=r"(r0), "=r"(r1) : "r"(a));
}
#define MBAR_INIT(a, c) asm volatile("mbarrier.init.shared.b64 [%0], %1;" :: "r"(a), "r"(c) : "memory")
#define MBAR_EXPECT(a, b) asm volatile("mbarrier.arrive.expect_tx.shared.b64 _, [%0], %1;" :: "r"(a), "r"(b) : "memory")
#define BULK(dst, src, sz, mb) \
    asm volatile("cp.async.bulk.shared::cluster.global.mbarrier::complete_tx::bytes [%0], [%1], %2, [%3];" \
                 :: "r"(dst), "l"(src), "r"(sz), "r"(mb) : "memory")
__device__ __forceinline__ void mbar_wait(uint32_t a, uint32_t ph) {
    asm volatile(
        "{\n.reg .pred P;\n"
        "WL%=:\n"
        "mbarrier.try_wait.parity.acquire.cta.shared::cta.b64 P, [%0], %1, 0x989680;\n"
        "@P bra WD%=;\n"
        "bra WL%=;\n"
        "WD%=:\n}"
        :: "r"(a), "r"(ph) : "memory");
}

#define MMA_F16(c, a0, a1, a2, a3, b0, b1) \
    asm volatile("mma.sync.aligned.m16n8k16.row.col.f32.f16.f16.f32 " \
        "{%0,%1,%2,%3}, {%4,%5,%6,%7}, {%8,%9}, {%0,%1,%2,%3};" \
        : "+f"((c)[0]), "+f"((c)[1]), "+f"((c)[2]), "+f"((c)[3]) \
        : "r"(a0), "r"(a1), "r"(a2), "r"(a3), "r"(b0), "r"(b1))

// ---------------- prep kernels (write tiled + swizzled layouts) ----------------
__device__ __forceinline__ size_t a_idx(int m, int p) {
    int row = m & 127;
    return ((size_t)((m >> 7) * NKT + (p >> 6)) * 128 + row) * 64 +
           ((p & 63) ^ ((row & 3) << 4));
}
__device__ __forceinline__ size_t b_idx(int blk, int row, int p) {
    return ((size_t)(blk * NKT + (p >> 6)) * 256 + row) * 64 +
           ((p & 63) ^ ((row & 3) << 4));
}

__global__ void conv_x(const float* __restrict__ x) {
    int g = blockIdx.x * 256 + threadIdx.x;
    if (g == 0) g_cnt = 0;
    int m = g >> 10, k = g & 1023;
    float v = x[g];
    __half hh = __float2half_rn(v);
    float hf = __half2float(hh);
    int p = sp16(k);
    g_xc[a_idx(m, p)]        = hh;
    g_xc[a_idx(m, p + 1024)] = __float2half_rn(hf * (1.0f / SC));
    g_xc[a_idx(m, p + 2048)] = __float2half_rn((v - hf) * SC);
}

__global__ void tr_wp(const float* __restrict__ Wp) {
    __shared__ float t[32][33];
    int n0 = blockIdx.x * 32, k0 = blockIdx.y * 32;
    int tx = threadIdx.x, ty = threadIdx.y;
    #pragma unroll
    for (int i = 0; i < 4; i++)
        t[ty + i * 8][tx] = Wp[(size_t)(k0 + ty + i * 8) * (RNUM * 256) + n0 + tx];
    __syncthreads();
    #pragma unroll
    for (int i = 0; i < 4; i++) {
        int rr = ty + i * 8;
        int n = n0 + rr;
        float v = t[tx][rr];
        __half hh = __float2half_rn(v);
        float hf = __half2float(hh);
        int p = sp16(k0 + tx);
        int r = n >> 8, nr = n & 255;
        g_wpc[b_idx(r, nr, p)]        = hh;
        g_wpc[b_idx(r, nr, p + 1024)] = __float2half_rn((v - hf) * SC);
        g_wpc[b_idx(r, nr, p + 2048)] = __float2half_rn(hf * (1.0f / SC));
    }
}

__global__ void tr_wc(const float* __restrict__ Wd, const float* __restrict__ Wa) {
    __shared__ float t[2][32][33];
    int n0 = blockIdx.x * 32, k0 = blockIdx.y * 32;
    int tx = threadIdx.x, ty = threadIdx.y;
    #pragma unroll
    for (int i = 0; i < 4; i++) {
        int rr = ty + i * 8;
        t[0][rr][tx] = Wd[(size_t)(k0 + rr) * DM + n0 + tx];
        t[1][rr][tx] = Wa[(size_t)(k0 + rr) * DM + n0 + tx];
    }
    __syncthreads();
    #pragma unroll
    for (int i = 0; i < 4; i++) {
        int rr = ty + i * 8;
        int p = sp16(k0 + tx);
        #pragma unroll
        for (int s = 0; s < 2; s++) {
            float v = t[s][tx][rr];
            __half hh = __float2half_rn(v);
            float hf = __half2float(hh);
            int col2 = 2 * (n0 + rr) + s;
            int nt = col2 >> 8, row = col2 & 255;
            g_wc[b_idx(nt, row, p)]        = hh;
            g_wc[b_idx(nt, row, p + 1024)] = __float2half_rn((v - hf) * SC);
            g_wc[b_idx(nt, row, p + 2048)] = __float2half_rn(hf * (1.0f / SC));
        }
    }
}

// ---------------- GEMM core ----------------
__device__ __forceinline__ void compute_tile(uint32_t sA, uint32_t sB,
                                             int wm, int wn, int gid, int qc,
                                             float acc[4][8][4]) {
    #pragma unroll
    for (int ks = 0; ks < 4; ks++) {
        uint32_t sw = (uint32_t)(ks * 32 + qc * 8) ^ (uint32_t)((gid & 3) << 5);
        uint32_t A0[4], A1[4], A2[4], A3[4], B0[8], B1[8];
        #pragma unroll
        for (int fm = 0; fm < 4; fm++) {
            uint32_t a = sA + (wm + fm * 16 + gid) * 128 + sw;
            lds64(A0[fm], A2[fm], a);
            lds64(A1[fm], A3[fm], a + 8 * 128);
        }
        #pragma unroll
        for (int fn = 0; fn < 8; fn++)
            lds64(B0[fn], B1[fn], sB + (wn + fn * 8 + gid) * 128 + sw);
        #pragma unroll
        for (int fm = 0; fm < 4; fm++)
            #pragma unroll
            for (int fn = 0; fn < 8; fn++)
                MMA_F16(acc[fm][fn], A0[fm], A1[fm], A2[fm], A3[fm], B0[fn], B1[fn]);
    }
}

// 3-stage bulk-copy pipeline, one barrier per k-tile
#define GEMM_MAINLOOP(Ablocks, Bblocks)                                         \
    float acc[4][8][4] = {};                                                    \
    if (tid == 0) {                                                             \
        MBAR_INIT(sb + 16, 1); MBAR_INIT(sb + 24, 1); MBAR_INIT(sb + 32, 1);    \
    }                                                                           \
    __syncthreads();                                                            \
    if (tid == 0) {                                                             \
        _Pragma("unroll")                                                       \
        for (int s = 0; s < 2; s++) {                                           \
            uint32_t mb = sb + 16 + 8 * s, st = sb + 1024 + s * STGB;           \
            MBAR_EXPECT(mb, STGB);                                              \
            BULK(st, (const char*)(Ablocks + (size_t)s * ABLK), 16384, mb);     \
            BULK(st + 16384, (const char*)(Bblocks + (size_t)s * BBLK), 32768, mb); \
        }                                                                       \
    }                                                                           \
    for (int kt = 0; kt < NKT; kt++) {                                          \
        int s = kt % 3;                                                         \
        mbar_wait(sb + 16 + 8 * s, (kt / 3) & 1);                               \
        __syncthreads();                                                        \
        if (kt + 2 < NKT && tid == 0) {                                         \
            int s2 = (kt + 2) % 3;                                              \
            uint32_t mb = sb + 16 + 8 * s2, st = sb + 1024 + s2 * STGB;         \
            MBAR_EXPECT(mb, STGB);                                              \
            BULK(st, (const char*)(Ablocks + (size_t)(kt + 2) * ABLK), 16384, mb); \
            BULK(st + 16384, (const char*)(Bblocks + (size_t)(kt + 2) * BBLK), 32768, mb); \
        }                                                                       \
        uint32_t st = sb + 1024 + s * STGB;                                     \
        compute_tile(st, st + 16384, wm, wn, gid, qc, acc);                     \
    }                                                                           \
    __syncthreads();

// ---------------- diag kernel ----------------
__global__ __launch_bounds__(256, 1) void diag_mma() {
    extern __shared__ __align__(1024) char smem[];
    uint32_t sb = smem_u32(smem);
    const int tid = threadIdx.x, wid = tid >> 5, lane = tid & 31;
    const int m0 = blockIdx.x * 128, nt = blockIdx.y;
    const int wm = (wid & 1) * 64, wn = (wid >> 1) * 64;
    const int gid = lane >> 2, qc = lane & 3;
    const int n0 = nt * 256;

    const __half* Ab = g_xc + (size_t)blockIdx.x * NKT * ABLK;
    const __half* Bb = g_wc + (size_t)nt * NKT * BBLK;
    GEMM_MAINLOOP(Ab, Bb)

    #pragma unroll
    for (int fm = 0; fm < 4; fm++)
        #pragma unroll
        for (int fn = 0; fn < 8; fn++) {
            int mm = m0 + wm + fm * 16 + gid;
            int tcol = (n0 + wn + fn * 8 + 2 * qc) >> 1;
            float* c = acc[fm][fn];
            float s0 = 1.0f / (1.0f + expf(-c[1]));
            float s1 = 1.0f / (1.0f + expf(-c[3]));
            g_dv[(size_t)mm * DM + tcol]       = s0 * tanhf(c[0]);
            g_dv[(size_t)(mm + 8) * DM + tcol] = s1 * tanhf(c[2]);
        }
}

// ---------------- perm kernel ----------------
__global__ __launch_bounds__(256, 1) void perm_mma(const float* __restrict__ h,
                                                   float* __restrict__ out) {
    extern __shared__ __align__(1024) char smem[];
    uint32_t sb = smem_u32(smem);
    const int tid = threadIdx.x, wid = tid >> 5, lane = tid & 31;
    const int m0 = blockIdx.x * 128, r = blockIdx.y;
    const int wm = (wid & 1) * 64, wn = (wid >> 1) * 64;
    const int gid = lane >> 2, qc = lane & 3;

    const __half* Ab = g_xc + (size_t)blockIdx.x * NKT * ABLK;
    const __half* Bb = g_wpc + (size_t)r * NKT * BBLK;
    GEMM_MAINLOOP(Ab, Bb)

    float* Csm = (float*)smem;
    #pragma unroll
    for (int fm = 0; fm < 4; fm++)
        #pragma unroll
        for (int fn = 0; fn < 8; fn++) {
            int mm = wm + fm * 16 + gid, nn = wn + fn * 8 + 2 * qc;
            float* c = acc[fm][fn];
            Csm[mm * CSTR + nn]           = c[0];
            Csm[mm * CSTR + nn + 1]       = c[1];
            Csm[(mm + 8) * CSTR + nn]     = c[2];
            Csm[(mm + 8) * CSTR + nn + 1] = c[3];
        }
    __syncthreads();

    // ---- sinkhorn + argmax (+ near-tie flag) + permute ----
    const int j = lane & 15, gb = (lane >> 4) << 4;
    const unsigned FULL = 0xffffffffu;

    #pragma unroll 1
    for (int pass = 0; pass < 8; pass++) {
        int m = pass * 16 + (tid >> 4);
        float la[16];
        #pragma unroll
        for (int i = 0; i < 16; i++)
            la[i] = 2.0f * Csm[m * CSTR + i * 16 + j];   // /TAU (TAU=0.5)

        #pragma unroll 1
        for (int it = 0; it < 5; it++) {
            #pragma unroll
            for (int i = 0; i < 16; i++) {
                float mx = la[i];
                mx = fmaxf(mx, __shfl_xor_sync(FULL, mx, 1));
                mx = fmaxf(mx, __shfl_xor_sync(FULL, mx, 2));
                mx = fmaxf(mx, __shfl_xor_sync(FULL, mx, 4));
                mx = fmaxf(mx, __shfl_xor_sync(FULL, mx, 8));
                float e = __expf(la[i] - mx);
                e += __shfl_xor_sync(FULL, e, 1);
                e += __shfl_xor_sync(FULL, e, 2);
                e += __shfl_xor_sync(FULL, e, 4);
                e += __shfl_xor_sync(FULL, e, 8);
                la[i] -= mx + __logf(e);
            }
            if (it < 4) {   // final col-norm is argmax-invariant: skip
                float mx = la[0];
                #pragma unroll
                for (int i = 1; i < 16; i++) mx = fmaxf(mx, la[i]);
                float ssum = 0.f;
                #pragma unroll
                for (int i = 0; i < 16; i++) ssum += __expf(la[i] - mx);
                float sub = mx + __logf(ssum);
                #pragma unroll
                for (int i = 0; i < 16; i++) la[i] -= sub;
            }
        }

        int best = 0; float bv = la[0], sv = -1e30f;
        #pragma unroll
        for (int i = 1; i < 16; i++) {
            if (la[i] > bv) { sv = bv; bv = la[i]; best = i; }
            else if (la[i] > sv) sv = la[i];
        }

        int bg = m0 + m;

        unsigned bal = __ballot_sync(FULL, (bv - sv) < TIE_EPS);
        if (((bal >> gb) & 0xFFFFu) && lane == gb) {
            int idx = atomicAdd(&g_cnt, 1);
            if (idx < MAXF) g_flags[idx] = make_int2(bg, r);
        }

        float hv = h[(size_t)bg * DM + r * 16 + j];
        float hp = 0.f;
        #pragma unroll
        for (int jj = 0; jj < 16; jj++) {
            int   ib = __shfl_sync(FULL, best, gb + jj);
            float hj = __shfl_sync(FULL, hv,   gb + jj);
            if (ib == j) hp += hj;
        }
        int oi = bg * DM + r * 16 + j;
        out[oi] = g_dv[oi] * hp;
    }
}

// ---------------- exact fixup: smem-staged coalesced, fp64 accum ----------------
__global__ __launch_bounds__(256) void fixup(const float* __restrict__ x,
                                             const float* __restrict__ Wp,
                                             const float* __restrict__ h,
                                             float* __restrict__ out) {
    extern __shared__ char fsm[];
    float*  xs = (float*)fsm;                      // 1024 floats
    float*  ws = (float*)(fsm + 4096);             // 64 x 256 floats
    double* Ls = (double*)(fsm + 4096 + 65536);    // 256 doubles
    int n = g_cnt; if (n > MAXF) n = MAXF;
    const int tid = threadIdx.x;

    for (int f = blockIdx.x; f < n; f += gridDim.x) {
        int bg = g_flags[f].x, r = g_flags[f].y;
        __syncthreads();
        for (int k = tid; k < 1024; k += 256) xs[k] = x[(size_t)bg * DM + k];

        double s0 = 0, s1 = 0, s2 = 0, s3 = 0;
        #pragma unroll 1
        for (int kc = 0; kc < 1024; kc += 64) {
            __syncthreads();
            #pragma unroll
            for (int i = 0; i < 16; i++) {           // 64 rows x 64 float4
                int idx = tid + i * 256;
                int row = idx >> 6, c4 = idx & 63;
                *(float4*)&ws[row * 256 + c4 * 4] =
                    *(const float4*)(Wp + (size_t)(kc + row) * (RNUM * 256) + r * 256 + c4 * 4);
            }
            __syncthreads();
            #pragma unroll
            for (int rr = 0; rr < 64; rr += 4) {
                s0 += (double)xs[kc + rr + 0] * (double)ws[(rr + 0) * 256 + tid];
                s1 += (double)xs[kc + rr + 1] * (double)ws[(rr + 1) * 256 + tid];
                s2 += (double)xs[kc + rr + 2] * (double)ws[(rr + 2) * 256 + tid];
                s3 += (double)xs[kc + rr + 3] * (double)ws[(rr + 3) * 256 + tid];
            }
        }
        Ls[tid] = 2.0 * ((s0 + s1) + (s2 + s3));
        __syncthreads();

        if (tid < 16) {
            const unsigned M16 = 0xFFFFu;
            int j = tid;
            double L[16];
            #pragma unroll
            for (int i = 0; i < 16; i++) L[i] = Ls[i * 16 + j];
            #pragma unroll 1
            for (int it = 0; it < 5; it++) {
                #pragma unroll 1
                for (int i = 0; i < 16; i++) {
                    double mx = L[i];
                    mx = fmax(mx, __shfl_xor_sync(M16, mx, 1));
                    mx = fmax(mx, __shfl_xor_sync(M16, mx, 2));
                    mx = fmax(mx, __shfl_xor_sync(M16, mx, 4));
                    mx = fmax(mx, __shfl_xor_sync(M16, mx, 8));
                    double e = exp(L[i] - mx);
                    e += __shfl_xor_sync(M16, e, 1);
                    e += __shfl_xor_sync(M16, e, 2);
                    e += __shfl_xor_sync(M16, e, 4);
                    e += __shfl_xor_sync(M16, e, 8);
                    L[i] -= mx + log(e);
                }
                if (it < 4) {
                    double mx = L[0];
                    #pragma unroll
                    for (int i = 1; i < 16; i++) mx = fmax(mx, L[i]);
                    double ss = 0.0;
                    #pragma unroll
                    for (int i = 0; i < 16; i++) ss += exp(L[i] - mx);
                    double sub = mx + log(ss);
                    #pragma unroll
                    for (int i = 0; i < 16; i++) L[i] -= sub;
                }
            }
            int best = 0; double bv = L[0];
            #pragma unroll
            for (int i = 1; i < 16; i++)
                if (L[i] > bv) { bv = L[i]; best = i; }

            float hv = h[(size_t)bg * DM + r * 16 + j];
            float hp = 0.f;
            #pragma unroll
            for (int jj = 0; jj < 16; jj++) {
                int   ib = __shfl_sync(M16, best, jj);
                float hj = __shfl_sync(M16, hv,   jj);
                if (ib == j) hp += hj;
            }
            int oi = bg * DM + r * 16 + j;
            out[oi] = g_dv[oi] * hp;
        }
    }
}

// ---------------- launch ----------------
extern "C" void kernel_launch(void* const* d_in, const int* in_sizes, int n_in,
                              void* d_out, int out_size) {
    const float* x  = (const float*)d_in[0];
    const float* h  = (const float*)d_in[1];
    const float* Wp = (const float*)d_in[2];
    const float* Wd = (const float*)d_in[3];
    const float* Wa = (const float*)d_in[4];
    float* out = (float*)d_out;

    cudaFuncSetAttribute(perm_mma, cudaFuncAttributeMaxDynamicSharedMemorySize, SMEMSZ);
    cudaFuncSetAttribute(diag_mma, cudaFuncAttributeMaxDynamicSharedMemorySize, SMEMSZ);
    cudaFuncSetAttribute(fixup,    cudaFuncAttributeMaxDynamicSharedMemorySize, FIXSMEM);

    conv_x<<<BATCH * DM / 256, 256>>>(x);
    tr_wp<<<dim3(512, 32), dim3(32, 8)>>>(Wp);
    tr_wc<<<dim3(32, 32), dim3(32, 8)>>>(Wd, Wa);
    diag_mma<<<dim3(16, 8), 256, SMEMSZ>>>();
    perm_mma<<<dim3(16, 64), 256, SMEMSZ>>>(h, out);
    fixup<<<512, 256, FIXSMEM>>>(x, Wp, h, out);
}

// round 10
// speedup vs baseline: 1.0467x; 1.0467x over previous
#include <cuda_runtime.h>
#include <cuda_fp16.h>
#include <cstdint>
#include <math.h>

#define BATCH 2048
#define DM    1024
#define RNUM  64
#define KH    3072          // concat K in halfs
#define KT    64            // k-tile in halfs (128 B rows)
#define NKT   (KH / KT)     // 48
#define ABLK  8192          // A tile block halfs (128 x 64) = 16 KB
#define BBLK  16384         // B tile block halfs (256 x 64) = 32 KB
#define STGB  49152         // stage bytes (A+B)
#define CSTR  257
#define MAXF  16384
#define SMEMSZ (1024 + 3 * STGB)
#define SC    64.0f
#define FIXSMEM (4096 + 65536 + 2048)

// ---------------- device scratch ----------------
__device__ float  g_dv[BATCH * DM];
__device__ __half g_xc[BATCH * KH];           // tiled [mtile][kt][row128][64] swizzled
__device__ __half g_wpc[RNUM * 256 * KH];     // tiled [r][kt][row256][64]
__device__ __half g_wc[2 * DM * KH];          // tiled [nt8][kt][row256][64]
__device__ int    g_cnt;
__device__ int2   g_flags[MAXF];

// ---------------- helpers ----------------
__device__ __forceinline__ uint32_t smem_u32(const void* p) {
    uint32_t a;
    asm("{ .reg .u64 t; cvta.to.shared.u64 t, %1; cvt.u32.u64 %0, t; }" : "=r"(a) : "l"(p));
    return a;
}
__device__ __forceinline__ int sp16(int k) {
    return (k & ~15) | ((k & 6) << 1) | ((k & 8) >> 2) | (k & 1);
}
__device__ __forceinline__ void lds64(uint32_t& r0, uint32_t& r1, uint32_t a) {
    asm volatile("ld.shared.v2.b32 {%0,%1}, [%2];" : "=r"(r0), "=r"(r1) : "r"(a));
}
// precise e^x via FMA-only polynomial (immune to -use_fast_math), x clamped low
__device__ __forceinline__ float exp_p(float x) {
    x = fmaxf(x, -80.0f);
    float n = rintf(x * 1.4426950408889634f);
    float r = fmaf(n, -0.693359375f, x);
    r = fmaf(n, 2.12194440e-4f, r);
    float p = 1.9875691500e-4f;
    p = fmaf(p, r, 1.3981999507e-3f);
    p = fmaf(p, r, 8.3334519073e-3f);
    p = fmaf(p, r, 4.1665795894e-2f);
    p = fmaf(p, r, 1.6666665459e-1f);
    p = fmaf(p, r, 5.0000001201e-1f);
    float q = fmaf(p, r * r, r) + 1.0f;
    return q * __int_as_float(((int)n + 127) << 23);
}
// full-precision reciprocal: rcp.approx + one Newton step
__device__ __forceinline__ float rcp_p(float x) {
    float r;
    asm("rcp.approx.f32 %0, %1;" : "=f"(r) : "f"(x));
    float e = fmaf(-x, r, 1.0f);
    return fmaf(r, e, r);
}
#define MBAR_INIT(a, c) asm volatile("mbarrier.init.shared.b64 [%0], %1;" :: "r"(a), "r"(c) : "memory")
#define MBAR_EXPECT(a, b) asm volatile("mbarrier.arrive.expect_tx.shared.b64 _, [%0], %1;" :: "r"(a), "r"(b) : "memory")
#define BULK(dst, src, sz, mb) \
    asm volatile("cp.async.bulk.shared::cluster.global.mbarrier::complete_tx::bytes [%0], [%1], %2, [%3];" \
                 :: "r"(dst), "l"(src), "r"(sz), "r"(mb) : "memory")
__device__ __forceinline__ void mbar_wait(uint32_t a, uint32_t ph) {
    asm volatile(
        "{\n.reg .pred P;\n"
        "WL%=:\n"
        "mbarrier.try_wait.parity.acquire.cta.shared::cta.b64 P, [%0], %1, 0x989680;\n"
        "@P bra WD%=;\n"
        "bra WL%=;\n"
        "WD%=:\n}"
        :: "r"(a), "r"(ph) : "memory");
}

#define MMA_F16(c, a0, a1, a2, a3, b0, b1) \
    asm volatile("mma.sync.aligned.m16n8k16.row.col.f32.f16.f16.f32 " \
        "{%0,%1,%2,%3}, {%4,%5,%6,%7}, {%8,%9}, {%0,%1,%2,%3};" \
        : "+f"((c)[0]), "+f"((c)[1]), "+f"((c)[2]), "+f"((c)[3]) \
        : "r"(a0), "r"(a1), "r"(a2), "r"(a3), "r"(b0), "r"(b1))

// ---------------- prep kernels ----------------
__device__ __forceinline__ size_t a_idx(int m, int p) {
    int row = m & 127;
    return ((size_t)((m >> 7) * NKT + (p >> 6)) * 128 + row) * 64 +
           ((p & 63) ^ ((row & 3) << 4));
}
__device__ __forceinline__ size_t b_idx(int blk, int row, int p) {
    return ((size_t)(blk * NKT + (p >> 6)) * 256 + row) * 64 +
           ((p & 63) ^ ((row & 3) << 4));
}

__global__ void conv_x(const float* __restrict__ x) {
    int g = blockIdx.x * 256 + threadIdx.x;
    if (g == 0) g_cnt = 0;
    int m = g >> 10, k = g & 1023;
    float v = x[g];
    __half hh = __float2half_rn(v);
    float hf = __half2float(hh);
    int p = sp16(k);
    g_xc[a_idx(m, p)]        = hh;
    g_xc[a_idx(m, p + 1024)] = __float2half_rn(hf * (1.0f / SC));
    g_xc[a_idx(m, p + 2048)] = __float2half_rn((v - hf) * SC);
}

__global__ void tr_wp(const float* __restrict__ Wp) {
    __shared__ float t[32][33];
    int n0 = blockIdx.x * 32, k0 = blockIdx.y * 32;
    int tx = threadIdx.x, ty = threadIdx.y;
    #pragma unroll
    for (int i = 0; i < 4; i++)
        t[ty + i * 8][tx] = Wp[(size_t)(k0 + ty + i * 8) * (RNUM * 256) + n0 + tx];
    __syncthreads();
    #pragma unroll
    for (int i = 0; i < 4; i++) {
        int rr = ty + i * 8;
        int n = n0 + rr;
        float v = t[tx][rr];
        __half hh = __float2half_rn(v);
        float hf = __half2float(hh);
        int p = sp16(k0 + tx);
        int r = n >> 8, nr = n & 255;
        g_wpc[b_idx(r, nr, p)]        = hh;
        g_wpc[b_idx(r, nr, p + 1024)] = __float2half_rn((v - hf) * SC);
        g_wpc[b_idx(r, nr, p + 2048)] = __float2half_rn(hf * (1.0f / SC));
    }
}

__global__ void tr_wc(const float* __restrict__ Wd, const float* __restrict__ Wa) {
    __shared__ float t[2][32][33];
    int n0 = blockIdx.x * 32, k0 = blockIdx.y * 32;
    int tx = threadIdx.x, ty = threadIdx.y;
    #pragma unroll
    for (int i = 0; i < 4; i++) {
        int rr = ty + i * 8;
        t[0][rr][tx] = Wd[(size_t)(k0 + rr) * DM + n0 + tx];
        t[1][rr][tx] = Wa[(size_t)(k0 + rr) * DM + n0 + tx];
    }
    __syncthreads();
    #pragma unroll
    for (int i = 0; i < 4; i++) {
        int rr = ty + i * 8;
        int p = sp16(k0 + tx);
        #pragma unroll
        for (int s = 0; s < 2; s++) {
            float v = t[s][tx][rr];
            __half hh = __float2half_rn(v);
            float hf = __half2float(hh);
            int col2 = 2 * (n0 + rr) + s;
            int nt = col2 >> 8, row = col2 & 255;
            g_wc[b_idx(nt, row, p)]        = hh;
            g_wc[b_idx(nt, row, p + 1024)] = __float2half_rn((v - hf) * SC);
            g_wc[b_idx(nt, row, p + 2048)] = __float2half_rn(hf * (1.0f / SC));
        }
    }
}

// ---------------- GEMM core (ks-pipelined fragment loads) ----------------
__device__ __forceinline__ void load_frag(uint32_t sA, uint32_t sB, int ks,
                                          int wm, int wn, int gid, int qc,
                                          uint32_t A0[4], uint32_t A1[4],
                                          uint32_t A2[4], uint32_t A3[4],
                                          uint32_t B0[8], uint32_t B1[8]) {
    uint32_t sw = (uint32_t)(ks * 32 + qc * 8) ^ (uint32_t)((gid & 3) << 5);
    #pragma unroll
    for (int fm = 0; fm < 4; fm++) {
        uint32_t a = sA + (wm + fm * 16 + gid) * 128 + sw;
        lds64(A0[fm], A2[fm], a);
        lds64(A1[fm], A3[fm], a + 8 * 128);
    }
    #pragma unroll
    for (int fn = 0; fn < 8; fn++)
        lds64(B0[fn], B1[fn], sB + (wn + fn * 8 + gid) * 128 + sw);
}

__device__ __forceinline__ void compute_tile(uint32_t sA, uint32_t sB,
                                             int wm, int wn, int gid, int qc,
                                             float acc[4][8][4]) {
    uint32_t A0[2][4], A1[2][4], A2[2][4], A3[2][4], B0[2][8], B1[2][8];
    load_frag(sA, sB, 0, wm, wn, gid, qc, A0[0], A1[0], A2[0], A3[0], B0[0], B1[0]);
    #pragma unroll
    for (int ks = 0; ks < 4; ks++) {
        int cur = ks & 1, nxt = cur ^ 1;
        if (ks < 3)
            load_frag(sA, sB, ks + 1, wm, wn, gid, qc,
                      A0[nxt], A1[nxt], A2[nxt], A3[nxt], B0[nxt], B1[nxt]);
        #pragma unroll
        for (int fm = 0; fm < 4; fm++)
            #pragma unroll
            for (int fn = 0; fn < 8; fn++)
                MMA_F16(acc[fm][fn], A0[cur][fm], A1[cur][fm], A2[cur][fm],
                        A3[cur][fm], B0[cur][fn], B1[cur][fn]);
    }
}

// 3-stage bulk-copy pipeline, one barrier per k-tile
#define GEMM_MAINLOOP(Ablocks, Bblocks)                                         \
    float acc[4][8][4] = {};                                                    \
    if (tid == 0) {                                                             \
        MBAR_INIT(sb + 16, 1); MBAR_INIT(sb + 24, 1); MBAR_INIT(sb + 32, 1);    \
    }                                                                           \
    __syncthreads();                                                            \
    if (tid == 0) {                                                             \
        _Pragma("unroll")                                                       \
        for (int s = 0; s < 2; s++) {                                           \
            uint32_t mb = sb + 16 + 8 * s, st = sb + 1024 + s * STGB;           \
            MBAR_EXPECT(mb, STGB);                                              \
            BULK(st, (const char*)(Ablocks + (size_t)s * ABLK), 16384, mb);     \
            BULK(st + 16384, (const char*)(Bblocks + (size_t)s * BBLK), 32768, mb); \
        }                                                                       \
    }                                                                           \
    for (int kt = 0; kt < NKT; kt++) {                                          \
        int s = kt % 3;                                                         \
        mbar_wait(sb + 16 + 8 * s, (kt / 3) & 1);                               \
        __syncthreads();                                                        \
        if (kt + 2 < NKT && tid == 0) {                                         \
            int s2 = (kt + 2) % 3;                                              \
            uint32_t mb = sb + 16 + 8 * s2, st = sb + 1024 + s2 * STGB;         \
            MBAR_EXPECT(mb, STGB);                                              \
            BULK(st, (const char*)(Ablocks + (size_t)(kt + 2) * ABLK), 16384, mb); \
            BULK(st + 16384, (const char*)(Bblocks + (size_t)(kt + 2) * BBLK), 32768, mb); \
        }                                                                       \
        uint32_t st = sb + 1024 + s * STGB;                                     \
        compute_tile(st, st + 16384, wm, wn, gid, qc, acc);                     \
    }                                                                           \
    __syncthreads();

// ---------------- diag kernel ----------------
__global__ __launch_bounds__(256, 1) void diag_mma() {
    extern __shared__ __align__(1024) char smem[];
    uint32_t sb = smem_u32(smem);
    const int tid = threadIdx.x, wid = tid >> 5, lane = tid & 31;
    const int m0 = blockIdx.x * 128, nt = blockIdx.y;
    const int wm = (wid & 1) * 64, wn = (wid >> 1) * 64;
    const int gid = lane >> 2, qc = lane & 3;
    const int n0 = nt * 256;

    const __half* Ab = g_xc + (size_t)blockIdx.x * NKT * ABLK;
    const __half* Bb = g_wc + (size_t)nt * NKT * BBLK;
    GEMM_MAINLOOP(Ab, Bb)

    #pragma unroll
    for (int fm = 0; fm < 4; fm++)
        #pragma unroll
        for (int fn = 0; fn < 8; fn++) {
            int mm = m0 + wm + fm * 16 + gid;
            int tcol = (n0 + wn + fn * 8 + 2 * qc) >> 1;
            float* c = acc[fm][fn];
            float s0 = 1.0f / (1.0f + expf(-c[1]));
            float s1 = 1.0f / (1.0f + expf(-c[3]));
            g_dv[(size_t)mm * DM + tcol]       = s0 * tanhf(c[0]);
            g_dv[(size_t)(mm + 8) * DM + tcol] = s1 * tanhf(c[2]);
        }
}

// ---------------- perm kernel ----------------
__global__ __launch_bounds__(256, 1) void perm_mma(const float* __restrict__ h,
                                                   float* __restrict__ out) {
    extern __shared__ __align__(1024) char smem[];
    uint32_t sb = smem_u32(smem);
    const int tid = threadIdx.x, wid = tid >> 5, lane = tid & 31;
    const int m0 = blockIdx.x * 128, r = blockIdx.y;
    const int wm = (wid & 1) * 64, wn = (wid >> 1) * 64;
    const int gid = lane >> 2, qc = lane & 3;

    const __half* Ab = g_xc + (size_t)blockIdx.x * NKT * ABLK;
    const __half* Bb = g_wpc + (size_t)r * NKT * BBLK;
    GEMM_MAINLOOP(Ab, Bb)

    float* Csm = (float*)smem;
    #pragma unroll
    for (int fm = 0; fm < 4; fm++)
        #pragma unroll
        for (int fn = 0; fn < 8; fn++) {
            int mm = wm + fm * 16 + gid, nn = wn + fn * 8 + 2 * qc;
            float* c = acc[fm][fn];
            Csm[mm * CSTR + nn]           = c[0];
            Csm[mm * CSTR + nn + 1]       = c[1];
            Csm[(mm + 8) * CSTR + nn]     = c[2];
            Csm[(mm + 8) * CSTR + nn + 1] = c[3];
        }
    __syncthreads();

    // ---- probability-domain sinkhorn + argmax (+ near-tie flag) + permute ----
    const int j = lane & 15, gb = (lane >> 4) << 4;
    const unsigned FULL = 0xffffffffu;

    #pragma unroll 1
    for (int pass = 0; pass < 8; pass++) {
        int m = pass * 16 + (tid >> 4);
        float p[16];
        // load logits (x2 for /TAU), subtract exact per-row max, exp once
        #pragma unroll
        for (int i = 0; i < 16; i++) {
            float la = 2.0f * Csm[m * CSTR + i * 16 + j];
            float mx = la;
            mx = fmaxf(mx, __shfl_xor_sync(FULL, mx, 1));
            mx = fmaxf(mx, __shfl_xor_sync(FULL, mx, 2));
            mx = fmaxf(mx, __shfl_xor_sync(FULL, mx, 4));
            mx = fmaxf(mx, __shfl_xor_sync(FULL, mx, 8));
            p[i] = exp_p(la - mx);
        }

        #pragma unroll 1
        for (int it = 0; it < 5; it++) {
            // row normalization (sum over columns j = across 16 lanes)
            #pragma unroll
            for (int i = 0; i < 16; i++) {
                float s = p[i];
                s += __shfl_xor_sync(FULL, s, 1);
                s += __shfl_xor_sync(FULL, s, 2);
                s += __shfl_xor_sync(FULL, s, 4);
                s += __shfl_xor_sync(FULL, s, 8);
                p[i] *= rcp_p(s);
            }
            if (it < 4) {   // final col-norm is argmax-invariant: skip
                float s = p[0];
                #pragma unroll
                for (int i = 1; i < 16; i++) s += p[i];
                float rc = rcp_p(s);
                #pragma unroll
                for (int i = 0; i < 16; i++) p[i] *= rc;
            }
        }

        int best = 0; float bv = p[0], sv = -1e30f;
        #pragma unroll
        for (int i = 1; i < 16; i++) {
            if (p[i] > bv) { sv = bv; bv = p[i]; best = i; }
            else if (p[i] > sv) sv = p[i];
        }

        int bg = m0 + m;

        unsigned bal = __ballot_sync(FULL, (bv - sv) < 4e-6f * bv);
        if (((bal >> gb) & 0xFFFFu) && lane == gb) {
            int idx = atomicAdd(&g_cnt, 1);
            if (idx < MAXF) g_flags[idx] = make_int2(bg, r);
        }

        float hv = h[(size_t)bg * DM + r * 16 + j];
        float hp = 0.f;
        #pragma unroll
        for (int jj = 0; jj < 16; jj++) {
            int   ib = __shfl_sync(FULL, best, gb + jj);
            float hj = __shfl_sync(FULL, hv,   gb + jj);
            if (ib == j) hp += hj;
        }
        int oi = bg * DM + r * 16 + j;
        out[oi] = g_dv[oi] * hp;
    }
}

// ---------------- exact fixup: smem-staged coalesced, fp64 accum ----------------
__global__ __launch_bounds__(256) void fixup(const float* __restrict__ x,
                                             const float* __restrict__ Wp,
                                             const float* __restrict__ h,
                                             float* __restrict__ out) {
    extern __shared__ char fsm[];
    float*  xs = (float*)fsm;                      // 1024 floats
    float*  ws = (float*)(fsm + 4096);             // 64 x 256 floats
    double* Ls = (double*)(fsm + 4096 + 65536);    // 256 doubles
    int n = g_cnt; if (n > MAXF) n = MAXF;
    const int tid = threadIdx.x;

    for (int f = blockIdx.x; f < n; f += gridDim.x) {
        int bg = g_flags[f].x, r = g_flags[f].y;
        __syncthreads();
        for (int k = tid; k < 1024; k += 256) xs[k] = x[(size_t)bg * DM + k];

        double s0 = 0, s1 = 0, s2 = 0, s3 = 0;
        #pragma unroll 1
        for (int kc = 0; kc < 1024; kc += 64) {
            __syncthreads();
            #pragma unroll
            for (int i = 0; i < 16; i++) {
                int idx = tid + i * 256;
                int row = idx >> 6, c4 = idx & 63;
                *(float4*)&ws[row * 256 + c4 * 4] =
                    *(const float4*)(Wp + (size_t)(kc + row) * (RNUM * 256) + r * 256 + c4 * 4);
            }
            __syncthreads();
            #pragma unroll
            for (int rr = 0; rr < 64; rr += 4) {
                s0 += (double)xs[kc + rr + 0] * (double)ws[(rr + 0) * 256 + tid];
                s1 += (double)xs[kc + rr + 1] * (double)ws[(rr + 1) * 256 + tid];
                s2 += (double)xs[kc + rr + 2] * (double)ws[(rr + 2) * 256 + tid];
                s3 += (double)xs[kc + rr + 3] * (double)ws[(rr + 3) * 256 + tid];
            }
        }
        Ls[tid] = 2.0 * ((s0 + s1) + (s2 + s3));
        __syncthreads();

        if (tid < 16) {
            const unsigned M16 = 0xFFFFu;
            int j = tid;
            double L[16];
            #pragma unroll
            for (int i = 0; i < 16; i++) L[i] = Ls[i * 16 + j];
            #pragma unroll 1
            for (int it = 0; it < 5; it++) {
                #pragma unroll 1
                for (int i = 0; i < 16; i++) {
                    double mx = L[i];
                    mx = fmax(mx, __shfl_xor_sync(M16, mx, 1));
                    mx = fmax(mx, __shfl_xor_sync(M16, mx, 2));
                    mx = fmax(mx, __shfl_xor_sync(M16, mx, 4));
                    mx = fmax(mx, __shfl_xor_sync(M16, mx, 8));
                    double e = exp(L[i] - mx);
                    e += __shfl_xor_sync(M16, e, 1);
                    e += __shfl_xor_sync(M16, e, 2);
                    e += __shfl_xor_sync(M16, e, 4);
                    e += __shfl_xor_sync(M16, e, 8);
                    L[i] -= mx + log(e);
                }
                if (it < 4) {
                    double mx = L[0];
                    #pragma unroll
                    for (int i = 1; i < 16; i++) mx = fmax(mx, L[i]);
                    double ss = 0.0;
                    #pragma unroll
                    for (int i = 0; i < 16; i++) ss += exp(L[i] - mx);
                    double sub = mx + log(ss);
                    #pragma unroll
                    for (int i = 0; i < 16; i++) L[i] -= sub;
                }
            }
            int best = 0; double bv = L[0];
            #pragma unroll
            for (int i = 1; i < 16; i++)
                if (L[i] > bv) { bv = L[i]; best = i; }

            float hv = h[(size_t)bg * DM + r * 16 + j];
            float hp = 0.f;
            #pragma unroll
            for (int jj = 0; jj < 16; jj++) {
                int   ib = __shfl_sync(M16, best, jj);
                float hj = __shfl_sync(M16, hv,   jj);
                if (ib == j) hp += hj;
            }
            int oi = bg * DM + r * 16 + j;
            out[oi] = g_dv[oi] * hp;
        }
    }
}

// ---------------- launch ----------------
extern "C" void kernel_launch(void* const* d_in, const int* in_sizes, int n_in,
                              void* d_out, int out_size) {
    const float* x  = (const float*)d_in[0];
    const float* h  = (const float*)d_in[1];
    const float* Wp = (const float*)d_in[2];
    const float* Wd = (const float*)d_in[3];
    const float* Wa = (const float*)d_in[4];
    float* out = (float*)d_out;

    cudaFuncSetAttribute(perm_mma, cudaFuncAttributeMaxDynamicSharedMemorySize, SMEMSZ);
    cudaFuncSetAttribute(diag_mma, cudaFuncAttributeMaxDynamicSharedMemorySize, SMEMSZ);
    cudaFuncSetAttribute(fixup,    cudaFuncAttributeMaxDynamicSharedMemorySize, FIXSMEM);

    conv_x<<<BATCH * DM / 256, 256>>>(x);
    tr_wp<<<dim3(512, 32), dim3(32, 8)>>>(Wp);
    tr_wc<<<dim3(32, 32), dim3(32, 8)>>>(Wd, Wa);
    diag_mma<<<dim3(16, 8), 256, SMEMSZ>>>();
    perm_mma<<<dim3(16, 64), 256, SMEMSZ>>>(h, out);
    fixup<<<512, 256, FIXSMEM>>>(x, Wp, h, out);
}

// round 11
// speedup vs baseline: 1.0799x; 1.0318x over previous
#include <cuda_runtime.h>
#include <cuda_fp16.h>
#include <cstdint>
#include <math.h>

#define BATCH 2048
#define DM    1024
#define RNUM  64
#define KH    3072          // concat K in halfs
#define KT    64            // k-tile in halfs (128 B rows)
#define NKT   (KH / KT)     // 48
#define ABLK  8192          // A tile block halfs (128 x 64) = 16 KB
#define BBLK  16384         // B tile block halfs (256 x 64) = 32 KB
#define STGB  49152         // stage bytes (A+B)
#define CSTR  257
#define MAXF  16384
#define SMEMSZ (1024 + 3 * STGB)
#define SC    64.0f
#define FIXSMEM (4096 + 65536 + 2048)

// ---------------- device scratch ----------------
__device__ float  g_dv[BATCH * DM];
__device__ __half g_xc[BATCH * KH];           // tiled [mtile][kt][row128][64] swizzled
__device__ __half g_wpc[RNUM * 256 * KH];     // tiled [r][kt][row256][64]
__device__ __half g_wc[2 * DM * KH];          // tiled [nt8][kt][row256][64]
__device__ int    g_cnt;
__device__ int2   g_flags[MAXF];

// ---------------- helpers ----------------
__device__ __forceinline__ uint32_t smem_u32(const void* p) {
    uint32_t a;
    asm("{ .reg .u64 t; cvta.to.shared.u64 t, %1; cvt.u32.u64 %0, t; }" : "=r"(a) : "l"(p));
    return a;
}
__device__ __forceinline__ void ldsm4(uint32_t* r, uint32_t a) {
    asm volatile("ldmatrix.sync.aligned.m8n8.x4.shared.b16 {%0,%1,%2,%3}, [%4];"
                 : "=r"(r[0]), "=r"(r[1]), "=r"(r[2]), "=r"(r[3]) : "r"(a));
}
// precise e^x via FMA-only polynomial
__device__ __forceinline__ float exp_p(float x) {
    x = fmaxf(x, -80.0f);
    float n = rintf(x * 1.4426950408889634f);
    float r = fmaf(n, -0.693359375f, x);
    r = fmaf(n, 2.12194440e-4f, r);
    float p = 1.9875691500e-4f;
    p = fmaf(p, r, 1.3981999507e-3f);
    p = fmaf(p, r, 8.3334519073e-3f);
    p = fmaf(p, r, 4.1665795894e-2f);
    p = fmaf(p, r, 1.6666665459e-1f);
    p = fmaf(p, r, 5.0000001201e-1f);
    float q = fmaf(p, r * r, r) + 1.0f;
    return q * __int_as_float(((int)n + 127) << 23);
}
__device__ __forceinline__ float rcp_p(float x) {
    float r;
    asm("rcp.approx.f32 %0, %1;" : "=f"(r) : "f"(x));
    float e = fmaf(-x, r, 1.0f);
    return fmaf(r, e, r);
}
#define MBAR_INIT(a, c) asm volatile("mbarrier.init.shared.b64 [%0], %1;" :: "r"(a), "r"(c) : "memory")
#define MBAR_EXPECT(a, b) asm volatile("mbarrier.arrive.expect_tx.shared.b64 _, [%0], %1;" :: "r"(a), "r"(b) : "memory")
#define BULK(dst, src, sz, mb) \
    asm volatile("cp.async.bulk.shared::cluster.global.mbarrier::complete_tx::bytes [%0], [%1], %2, [%3];" \
                 :: "r"(dst), "l"(src), "r"(sz), "r"(mb) : "memory")
__device__ __forceinline__ void mbar_wait(uint32_t a, uint32_t ph) {
    asm volatile(
        "{\n.reg .pred P;\n"
        "WL%=:\n"
        "mbarrier.try_wait.parity.acquire.cta.shared::cta.b64 P, [%0], %1, 0x989680;\n"
        "@P bra WD%=;\n"
        "bra WL%=;\n"
        "WD%=:\n}"
        :: "r"(a), "r"(ph) : "memory");
}

#define MMA_F16(c, a0, a1, a2, a3, b0, b1) \
    asm volatile("mma.sync.aligned.m16n8k16.row.col.f32.f16.f16.f32 " \
        "{%0,%1,%2,%3}, {%4,%5,%6,%7}, {%8,%9}, {%0,%1,%2,%3};" \
        : "+f"((c)[0]), "+f"((c)[1]), "+f"((c)[2]), "+f"((c)[3]) \
        : "r"(a0), "r"(a1), "r"(a2), "r"(a3), "r"(b0), "r"(b1))

// ---------------- prep kernels (natural k order, 8-row swizzle) ----------------
__device__ __forceinline__ size_t a_idx(int m, int p) {
    int row = m & 127;
    return ((size_t)((m >> 7) * NKT + (p >> 6)) * 128 + row) * 64 +
           ((p & 63) ^ ((row & 7) << 3));
}
__device__ __forceinline__ size_t b_idx(int blk, int row, int p) {
    return ((size_t)(blk * NKT + (p >> 6)) * 256 + row) * 64 +
           ((p & 63) ^ ((row & 7) << 3));
}

__global__ void conv_x(const float* __restrict__ x) {
    int g = blockIdx.x * 256 + threadIdx.x;
    if (g == 0) g_cnt = 0;
    int m = g >> 10, k = g & 1023;
    float v = x[g];
    __half hh = __float2half_rn(v);
    float hf = __half2float(hh);
    g_xc[a_idx(m, k)]        = hh;
    g_xc[a_idx(m, k + 1024)] = __float2half_rn(hf * (1.0f / SC));
    g_xc[a_idx(m, k + 2048)] = __float2half_rn((v - hf) * SC);
}

__global__ void tr_wp(const float* __restrict__ Wp) {
    __shared__ float t[32][33];
    int n0 = blockIdx.x * 32, k0 = blockIdx.y * 32;
    int tx = threadIdx.x, ty = threadIdx.y;
    #pragma unroll
    for (int i = 0; i < 4; i++)
        t[ty + i * 8][tx] = Wp[(size_t)(k0 + ty + i * 8) * (RNUM * 256) + n0 + tx];
    __syncthreads();
    #pragma unroll
    for (int i = 0; i < 4; i++) {
        int rr = ty + i * 8;
        int n = n0 + rr;
        float v = t[tx][rr];
        __half hh = __float2half_rn(v);
        float hf = __half2float(hh);
        int p = k0 + tx;
        int r = n >> 8, nr = n & 255;
        g_wpc[b_idx(r, nr, p)]        = hh;
        g_wpc[b_idx(r, nr, p + 1024)] = __float2half_rn((v - hf) * SC);
        g_wpc[b_idx(r, nr, p + 2048)] = __float2half_rn(hf * (1.0f / SC));
    }
}

__global__ void tr_wc(const float* __restrict__ Wd, const float* __restrict__ Wa) {
    __shared__ float t[2][32][33];
    int n0 = blockIdx.x * 32, k0 = blockIdx.y * 32;
    int tx = threadIdx.x, ty = threadIdx.y;
    #pragma unroll
    for (int i = 0; i < 4; i++) {
        int rr = ty + i * 8;
        t[0][rr][tx] = Wd[(size_t)(k0 + rr) * DM + n0 + tx];
        t[1][rr][tx] = Wa[(size_t)(k0 + rr) * DM + n0 + tx];
    }
    __syncthreads();
    #pragma unroll
    for (int i = 0; i < 4; i++) {
        int rr = ty + i * 8;
        int p = k0 + tx;
        #pragma unroll
        for (int s = 0; s < 2; s++) {
            float v = t[s][tx][rr];
            __half hh = __float2half_rn(v);
            float hf = __half2float(hh);
            int col2 = 2 * (n0 + rr) + s;
            int nt = col2 >> 8, row = col2 & 255;
            g_wc[b_idx(nt, row, p)]        = hh;
            g_wc[b_idx(nt, row, p + 1024)] = __float2half_rn((v - hf) * SC);
            g_wc[b_idx(nt, row, p + 2048)] = __float2half_rn(hf * (1.0f / SC));
        }
    }
}

// ---------------- GEMM core: ldmatrix.x4, conflict-free, ks-pipelined ----------------
__device__ __forceinline__ void compute_tile(uint32_t sA, uint32_t sB,
                                             int wm, int wn, int lane,
                                             float acc[4][8][4]) {
    const uint32_t sz    = (uint32_t)(lane & 7) << 4;
    const uint32_t arow  = (uint32_t)(wm + (lane & 15));
    const uint32_t akoff = (uint32_t)(lane >> 4) << 4;
    const uint32_t brow  = (uint32_t)(wn + (lane & 7) + ((lane >> 4) << 3));
    const uint32_t bkoff = (uint32_t)((lane >> 3) & 1) << 4;
    const uint32_t aBase = sA + arow * 128;
    const uint32_t bBase = sB + brow * 128;

    uint32_t Af[2][4][4], Bf[2][4][4];
    #pragma unroll
    for (int fm = 0; fm < 4; fm++)
        ldsm4(Af[0][fm], aBase + fm * 2048 + (akoff ^ sz));
    #pragma unroll
    for (int fp = 0; fp < 4; fp++)
        ldsm4(Bf[0][fp], bBase + fp * 2048 + (bkoff ^ sz));

    #pragma unroll
    for (int ks = 0; ks < 4; ks++) {
        int cur = ks & 1, nxt = cur ^ 1;
        if (ks < 3) {
            uint32_t ko = (uint32_t)(ks + 1) * 32;
            #pragma unroll
            for (int fm = 0; fm < 4; fm++)
                ldsm4(Af[nxt][fm], aBase + fm * 2048 + ((ko + akoff) ^ sz));
            #pragma unroll
            for (int fp = 0; fp < 4; fp++)
                ldsm4(Bf[nxt][fp], bBase + fp * 2048 + ((ko + bkoff) ^ sz));
        }
        #pragma unroll
        for (int fm = 0; fm < 4; fm++)
            #pragma unroll
            for (int fp = 0; fp < 4; fp++) {
                MMA_F16(acc[fm][2 * fp], Af[cur][fm][0], Af[cur][fm][1],
                        Af[cur][fm][2], Af[cur][fm][3], Bf[cur][fp][0], Bf[cur][fp][1]);
                MMA_F16(acc[fm][2 * fp + 1], Af[cur][fm][0], Af[cur][fm][1],
                        Af[cur][fm][2], Af[cur][fm][3], Bf[cur][fp][2], Bf[cur][fp][3]);
            }
    }
}

// 3-stage bulk-copy pipeline, one barrier per k-tile
#define GEMM_MAINLOOP(Ablocks, Bblocks)                                         \
    float acc[4][8][4] = {};                                                    \
    if (tid == 0) {                                                             \
        MBAR_INIT(sb + 16, 1); MBAR_INIT(sb + 24, 1); MBAR_INIT(sb + 32, 1);    \
    }                                                                           \
    __syncthreads();                                                            \
    if (tid == 0) {                                                             \
        _Pragma("unroll")                                                       \
        for (int s = 0; s < 2; s++) {                                           \
            uint32_t mb = sb + 16 + 8 * s, st = sb + 1024 + s * STGB;           \
            MBAR_EXPECT(mb, STGB);                                              \
            BULK(st, (const char*)(Ablocks + (size_t)s * ABLK), 16384, mb);     \
            BULK(st + 16384, (const char*)(Bblocks + (size_t)s * BBLK), 32768, mb); \
        }                                                                       \
    }                                                                           \
    for (int kt = 0; kt < NKT; kt++) {                                          \
        int s = kt % 3;                                                         \
        mbar_wait(sb + 16 + 8 * s, (kt / 3) & 1);                               \
        __syncthreads();                                                        \
        if (kt + 2 < NKT && tid == 0) {                                         \
            int s2 = (kt + 2) % 3;                                              \
            uint32_t mb = sb + 16 + 8 * s2, st = sb + 1024 + s2 * STGB;         \
            MBAR_EXPECT(mb, STGB);                                              \
            BULK(st, (const char*)(Ablocks + (size_t)(kt + 2) * ABLK), 16384, mb); \
            BULK(st + 16384, (const char*)(Bblocks + (size_t)(kt + 2) * BBLK), 32768, mb); \
        }                                                                       \
        uint32_t st = sb + 1024 + s * STGB;                                     \
        compute_tile(st, st + 16384, wm, wn, lane, acc);                        \
    }                                                                           \
    __syncthreads();

// ---------------- diag kernel ----------------
__global__ __launch_bounds__(256, 1) void diag_mma() {
    extern __shared__ __align__(1024) char smem[];
    uint32_t sb = smem_u32(smem);
    const int tid = threadIdx.x, wid = tid >> 5, lane = tid & 31;
    const int m0 = blockIdx.x * 128, nt = blockIdx.y;
    const int wm = (wid & 1) * 64, wn = (wid >> 1) * 64;
    const int gid = lane >> 2, qc = lane & 3;
    const int n0 = nt * 256;

    const __half* Ab = g_xc + (size_t)blockIdx.x * NKT * ABLK;
    const __half* Bb = g_wc + (size_t)nt * NKT * BBLK;
    GEMM_MAINLOOP(Ab, Bb)

    #pragma unroll
    for (int fm = 0; fm < 4; fm++)
        #pragma unroll
        for (int fn = 0; fn < 8; fn++) {
            int mm = m0 + wm + fm * 16 + gid;
            int tcol = (n0 + wn + fn * 8 + 2 * qc) >> 1;
            float* c = acc[fm][fn];
            float s0 = 1.0f / (1.0f + expf(-c[1]));
            float s1 = 1.0f / (1.0f + expf(-c[3]));
            g_dv[(size_t)mm * DM + tcol]       = s0 * tanhf(c[0]);
            g_dv[(size_t)(mm + 8) * DM + tcol] = s1 * tanhf(c[2]);
        }
}

// ---------------- perm kernel ----------------
__global__ __launch_bounds__(256, 1) void perm_mma(const float* __restrict__ h,
                                                   float* __restrict__ out) {
    extern __shared__ __align__(1024) char smem[];
    uint32_t sb = smem_u32(smem);
    const int tid = threadIdx.x, wid = tid >> 5, lane = tid & 31;
    const int m0 = blockIdx.x * 128, r = blockIdx.y;
    const int wm = (wid & 1) * 64, wn = (wid >> 1) * 64;
    const int gid = lane >> 2, qc = lane & 3;

    const __half* Ab = g_xc + (size_t)blockIdx.x * NKT * ABLK;
    const __half* Bb = g_wpc + (size_t)r * NKT * BBLK;
    GEMM_MAINLOOP(Ab, Bb)

    float* Csm = (float*)smem;
    #pragma unroll
    for (int fm = 0; fm < 4; fm++)
        #pragma unroll
        for (int fn = 0; fn < 8; fn++) {
            int mm = wm + fm * 16 + gid, nn = wn + fn * 8 + 2 * qc;
            float* c = acc[fm][fn];
            Csm[mm * CSTR + nn]           = c[0];
            Csm[mm * CSTR + nn + 1]       = c[1];
            Csm[(mm + 8) * CSTR + nn]     = c[2];
            Csm[(mm + 8) * CSTR + nn + 1] = c[3];
        }
    __syncthreads();

    // ---- probability-domain sinkhorn + argmax (+ near-tie flag) + permute ----
    const int j = lane & 15, gb = (lane >> 4) << 4;
    const unsigned FULL = 0xffffffffu;

    #pragma unroll 1
    for (int pass = 0; pass < 8; pass++) {
        int m = pass * 16 + (tid >> 4);
        float p[16];
        #pragma unroll
        for (int i = 0; i < 16; i++) {
            float la = 2.0f * Csm[m * CSTR + i * 16 + j];
            float mx = la;
            mx = fmaxf(mx, __shfl_xor_sync(FULL, mx, 1));
            mx = fmaxf(mx, __shfl_xor_sync(FULL, mx, 2));
            mx = fmaxf(mx, __shfl_xor_sync(FULL, mx, 4));
            mx = fmaxf(mx, __shfl_xor_sync(FULL, mx, 8));
            p[i] = exp_p(la - mx);
        }

        #pragma unroll 1
        for (int it = 0; it < 5; it++) {
            #pragma unroll
            for (int i = 0; i < 16; i++) {
                float s = p[i];
                s += __shfl_xor_sync(FULL, s, 1);
                s += __shfl_xor_sync(FULL, s, 2);
                s += __shfl_xor_sync(FULL, s, 4);
                s += __shfl_xor_sync(FULL, s, 8);
                p[i] *= rcp_p(s);
            }
            if (it < 4) {
                float s = p[0];
                #pragma unroll
                for (int i = 1; i < 16; i++) s += p[i];
                float rc = rcp_p(s);
                #pragma unroll
                for (int i = 0; i < 16; i++) p[i] *= rc;
            }
        }

        int best = 0; float bv = p[0], sv = -1e30f;
        #pragma unroll
        for (int i = 1; i < 16; i++) {
            if (p[i] > bv) { sv = bv; bv = p[i]; best = i; }
            else if (p[i] > sv) sv = p[i];
        }

        int bg = m0 + m;

        unsigned bal = __ballot_sync(FULL, (bv - sv) < 4e-6f * bv);
        if (((bal >> gb) & 0xFFFFu) && lane == gb) {
            int idx = atomicAdd(&g_cnt, 1);
            if (idx < MAXF) g_flags[idx] = make_int2(bg, r);
        }

        float hv = h[(size_t)bg * DM + r * 16 + j];
        float hp = 0.f;
        #pragma unroll
        for (int jj = 0; jj < 16; jj++) {
            int   ib = __shfl_sync(FULL, best, gb + jj);
            float hj = __shfl_sync(FULL, hv,   gb + jj);
            if (ib == j) hp += hj;
        }
        int oi = bg * DM + r * 16 + j;
        out[oi] = g_dv[oi] * hp;
    }
}

// ---------------- exact fixup: smem-staged coalesced, fp64 accum ----------------
__global__ __launch_bounds__(256) void fixup(const float* __restrict__ x,
                                             const float* __restrict__ Wp,
                                             const float* __restrict__ h,
                                             float* __restrict__ out) {
    extern __shared__ char fsm[];
    float*  xs = (float*)fsm;                      // 1024 floats
    float*  ws = (float*)(fsm + 4096);             // 64 x 256 floats
    double* Ls = (double*)(fsm + 4096 + 65536);    // 256 doubles
    int n = g_cnt; if (n > MAXF) n = MAXF;
    const int tid = threadIdx.x;

    for (int f = blockIdx.x; f < n; f += gridDim.x) {
        int bg = g_flags[f].x, r = g_flags[f].y;
        __syncthreads();
        for (int k = tid; k < 1024; k += 256) xs[k] = x[(size_t)bg * DM + k];

        double s0 = 0, s1 = 0, s2 = 0, s3 = 0;
        #pragma unroll 1
        for (int kc = 0; kc < 1024; kc += 64) {
            __syncthreads();
            #pragma unroll
            for (int i = 0; i < 16; i++) {
                int idx = tid + i * 256;
                int row = idx >> 6, c4 = idx & 63;
                *(float4*)&ws[row * 256 + c4 * 4] =
                    *(const float4*)(Wp + (size_t)(kc + row) * (RNUM * 256) + r * 256 + c4 * 4);
            }
            __syncthreads();
            #pragma unroll
            for (int rr = 0; rr < 64; rr += 4) {
                s0 += (double)xs[kc + rr + 0] * (double)ws[(rr + 0) * 256 + tid];
                s1 += (double)xs[kc + rr + 1] * (double)ws[(rr + 1) * 256 + tid];
                s2 += (double)xs[kc + rr + 2] * (double)ws[(rr + 2) * 256 + tid];
                s3 += (double)xs[kc + rr + 3] * (double)ws[(rr + 3) * 256 + tid];
            }
        }
        Ls[tid] = 2.0 * ((s0 + s1) + (s2 + s3));
        __syncthreads();

        if (tid < 16) {
            const unsigned M16 = 0xFFFFu;
            int j = tid;
            double L[16];
            #pragma unroll
            for (int i = 0; i < 16; i++) L[i] = Ls[i * 16 + j];
            #pragma unroll 1
            for (int it = 0; it < 5; it++) {
                #pragma unroll 1
                for (int i = 0; i < 16; i++) {
                    double mx = L[i];
                    mx = fmax(mx, __shfl_xor_sync(M16, mx, 1));
                    mx = fmax(mx, __shfl_xor_sync(M16, mx, 2));
                    mx = fmax(mx, __shfl_xor_sync(M16, mx, 4));
                    mx = fmax(mx, __shfl_xor_sync(M16, mx, 8));
                    double e = exp(L[i] - mx);
                    e += __shfl_xor_sync(M16, e, 1);
                    e += __shfl_xor_sync(M16, e, 2);
                    e += __shfl_xor_sync(M16, e, 4);
                    e += __shfl_xor_sync(M16, e, 8);
                    L[i] -= mx + log(e);
                }
                if (it < 4) {
                    double mx = L[0];
                    #pragma unroll
                    for (int i = 1; i < 16; i++) mx = fmax(mx, L[i]);
                    double ss = 0.0;
                    #pragma unroll
                    for (int i = 0; i < 16; i++) ss += exp(L[i] - mx);
                    double sub = mx + log(ss);
                    #pragma unroll
                    for (int i = 0; i < 16; i++) L[i] -= sub;
                }
            }
            int best = 0; double bv = L[0];
            #pragma unroll
            for (int i = 1; i < 16; i++)
                if (L[i] > bv) { bv = L[i]; best = i; }

            float hv = h[(size_t)bg * DM + r * 16 + j];
            float hp = 0.f;
            #pragma unroll
            for (int jj = 0; jj < 16; jj++) {
                int   ib = __shfl_sync(M16, best, jj);
                float hj = __shfl_sync(M16, hv,   jj);
                if (ib == j) hp += hj;
            }
            int oi = bg * DM + r * 16 + j;
            out[oi] = g_dv[oi] * hp;
        }
    }
}

// ---------------- launch ----------------
extern "C" void kernel_launch(void* const* d_in, const int* in_sizes, int n_in,
                              void* d_out, int out_size) {
    const float* x  = (const float*)d_in[0];
    const float* h  = (const float*)d_in[1];
    const float* Wp = (const float*)d_in[2];
    const float* Wd = (const float*)d_in[3];
    const float* Wa = (const float*)d_in[4];
    float* out = (float*)d_out;

    cudaFuncSetAttribute(perm_mma, cudaFuncAttributeMaxDynamicSharedMemorySize, SMEMSZ);
    cudaFuncSetAttribute(diag_mma, cudaFuncAttributeMaxDynamicSharedMemorySize, SMEMSZ);
    cudaFuncSetAttribute(fixup,    cudaFuncAttributeMaxDynamicSharedMemorySize, FIXSMEM);

    conv_x<<<BATCH * DM / 256, 256>>>(x);
    tr_wp<<<dim3(512, 32), dim3(32, 8)>>>(Wp);
    tr_wc<<<dim3(32, 32), dim3(32, 8)>>>(Wd, Wa);
    diag_mma<<<dim3(16, 8), 256, SMEMSZ>>>();
    perm_mma<<<dim3(16, 64), 256, SMEMSZ>>>(h, out);
    fixup<<<512, 256, FIXSMEM>>>(x, Wp, h, out);
}

// round 12
// speedup vs baseline: 1.1044x; 1.0226x over previous
#include <cuda_runtime.h>
#include <cuda_fp16.h>
#include <cstdint>
#include <math.h>

#define BATCH 2048
#define DM    1024
#define RNUM  64
#define KH    3072          // concat K in halfs
#define KT    64            // k-tile in halfs (128 B rows)
#define NKT   (KH / KT)     // 48
#define ABLK  8192          // A tile block halfs (128 x 64) = 16 KB
#define BBLK  16384         // B tile block halfs (256 x 64) = 32 KB
#define STGB  49152         // stage bytes (A+B)
#define CSTR  257
#define MAXF  16384
#define SMEMSZ (1024 + 3 * STGB)
#define SC    64.0f
#define FIXSMEM (4096 + 65536 + 2048)

// ---------------- device scratch ----------------
__device__ float  g_dv[BATCH * DM];
__device__ __half g_xc[BATCH * KH];           // tiled [mtile][kt][row128][64] swizzled
__device__ __half g_wpc[RNUM * 256 * KH];     // tiled [r][kt][row256][64]
__device__ __half g_wc[2 * DM * KH];          // tiled [nt8][kt][row256][64]
__device__ int    g_cnt;
__device__ int2   g_flags[MAXF];

// ---------------- helpers ----------------
__device__ __forceinline__ uint32_t smem_u32(const void* p) {
    uint32_t a;
    asm("{ .reg .u64 t; cvta.to.shared.u64 t, %1; cvt.u32.u64 %0, t; }" : "=r"(a) : "l"(p));
    return a;
}
__device__ __forceinline__ void ldsm4(uint32_t* r, uint32_t a) {
    asm volatile("ldmatrix.sync.aligned.m8n8.x4.shared.b16 {%0,%1,%2,%3}, [%4];"
                 : "=r"(r[0]), "=r"(r[1]), "=r"(r[2]), "=r"(r[3]) : "r"(a));
}
// precise e^x via FMA-only polynomial
__device__ __forceinline__ float exp_p(float x) {
    x = fmaxf(x, -80.0f);
    float n = rintf(x * 1.4426950408889634f);
    float r = fmaf(n, -0.693359375f, x);
    r = fmaf(n, 2.12194440e-4f, r);
    float p = 1.9875691500e-4f;
    p = fmaf(p, r, 1.3981999507e-3f);
    p = fmaf(p, r, 8.3334519073e-3f);
    p = fmaf(p, r, 4.1665795894e-2f);
    p = fmaf(p, r, 1.6666665459e-1f);
    p = fmaf(p, r, 5.0000001201e-1f);
    float q = fmaf(p, r * r, r) + 1.0f;
    return q * __int_as_float(((int)n + 127) << 23);
}
__device__ __forceinline__ float rcp_p(float x) {
    float r;
    asm("rcp.approx.f32 %0, %1;" : "=f"(r) : "f"(x));
    float e = fmaf(-x, r, 1.0f);
    return fmaf(r, e, r);
}
#define MBAR_INIT(a, c) asm volatile("mbarrier.init.shared.b64 [%0], %1;" :: "r"(a), "r"(c) : "memory")
#define MBAR_EXPECT(a, b) asm volatile("mbarrier.arrive.expect_tx.shared.b64 _, [%0], %1;" :: "r"(a), "r"(b) : "memory")
#define BULK(dst, src, sz, mb) \
    asm volatile("cp.async.bulk.shared::cluster.global.mbarrier::complete_tx::bytes [%0], [%1], %2, [%3];" \
                 :: "r"(dst), "l"(src), "r"(sz), "r"(mb) : "memory")
__device__ __forceinline__ void mbar_wait(uint32_t a, uint32_t ph) {
    asm volatile(
        "{\n.reg .pred P;\n"
        "WL%=:\n"
        "mbarrier.try_wait.parity.acquire.cta.shared::cta.b64 P, [%0], %1, 0x989680;\n"
        "@P bra WD%=;\n"
        "bra WL%=;\n"
        "WD%=:\n}"
        :: "r"(a), "r"(ph) : "memory");
}

#define MMA_F16(c, a0, a1, a2, a3, b0, b1) \
    asm volatile("mma.sync.aligned.m16n8k16.row.col.f32.f16.f16.f32 " \
        "{%0,%1,%2,%3}, {%4,%5,%6,%7}, {%8,%9}, {%0,%1,%2,%3};" \
        : "+f"((c)[0]), "+f"((c)[1]), "+f"((c)[2]), "+f"((c)[3]) \
        : "r"(a0), "r"(a1), "r"(a2), "r"(a3), "r"(b0), "r"(b1))

// ---------------- prep kernels (natural k order, 8-row swizzle) ----------------
__device__ __forceinline__ size_t a_idx(int m, int p) {
    int row = m & 127;
    return ((size_t)((m >> 7) * NKT + (p >> 6)) * 128 + row) * 64 +
           ((p & 63) ^ ((row & 7) << 3));
}
__device__ __forceinline__ size_t b_idx(int blk, int row, int p) {
    return ((size_t)(blk * NKT + (p >> 6)) * 256 + row) * 64 +
           ((p & 63) ^ ((row & 7) << 3));
}

__global__ void conv_x(const float* __restrict__ x) {
    int g = blockIdx.x * 256 + threadIdx.x;
    if (g == 0) g_cnt = 0;
    int m = g >> 10, k = g & 1023;
    float v = x[g];
    __half hh = __float2half_rn(v);
    float hf = __half2float(hh);
    g_xc[a_idx(m, k)]        = hh;
    g_xc[a_idx(m, k + 1024)] = __float2half_rn(hf * (1.0f / SC));
    g_xc[a_idx(m, k + 2048)] = __float2half_rn((v - hf) * SC);
}

__global__ void tr_wp(const float* __restrict__ Wp) {
    __shared__ float t[32][33];
    int n0 = blockIdx.x * 32, k0 = blockIdx.y * 32;
    int tx = threadIdx.x, ty = threadIdx.y;
    #pragma unroll
    for (int i = 0; i < 4; i++)
        t[ty + i * 8][tx] = Wp[(size_t)(k0 + ty + i * 8) * (RNUM * 256) + n0 + tx];
    __syncthreads();
    #pragma unroll
    for (int i = 0; i < 4; i++) {
        int rr = ty + i * 8;
        int n = n0 + rr;
        float v = t[tx][rr];
        __half hh = __float2half_rn(v);
        float hf = __half2float(hh);
        int p = k0 + tx;
        int r = n >> 8, nr = n & 255;
        g_wpc[b_idx(r, nr, p)]        = hh;
        g_wpc[b_idx(r, nr, p + 1024)] = __float2half_rn((v - hf) * SC);
        g_wpc[b_idx(r, nr, p + 2048)] = __float2half_rn(hf * (1.0f / SC));
    }
}

__global__ void tr_wc(const float* __restrict__ Wd, const float* __restrict__ Wa) {
    __shared__ float t[2][32][33];
    int n0 = blockIdx.x * 32, k0 = blockIdx.y * 32;
    int tx = threadIdx.x, ty = threadIdx.y;
    #pragma unroll
    for (int i = 0; i < 4; i++) {
        int rr = ty + i * 8;
        t[0][rr][tx] = Wd[(size_t)(k0 + rr) * DM + n0 + tx];
        t[1][rr][tx] = Wa[(size_t)(k0 + rr) * DM + n0 + tx];
    }
    __syncthreads();
    #pragma unroll
    for (int i = 0; i < 4; i++) {
        int rr = ty + i * 8;
        int p = k0 + tx;
        #pragma unroll
        for (int s = 0; s < 2; s++) {
            float v = t[s][tx][rr];
            __half hh = __float2half_rn(v);
            float hf = __half2float(hh);
            int col2 = 2 * (n0 + rr) + s;
            int nt = col2 >> 8, row = col2 & 255;
            g_wc[b_idx(nt, row, p)]        = hh;
            g_wc[b_idx(nt, row, p + 1024)] = __float2half_rn((v - hf) * SC);
            g_wc[b_idx(nt, row, p + 2048)] = __float2half_rn(hf * (1.0f / SC));
        }
    }
}

// ---------------- GEMM core: 16 warps, 64x32 warp tile, ldmatrix.x4 ----------------
__device__ __forceinline__ void compute_tile(uint32_t sA, uint32_t sB,
                                             int wm, int wn, int lane,
                                             float acc[4][4][4]) {
    const uint32_t sz    = (uint32_t)(lane & 7) << 4;
    const uint32_t arow  = (uint32_t)(wm + (lane & 15));
    const uint32_t akoff = (uint32_t)(lane >> 4) << 4;
    const uint32_t brow  = (uint32_t)(wn + (lane & 7) + ((lane >> 4) << 3));
    const uint32_t bkoff = (uint32_t)((lane >> 3) & 1) << 4;
    const uint32_t aBase = sA + arow * 128;
    const uint32_t bBase = sB + brow * 128;

    #pragma unroll
    for (int ks = 0; ks < 4; ks++) {
        uint32_t ko = (uint32_t)ks * 32;
        uint32_t Af[4][4], Bf[2][4];
        #pragma unroll
        for (int fm = 0; fm < 4; fm++)
            ldsm4(Af[fm], aBase + fm * 2048 + ((ko + akoff) ^ sz));
        #pragma unroll
        for (int fp = 0; fp < 2; fp++)
            ldsm4(Bf[fp], bBase + fp * 2048 + ((ko + bkoff) ^ sz));
        #pragma unroll
        for (int fm = 0; fm < 4; fm++)
            #pragma unroll
            for (int fp = 0; fp < 2; fp++) {
                MMA_F16(acc[fm][2 * fp], Af[fm][0], Af[fm][1],
                        Af[fm][2], Af[fm][3], Bf[fp][0], Bf[fp][1]);
                MMA_F16(acc[fm][2 * fp + 1], Af[fm][0], Af[fm][1],
                        Af[fm][2], Af[fm][3], Bf[fp][2], Bf[fp][3]);
            }
    }
}

// 3-stage bulk-copy pipeline, one barrier per k-tile
#define GEMM_MAINLOOP(Ablocks, Bblocks)                                         \
    float acc[4][4][4] = {};                                                    \
    if (tid == 0) {                                                             \
        MBAR_INIT(sb + 16, 1); MBAR_INIT(sb + 24, 1); MBAR_INIT(sb + 32, 1);    \
    }                                                                           \
    __syncthreads();                                                            \
    if (tid == 0) {                                                             \
        _Pragma("unroll")                                                       \
        for (int s = 0; s < 2; s++) {                                           \
            uint32_t mb = sb + 16 + 8 * s, st = sb + 1024 + s * STGB;           \
            MBAR_EXPECT(mb, STGB);                                              \
            BULK(st, (const char*)(Ablocks + (size_t)s * ABLK), 16384, mb);     \
            BULK(st + 16384, (const char*)(Bblocks + (size_t)s * BBLK), 32768, mb); \
        }                                                                       \
    }                                                                           \
    for (int kt = 0; kt < NKT; kt++) {                                          \
        int s = kt % 3;                                                         \
        mbar_wait(sb + 16 + 8 * s, (kt / 3) & 1);                               \
        __syncthreads();                                                        \
        if (kt + 2 < NKT && tid == 0) {                                         \
            int s2 = (kt + 2) % 3;                                              \
            uint32_t mb = sb + 16 + 8 * s2, st = sb + 1024 + s2 * STGB;         \
            MBAR_EXPECT(mb, STGB);                                              \
            BULK(st, (const char*)(Ablocks + (size_t)(kt + 2) * ABLK), 16384, mb); \
            BULK(st + 16384, (const char*)(Bblocks + (size_t)(kt + 2) * BBLK), 32768, mb); \
        }                                                                       \
        uint32_t st = sb + 1024 + s * STGB;                                     \
        compute_tile(st, st + 16384, wm, wn, lane, acc);                        \
    }                                                                           \
    __syncthreads();

// ---------------- diag kernel (512 thr, 16 warps, 64x32 warp tiles) ----------------
__global__ __launch_bounds__(512, 1) void diag_mma() {
    extern __shared__ __align__(1024) char smem[];
    uint32_t sb = smem_u32(smem);
    const int tid = threadIdx.x, wid = tid >> 5, lane = tid & 31;
    const int m0 = blockIdx.x * 128, nt = blockIdx.y;
    const int wm = (wid & 1) * 64, wn = (wid >> 1) * 32;
    const int gid = lane >> 2, qc = lane & 3;
    const int n0 = nt * 256;

    const __half* Ab = g_xc + (size_t)blockIdx.x * NKT * ABLK;
    const __half* Bb = g_wc + (size_t)nt * NKT * BBLK;
    GEMM_MAINLOOP(Ab, Bb)

    #pragma unroll
    for (int fm = 0; fm < 4; fm++)
        #pragma unroll
        for (int fn = 0; fn < 4; fn++) {
            int mm = m0 + wm + fm * 16 + gid;
            int tcol = (n0 + wn + fn * 8 + 2 * qc) >> 1;
            float* c = acc[fm][fn];
            float s0 = 1.0f / (1.0f + expf(-c[1]));
            float s1 = 1.0f / (1.0f + expf(-c[3]));
            g_dv[(size_t)mm * DM + tcol]       = s0 * tanhf(c[0]);
            g_dv[(size_t)(mm + 8) * DM + tcol] = s1 * tanhf(c[2]);
        }
}

// ---------------- perm kernel (512 thr) ----------------
__global__ __launch_bounds__(512, 1) void perm_mma(const float* __restrict__ h,
                                                   float* __restrict__ out) {
    extern __shared__ __align__(1024) char smem[];
    uint32_t sb = smem_u32(smem);
    const int tid = threadIdx.x, wid = tid >> 5, lane = tid & 31;
    const int m0 = blockIdx.x * 128, r = blockIdx.y;
    const int wm = (wid & 1) * 64, wn = (wid >> 1) * 32;
    const int gid = lane >> 2, qc = lane & 3;

    const __half* Ab = g_xc + (size_t)blockIdx.x * NKT * ABLK;
    const __half* Bb = g_wpc + (size_t)r * NKT * BBLK;
    GEMM_MAINLOOP(Ab, Bb)

    float* Csm = (float*)smem;
    #pragma unroll
    for (int fm = 0; fm < 4; fm++)
        #pragma unroll
        for (int fn = 0; fn < 4; fn++) {
            int mm = wm + fm * 16 + gid, nn = wn + fn * 8 + 2 * qc;
            float* c = acc[fm][fn];
            Csm[mm * CSTR + nn]           = c[0];
            Csm[mm * CSTR + nn + 1]       = c[1];
            Csm[(mm + 8) * CSTR + nn]     = c[2];
            Csm[(mm + 8) * CSTR + nn + 1] = c[3];
        }
    __syncthreads();

    // ---- probability-domain sinkhorn + argmax (+ near-tie flag) + permute ----
    const int j = lane & 15, gb = (lane >> 4) << 4;
    const unsigned FULL = 0xffffffffu;

    #pragma unroll 1
    for (int pass = 0; pass < 4; pass++) {
        int m = pass * 32 + (tid >> 4);
        float p[16];
        #pragma unroll
        for (int i = 0; i < 16; i++) {
            float la = 2.0f * Csm[m * CSTR + i * 16 + j];
            float mx = la;
            mx = fmaxf(mx, __shfl_xor_sync(FULL, mx, 1));
            mx = fmaxf(mx, __shfl_xor_sync(FULL, mx, 2));
            mx = fmaxf(mx, __shfl_xor_sync(FULL, mx, 4));
            mx = fmaxf(mx, __shfl_xor_sync(FULL, mx, 8));
            p[i] = exp_p(la - mx);
        }

        #pragma unroll 1
        for (int it = 0; it < 5; it++) {
            #pragma unroll
            for (int i = 0; i < 16; i++) {
                float s = p[i];
                s += __shfl_xor_sync(FULL, s, 1);
                s += __shfl_xor_sync(FULL, s, 2);
                s += __shfl_xor_sync(FULL, s, 4);
                s += __shfl_xor_sync(FULL, s, 8);
                p[i] *= rcp_p(s);
            }
            if (it < 4) {
                float s = p[0];
                #pragma unroll
                for (int i = 1; i < 16; i++) s += p[i];
                float rc = rcp_p(s);
                #pragma unroll
                for (int i = 0; i < 16; i++) p[i] *= rc;
            }
        }

        int best = 0; float bv = p[0], sv = -1e30f;
        #pragma unroll
        for (int i = 1; i < 16; i++) {
            if (p[i] > bv) { sv = bv; bv = p[i]; best = i; }
            else if (p[i] > sv) sv = p[i];
        }

        int bg = m0 + m;

        unsigned bal = __ballot_sync(FULL, (bv - sv) < 4e-6f * bv);
        if (((bal >> gb) & 0xFFFFu) && lane == gb) {
            int idx = atomicAdd(&g_cnt, 1);
            if (idx < MAXF) g_flags[idx] = make_int2(bg, r);
        }

        float hv = h[(size_t)bg * DM + r * 16 + j];
        float hp = 0.f;
        #pragma unroll
        for (int jj = 0; jj < 16; jj++) {
            int   ib = __shfl_sync(FULL, best, gb + jj);
            float hj = __shfl_sync(FULL, hv,   gb + jj);
            if (ib == j) hp += hj;
        }
        int oi = bg * DM + r * 16 + j;
        out[oi] = g_dv[oi] * hp;
    }
}

// ---------------- exact fixup: smem-staged coalesced, fp64 accum ----------------
__global__ __launch_bounds__(256) void fixup(const float* __restrict__ x,
                                             const float* __restrict__ Wp,
                                             const float* __restrict__ h,
                                             float* __restrict__ out) {
    extern __shared__ char fsm[];
    float*  xs = (float*)fsm;                      // 1024 floats
    float*  ws = (float*)(fsm + 4096);             // 64 x 256 floats
    double* Ls = (double*)(fsm + 4096 + 65536);    // 256 doubles
    int n = g_cnt; if (n > MAXF) n = MAXF;
    const int tid = threadIdx.x;

    for (int f = blockIdx.x; f < n; f += gridDim.x) {
        int bg = g_flags[f].x, r = g_flags[f].y;
        __syncthreads();
        for (int k = tid; k < 1024; k += 256) xs[k] = x[(size_t)bg * DM + k];

        double s0 = 0, s1 = 0, s2 = 0, s3 = 0;
        #pragma unroll 1
        for (int kc = 0; kc < 1024; kc += 64) {
            __syncthreads();
            #pragma unroll
            for (int i = 0; i < 16; i++) {
                int idx = tid + i * 256;
                int row = idx >> 6, c4 = idx & 63;
                *(float4*)&ws[row * 256 + c4 * 4] =
                    *(const float4*)(Wp + (size_t)(kc + row) * (RNUM * 256) + r * 256 + c4 * 4);
            }
            __syncthreads();
            #pragma unroll
            for (int rr = 0; rr < 64; rr += 4) {
                s0 += (double)xs[kc + rr + 0] * (double)ws[(rr + 0) * 256 + tid];
                s1 += (double)xs[kc + rr + 1] * (double)ws[(rr + 1) * 256 + tid];
                s2 += (double)xs[kc + rr + 2] * (double)ws[(rr + 2) * 256 + tid];
                s3 += (double)xs[kc + rr + 3] * (double)ws[(rr + 3) * 256 + tid];
            }
        }
        Ls[tid] = 2.0 * ((s0 + s1) + (s2 + s3));
        __syncthreads();

        if (tid < 16) {
            const unsigned M16 = 0xFFFFu;
            int j = tid;
            double L[16];
            #pragma unroll
            for (int i = 0; i < 16; i++) L[i] = Ls[i * 16 + j];
            #pragma unroll 1
            for (int it = 0; it < 5; it++) {
                #pragma unroll 1
                for (int i = 0; i < 16; i++) {
                    double mx = L[i];
                    mx = fmax(mx, __shfl_xor_sync(M16, mx, 1));
                    mx = fmax(mx, __shfl_xor_sync(M16, mx, 2));
                    mx = fmax(mx, __shfl_xor_sync(M16, mx, 4));
                    mx = fmax(mx, __shfl_xor_sync(M16, mx, 8));
                    double e = exp(L[i] - mx);
                    e += __shfl_xor_sync(M16, e, 1);
                    e += __shfl_xor_sync(M16, e, 2);
                    e += __shfl_xor_sync(M16, e, 4);
                    e += __shfl_xor_sync(M16, e, 8);
                    L[i] -= mx + log(e);
                }
                if (it < 4) {
                    double mx = L[0];
                    #pragma unroll
                    for (int i = 1; i < 16; i++) mx = fmax(mx, L[i]);
                    double ss = 0.0;
                    #pragma unroll
                    for (int i = 0; i < 16; i++) ss += exp(L[i] - mx);
                    double sub = mx + log(ss);
                    #pragma unroll
                    for (int i = 0; i < 16; i++) L[i] -= sub;
                }
            }
            int best = 0; double bv = L[0];
            #pragma unroll
            for (int i = 1; i < 16; i++)
                if (L[i] > bv) { bv = L[i]; best = i; }

            float hv = h[(size_t)bg * DM + r * 16 + j];
            float hp = 0.f;
            #pragma unroll
            for (int jj = 0; jj < 16; jj++) {
                int   ib = __shfl_sync(M16, best, jj);
                float hj = __shfl_sync(M16, hv,   jj);
                if (ib == j) hp += hj;
            }
            int oi = bg * DM + r * 16 + j;
            out[oi] = g_dv[oi] * hp;
        }
    }
}

// ---------------- launch ----------------
extern "C" void kernel_launch(void* const* d_in, const int* in_sizes, int n_in,
                              void* d_out, int out_size) {
    const float* x  = (const float*)d_in[0];
    const float* h  = (const float*)d_in[1];
    const float* Wp = (const float*)d_in[2];
    const float* Wd = (const float*)d_in[3];
    const float* Wa = (const float*)d_in[4];
    float* out = (float*)d_out;

    cudaFuncSetAttribute(perm_mma, cudaFuncAttributeMaxDynamicSharedMemorySize, SMEMSZ);
    cudaFuncSetAttribute(diag_mma, cudaFuncAttributeMaxDynamicSharedMemorySize, SMEMSZ);
    cudaFuncSetAttribute(fixup,    cudaFuncAttributeMaxDynamicSharedMemorySize, FIXSMEM);

    conv_x<<<BATCH * DM / 256, 256>>>(x);
    tr_wp<<<dim3(512, 32), dim3(32, 8)>>>(Wp);
    tr_wc<<<dim3(32, 32), dim3(32, 8)>>>(Wd, Wa);
    diag_mma<<<dim3(16, 8), 512, SMEMSZ>>>();
    perm_mma<<<dim3(16, 64), 512, SMEMSZ>>>(h, out);
    fixup<<<512, 256, FIXSMEM>>>(x, Wp, h, out);
}

// round 13
// speedup vs baseline: 1.1400x; 1.0322x over previous
#include <cuda_runtime.h>
#include <cuda_fp16.h>
#include <cstdint>
#include <math.h>

#define BATCH 2048
#define DM    1024
#define RNUM  64
#define KH    3072          // concat K in halfs
#define KT    64            // k-tile in halfs (128 B rows)
#define NKT   (KH / KT)     // 48
#define ABLK  8192          // A tile block halfs (128 x 64) = 16 KB
#define BBLK  16384         // B tile block halfs (256 x 64) = 32 KB
#define STGB  49152         // stage bytes (A+B)
#define CSTR  257
#define MAXF  16384
#define SMEMSZ (1024 + 3 * STGB)
#define SC    64.0f
#define FIXSMEM (4096 + 65536 + 2048)

// ---------------- device scratch ----------------
__device__ float  g_dv[BATCH * DM];
__device__ __half g_xc[BATCH * KH];           // tiled [mtile][kt][row128][64] swizzled
__device__ __half g_wpc[RNUM * 256 * KH];     // tiled [r][kt][row256][64]
__device__ __half g_wc[2 * DM * KH];          // tiled [nt8][kt][row256][64]
__device__ int    g_cnt;
__device__ int2   g_flags[MAXF];

// ---------------- helpers ----------------
__device__ __forceinline__ uint32_t smem_u32(const void* p) {
    uint32_t a;
    asm("{ .reg .u64 t; cvta.to.shared.u64 t, %1; cvt.u32.u64 %0, t; }" : "=r"(a) : "l"(p));
    return a;
}
__device__ __forceinline__ void ldsm4(uint32_t* r, uint32_t a) {
    asm volatile("ldmatrix.sync.aligned.m8n8.x4.shared.b16 {%0,%1,%2,%3}, [%4];"
                 : "=r"(r[0]), "=r"(r[1]), "=r"(r[2]), "=r"(r[3]) : "r"(a));
}
// precise e^x via FMA-only polynomial
__device__ __forceinline__ float exp_p(float x) {
    x = fmaxf(x, -80.0f);
    float n = rintf(x * 1.4426950408889634f);
    float r = fmaf(n, -0.693359375f, x);
    r = fmaf(n, 2.12194440e-4f, r);
    float p = 1.9875691500e-4f;
    p = fmaf(p, r, 1.3981999507e-3f);
    p = fmaf(p, r, 8.3334519073e-3f);
    p = fmaf(p, r, 4.1665795894e-2f);
    p = fmaf(p, r, 1.6666665459e-1f);
    p = fmaf(p, r, 5.0000001201e-1f);
    float q = fmaf(p, r * r, r) + 1.0f;
    return q * __int_as_float(((int)n + 127) << 23);
}
__device__ __forceinline__ float rcp_p(float x) {
    float r;
    asm("rcp.approx.f32 %0, %1;" : "=f"(r) : "f"(x));
    float e = fmaf(-x, r, 1.0f);
    return fmaf(r, e, r);
}
#define MBAR_INIT(a, c) asm volatile("mbarrier.init.shared.b64 [%0], %1;" :: "r"(a), "r"(c) : "memory")
#define MBAR_EXPECT(a, b) asm volatile("mbarrier.arrive.expect_tx.shared.b64 _, [%0], %1;" :: "r"(a), "r"(b) : "memory")
#define MBAR_ARRIVE(a) asm volatile("mbarrier.arrive.shared.b64 _, [%0];" :: "r"(a) : "memory")
#define BULK(dst, src, sz, mb) \
    asm volatile("cp.async.bulk.shared::cluster.global.mbarrier::complete_tx::bytes [%0], [%1], %2, [%3];" \
                 :: "r"(dst), "l"(src), "r"(sz), "r"(mb) : "memory")
__device__ __forceinline__ void mbar_wait(uint32_t a, uint32_t ph) {
    asm volatile(
        "{\n.reg .pred P;\n"
        "WL%=:\n"
        "mbarrier.try_wait.parity.acquire.cta.shared::cta.b64 P, [%0], %1, 0x989680;\n"
        "@P bra WD%=;\n"
        "bra WL%=;\n"
        "WD%=:\n}"
        :: "r"(a), "r"(ph) : "memory");
}

#define MMA_F16(c, a0, a1, a2, a3, b0, b1) \
    asm volatile("mma.sync.aligned.m16n8k16.row.col.f32.f16.f16.f32 " \
        "{%0,%1,%2,%3}, {%4,%5,%6,%7}, {%8,%9}, {%0,%1,%2,%3};" \
        : "+f"((c)[0]), "+f"((c)[1]), "+f"((c)[2]), "+f"((c)[3]) \
        : "r"(a0), "r"(a1), "r"(a2), "r"(a3), "r"(b0), "r"(b1))

// ---------------- prep kernels (natural k order, 8-row swizzle) ----------------
__device__ __forceinline__ size_t a_idx(int m, int p) {
    int row = m & 127;
    return ((size_t)((m >> 7) * NKT + (p >> 6)) * 128 + row) * 64 +
           ((p & 63) ^ ((row & 7) << 3));
}
__device__ __forceinline__ size_t b_idx(int blk, int row, int p) {
    return ((size_t)(blk * NKT + (p >> 6)) * 256 + row) * 64 +
           ((p & 63) ^ ((row & 7) << 3));
}

__global__ void conv_x(const float* __restrict__ x) {
    int g = blockIdx.x * 256 + threadIdx.x;
    if (g == 0) g_cnt = 0;
    int m = g >> 10, k = g & 1023;
    float v = x[g];
    __half hh = __float2half_rn(v);
    float hf = __half2float(hh);
    g_xc[a_idx(m, k)]        = hh;
    g_xc[a_idx(m, k + 1024)] = __float2half_rn(hf * (1.0f / SC));
    g_xc[a_idx(m, k + 2048)] = __float2half_rn((v - hf) * SC);
}

__global__ void tr_wp(const float* __restrict__ Wp) {
    __shared__ float t[32][33];
    int n0 = blockIdx.x * 32, k0 = blockIdx.y * 32;
    int tx = threadIdx.x, ty = threadIdx.y;
    #pragma unroll
    for (int i = 0; i < 4; i++)
        t[ty + i * 8][tx] = Wp[(size_t)(k0 + ty + i * 8) * (RNUM * 256) + n0 + tx];
    __syncthreads();
    #pragma unroll
    for (int i = 0; i < 4; i++) {
        int rr = ty + i * 8;
        int n = n0 + rr;
        float v = t[tx][rr];
        __half hh = __float2half_rn(v);
        float hf = __half2float(hh);
        int p = k0 + tx;
        int r = n >> 8, nr = n & 255;
        g_wpc[b_idx(r, nr, p)]        = hh;
        g_wpc[b_idx(r, nr, p + 1024)] = __float2half_rn((v - hf) * SC);
        g_wpc[b_idx(r, nr, p + 2048)] = __float2half_rn(hf * (1.0f / SC));
    }
}

__global__ void tr_wc(const float* __restrict__ Wd, const float* __restrict__ Wa) {
    __shared__ float t[2][32][33];
    int n0 = blockIdx.x * 32, k0 = blockIdx.y * 32;
    int tx = threadIdx.x, ty = threadIdx.y;
    #pragma unroll
    for (int i = 0; i < 4; i++) {
        int rr = ty + i * 8;
        t[0][rr][tx] = Wd[(size_t)(k0 + rr) * DM + n0 + tx];
        t[1][rr][tx] = Wa[(size_t)(k0 + rr) * DM + n0 + tx];
    }
    __syncthreads();
    #pragma unroll
    for (int i = 0; i < 4; i++) {
        int rr = ty + i * 8;
        int p = k0 + tx;
        #pragma unroll
        for (int s = 0; s < 2; s++) {
            float v = t[s][tx][rr];
            __half hh = __float2half_rn(v);
            float hf = __half2float(hh);
            int col2 = 2 * (n0 + rr) + s;
            int nt = col2 >> 8, row = col2 & 255;
            g_wc[b_idx(nt, row, p)]        = hh;
            g_wc[b_idx(nt, row, p + 1024)] = __float2half_rn((v - hf) * SC);
            g_wc[b_idx(nt, row, p + 2048)] = __float2half_rn(hf * (1.0f / SC));
        }
    }
}

// ---------------- GEMM core: 16 warps, 64x32 warp tile, ldmatrix.x4 ----------------
__device__ __forceinline__ void compute_tile(uint32_t sA, uint32_t sB,
                                             int wm, int wn, int lane,
                                             float acc[4][4][4]) {
    const uint32_t sz    = (uint32_t)(lane & 7) << 4;
    const uint32_t arow  = (uint32_t)(wm + (lane & 15));
    const uint32_t akoff = (uint32_t)(lane >> 4) << 4;
    const uint32_t brow  = (uint32_t)(wn + (lane & 7) + ((lane >> 4) << 3));
    const uint32_t bkoff = (uint32_t)((lane >> 3) & 1) << 4;
    const uint32_t aBase = sA + arow * 128;
    const uint32_t bBase = sB + brow * 128;

    #pragma unroll
    for (int ks = 0; ks < 4; ks++) {
        uint32_t ko = (uint32_t)ks * 32;
        uint32_t Af[4][4], Bf[2][4];
        #pragma unroll
        for (int fm = 0; fm < 4; fm++)
            ldsm4(Af[fm], aBase + fm * 2048 + ((ko + akoff) ^ sz));
        #pragma unroll
        for (int fp = 0; fp < 2; fp++)
            ldsm4(Bf[fp], bBase + fp * 2048 + ((ko + bkoff) ^ sz));
        #pragma unroll
        for (int fm = 0; fm < 4; fm++)
            #pragma unroll
            for (int fp = 0; fp < 2; fp++) {
                MMA_F16(acc[fm][2 * fp], Af[fm][0], Af[fm][1],
                        Af[fm][2], Af[fm][3], Bf[fp][0], Bf[fp][1]);
                MMA_F16(acc[fm][2 * fp + 1], Af[fm][0], Af[fm][1],
                        Af[fm][2], Af[fm][3], Bf[fp][2], Bf[fp][3]);
            }
    }
}

// 3-stage bulk-copy pipeline with per-stage full/empty mbarriers (no per-ktile
// __syncthreads -> warps de-phase, LDSM and MMA overlap across warps)
#define GEMM_MAINLOOP(Ablocks, Bblocks)                                         \
    float acc[4][4][4] = {};                                                    \
    if (tid == 0) {                                                             \
        MBAR_INIT(sb + 16, 1);  MBAR_INIT(sb + 24, 1);  MBAR_INIT(sb + 32, 1);  \
        MBAR_INIT(sb + 40, 16); MBAR_INIT(sb + 48, 16); MBAR_INIT(sb + 56, 16); \
    }                                                                           \
    __syncthreads();                                                            \
    if (tid == 0) {                                                             \
        _Pragma("unroll")                                                       \
        for (int s = 0; s < 2; s++) {                                           \
            uint32_t mb = sb + 16 + 8 * s, st = sb + 1024 + s * STGB;           \
            MBAR_EXPECT(mb, STGB);                                              \
            BULK(st, (const char*)(Ablocks + (size_t)s * ABLK), 16384, mb);     \
            BULK(st + 16384, (const char*)(Bblocks + (size_t)s * BBLK), 32768, mb); \
        }                                                                       \
    }                                                                           \
    for (int kt = 0; kt < NKT; kt++) {                                          \
        int s = kt % 3;                                                         \
        mbar_wait(sb + 16 + 8 * s, (kt / 3) & 1);                               \
        uint32_t st = sb + 1024 + s * STGB;                                     \
        compute_tile(st, st + 16384, wm, wn, lane, acc);                        \
        __syncwarp();                                                           \
        if (lane == 0) MBAR_ARRIVE(sb + 40 + 8 * s);                            \
        if (tid == 0 && kt + 2 < NKT) {                                         \
            int k2 = kt + 2, s2 = k2 % 3;                                       \
            if (k2 >= 3) mbar_wait(sb + 40 + 8 * s2, ((k2 / 3) - 1) & 1);       \
            uint32_t mb = sb + 16 + 8 * s2, st2 = sb + 1024 + s2 * STGB;        \
            MBAR_EXPECT(mb, STGB);                                              \
            BULK(st2, (const char*)(Ablocks + (size_t)k2 * ABLK), 16384, mb);   \
            BULK(st2 + 16384, (const char*)(Bblocks + (size_t)k2 * BBLK), 32768, mb); \
        }                                                                       \
    }                                                                           \
    __syncthreads();

// ---------------- diag kernel (512 thr, 16 warps, 64x32 warp tiles) ----------------
__global__ __launch_bounds__(512, 1) void diag_mma() {
    extern __shared__ __align__(1024) char smem[];
    uint32_t sb = smem_u32(smem);
    const int tid = threadIdx.x, wid = tid >> 5, lane = tid & 31;
    const int m0 = blockIdx.x * 128, nt = blockIdx.y;
    const int wm = (wid & 1) * 64, wn = (wid >> 1) * 32;
    const int gid = lane >> 2, qc = lane & 3;
    const int n0 = nt * 256;

    const __half* Ab = g_xc + (size_t)blockIdx.x * NKT * ABLK;
    const __half* Bb = g_wc + (size_t)nt * NKT * BBLK;
    GEMM_MAINLOOP(Ab, Bb)

    #pragma unroll
    for (int fm = 0; fm < 4; fm++)
        #pragma unroll
        for (int fn = 0; fn < 4; fn++) {
            int mm = m0 + wm + fm * 16 + gid;
            int tcol = (n0 + wn + fn * 8 + 2 * qc) >> 1;
            float* c = acc[fm][fn];
            float s0 = 1.0f / (1.0f + expf(-c[1]));
            float s1 = 1.0f / (1.0f + expf(-c[3]));
            g_dv[(size_t)mm * DM + tcol]       = s0 * tanhf(c[0]);
            g_dv[(size_t)(mm + 8) * DM + tcol] = s1 * tanhf(c[2]);
        }
}

// ---------------- perm kernel (512 thr) ----------------
__global__ __launch_bounds__(512, 1) void perm_mma(const float* __restrict__ h,
                                                   float* __restrict__ out) {
    extern __shared__ __align__(1024) char smem[];
    uint32_t sb = smem_u32(smem);
    const int tid = threadIdx.x, wid = tid >> 5, lane = tid & 31;
    const int m0 = blockIdx.x * 128, r = blockIdx.y;
    const int wm = (wid & 1) * 64, wn = (wid >> 1) * 32;
    const int gid = lane >> 2, qc = lane & 3;

    const __half* Ab = g_xc + (size_t)blockIdx.x * NKT * ABLK;
    const __half* Bb = g_wpc + (size_t)r * NKT * BBLK;
    GEMM_MAINLOOP(Ab, Bb)

    float* Csm = (float*)smem;
    #pragma unroll
    for (int fm = 0; fm < 4; fm++)
        #pragma unroll
        for (int fn = 0; fn < 4; fn++) {
            int mm = wm + fm * 16 + gid, nn = wn + fn * 8 + 2 * qc;
            float* c = acc[fm][fn];
            Csm[mm * CSTR + nn]           = c[0];
            Csm[mm * CSTR + nn + 1]       = c[1];
            Csm[(mm + 8) * CSTR + nn]     = c[2];
            Csm[(mm + 8) * CSTR + nn + 1] = c[3];
        }
    __syncthreads();

    // ---- probability-domain sinkhorn + argmax (+ near-tie flag) + permute ----
    const int j = lane & 15, gb = (lane >> 4) << 4;
    const unsigned FULL = 0xffffffffu;

    #pragma unroll 1
    for (int pass = 0; pass < 4; pass++) {
        int m = pass * 32 + (tid >> 4);
        float p[16];
        #pragma unroll
        for (int i = 0; i < 16; i++) {
            float la = 2.0f * Csm[m * CSTR + i * 16 + j];
            float mx = la;
            mx = fmaxf(mx, __shfl_xor_sync(FULL, mx, 1));
            mx = fmaxf(mx, __shfl_xor_sync(FULL, mx, 2));
            mx = fmaxf(mx, __shfl_xor_sync(FULL, mx, 4));
            mx = fmaxf(mx, __shfl_xor_sync(FULL, mx, 8));
            p[i] = exp_p(la - mx);
        }

        #pragma unroll 1
        for (int it = 0; it < 5; it++) {
            #pragma unroll
            for (int i = 0; i < 16; i++) {
                float s = p[i];
                s += __shfl_xor_sync(FULL, s, 1);
                s += __shfl_xor_sync(FULL, s, 2);
                s += __shfl_xor_sync(FULL, s, 4);
                s += __shfl_xor_sync(FULL, s, 8);
                p[i] *= rcp_p(s);
            }
            if (it < 4) {
                float s = p[0];
                #pragma unroll
                for (int i = 1; i < 16; i++) s += p[i];
                float rc = rcp_p(s);
                #pragma unroll
                for (int i = 0; i < 16; i++) p[i] *= rc;
            }
        }

        int best = 0; float bv = p[0], sv = -1e30f;
        #pragma unroll
        for (int i = 1; i < 16; i++) {
            if (p[i] > bv) { sv = bv; bv = p[i]; best = i; }
            else if (p[i] > sv) sv = p[i];
        }

        int bg = m0 + m;

        unsigned bal = __ballot_sync(FULL, (bv - sv) < 4e-6f * bv);
        if (((bal >> gb) & 0xFFFFu) && lane == gb) {
            int idx = atomicAdd(&g_cnt, 1);
            if (idx < MAXF) g_flags[idx] = make_int2(bg, r);
        }

        float hv = h[(size_t)bg * DM + r * 16 + j];
        float hp = 0.f;
        #pragma unroll
        for (int jj = 0; jj < 16; jj++) {
            int   ib = __shfl_sync(FULL, best, gb + jj);
            float hj = __shfl_sync(FULL, hv,   gb + jj);
            if (ib == j) hp += hj;
        }
        int oi = bg * DM + r * 16 + j;
        out[oi] = g_dv[oi] * hp;
    }
}

// ---------------- exact fixup: smem-staged coalesced, fp64 accum ----------------
__global__ __launch_bounds__(256) void fixup(const float* __restrict__ x,
                                             const float* __restrict__ Wp,
                                             const float* __restrict__ h,
                                             float* __restrict__ out) {
    extern __shared__ char fsm[];
    float*  xs = (float*)fsm;                      // 1024 floats
    float*  ws = (float*)(fsm + 4096);             // 64 x 256 floats
    double* Ls = (double*)(fsm + 4096 + 65536);    // 256 doubles
    int n = g_cnt; if (n > MAXF) n = MAXF;
    const int tid = threadIdx.x;

    for (int f = blockIdx.x; f < n; f += gridDim.x) {
        int bg = g_flags[f].x, r = g_flags[f].y;
        __syncthreads();
        for (int k = tid; k < 1024; k += 256) xs[k] = x[(size_t)bg * DM + k];

        double s0 = 0, s1 = 0, s2 = 0, s3 = 0;
        #pragma unroll 1
        for (int kc = 0; kc < 1024; kc += 64) {
            __syncthreads();
            #pragma unroll
            for (int i = 0; i < 16; i++) {
                int idx = tid + i * 256;
                int row = idx >> 6, c4 = idx & 63;
                *(float4*)&ws[row * 256 + c4 * 4] =
                    *(const float4*)(Wp + (size_t)(kc + row) * (RNUM * 256) + r * 256 + c4 * 4);
            }
            __syncthreads();
            #pragma unroll
            for (int rr = 0; rr < 64; rr += 4) {
                s0 += (double)xs[kc + rr + 0] * (double)ws[(rr + 0) * 256 + tid];
                s1 += (double)xs[kc + rr + 1] * (double)ws[(rr + 1) * 256 + tid];
                s2 += (double)xs[kc + rr + 2] * (double)ws[(rr + 2) * 256 + tid];
                s3 += (double)xs[kc + rr + 3] * (double)ws[(rr + 3) * 256 + tid];
            }
        }
        Ls[tid] = 2.0 * ((s0 + s1) + (s2 + s3));
        __syncthreads();

        if (tid < 16) {
            const unsigned M16 = 0xFFFFu;
            int j = tid;
            double L[16];
            #pragma unroll
            for (int i = 0; i < 16; i++) L[i] = Ls[i * 16 + j];
            #pragma unroll 1
            for (int it = 0; it < 5; it++) {
                #pragma unroll 1
                for (int i = 0; i < 16; i++) {
                    double mx = L[i];
                    mx = fmax(mx, __shfl_xor_sync(M16, mx, 1));
                    mx = fmax(mx, __shfl_xor_sync(M16, mx, 2));
                    mx = fmax(mx, __shfl_xor_sync(M16, mx, 4));
                    mx = fmax(mx, __shfl_xor_sync(M16, mx, 8));
                    double e = exp(L[i] - mx);
                    e += __shfl_xor_sync(M16, e, 1);
                    e += __shfl_xor_sync(M16, e, 2);
                    e += __shfl_xor_sync(M16, e, 4);
                    e += __shfl_xor_sync(M16, e, 8);
                    L[i] -= mx + log(e);
                }
                if (it < 4) {
                    double mx = L[0];
                    #pragma unroll
                    for (int i = 1; i < 16; i++) mx = fmax(mx, L[i]);
                    double ss = 0.0;
                    #pragma unroll
                    for (int i = 0; i < 16; i++) ss += exp(L[i] - mx);
                    double sub = mx + log(ss);
                    #pragma unroll
                    for (int i = 0; i < 16; i++) L[i] -= sub;
                }
            }
            int best = 0; double bv = L[0];
            #pragma unroll
            for (int i = 1; i < 16; i++)
                if (L[i] > bv) { bv = L[i]; best = i; }

            float hv = h[(size_t)bg * DM + r * 16 + j];
            float hp = 0.f;
            #pragma unroll
            for (int jj = 0; jj < 16; jj++) {
                int   ib = __shfl_sync(M16, best, jj);
                float hj = __shfl_sync(M16, hv,   jj);
                if (ib == j) hp += hj;
            }
            int oi = bg * DM + r * 16 + j;
            out[oi] = g_dv[oi] * hp;
        }
    }
}

// ---------------- launch ----------------
extern "C" void kernel_launch(void* const* d_in, const int* in_sizes, int n_in,
                              void* d_out, int out_size) {
    const float* x  = (const float*)d_in[0];
    const float* h  = (const float*)d_in[1];
    const float* Wp = (const float*)d_in[2];
    const float* Wd = (const float*)d_in[3];
    const float* Wa = (const float*)d_in[4];
    float* out = (float*)d_out;

    cudaFuncSetAttribute(perm_mma, cudaFuncAttributeMaxDynamicSharedMemorySize, SMEMSZ);
    cudaFuncSetAttribute(diag_mma, cudaFuncAttributeMaxDynamicSharedMemorySize, SMEMSZ);
    cudaFuncSetAttribute(fixup,    cudaFuncAttributeMaxDynamicSharedMemorySize, FIXSMEM);

    conv_x<<<BATCH * DM / 256, 256>>>(x);
    tr_wp<<<dim3(512, 32), dim3(32, 8)>>>(Wp);
    tr_wc<<<dim3(32, 32), dim3(32, 8)>>>(Wd, Wa);
    diag_mma<<<dim3(16, 8), 512, SMEMSZ>>>();
    perm_mma<<<dim3(16, 64), 512, SMEMSZ>>>(h, out);
    fixup<<<512, 256, FIXSMEM>>>(x, Wp, h, out);
}

// round 14
// speedup vs baseline: 1.1715x; 1.0276x over previous
#include <cuda_runtime.h>
#include <cuda_fp16.h>
#include <cstdint>
#include <math.h>

#define BATCH 2048
#define DM    1024
#define RNUM  64
#define KH    3072          // concat K in halfs
#define KT    64            // k-tile in halfs (128 B rows)
#define NKT   (KH / KT)     // 48
#define ABLK  8192          // A tile block halfs (128 x 64) = 16 KB
#define BBLK  16384         // B tile block halfs (256 x 64) = 32 KB
#define STGB  49152         // stage bytes (A+B)
#define NSTG  4
#define CSTR  257
#define MAXF  16384
#define SMEMSZ (1024 + NSTG * STGB)
#define SC    64.0f
#define FIXSMEM (4096 + 65536 + 2048)

// ---------------- device scratch ----------------
__device__ float  g_dv[BATCH * DM];
__device__ __half g_xc[BATCH * KH];           // tiled [mtile][kt][row128][64] swizzled
__device__ __half g_wpc[RNUM * 256 * KH];     // tiled [r][kt][row256][64]
__device__ __half g_wc[2 * DM * KH];          // tiled [nt8][kt][row256][64]
__device__ int    g_cnt;
__device__ int2   g_flags[MAXF];

// ---------------- helpers ----------------
__device__ __forceinline__ uint32_t smem_u32(const void* p) {
    uint32_t a;
    asm("{ .reg .u64 t; cvta.to.shared.u64 t, %1; cvt.u32.u64 %0, t; }" : "=r"(a) : "l"(p));
    return a;
}
__device__ __forceinline__ void ldsm4(uint32_t* r, uint32_t a) {
    asm volatile("ldmatrix.sync.aligned.m8n8.x4.shared.b16 {%0,%1,%2,%3}, [%4];"
                 : "=r"(r[0]), "=r"(r[1]), "=r"(r[2]), "=r"(r[3]) : "r"(a));
}
// precise e^x via FMA-only polynomial
__device__ __forceinline__ float exp_p(float x) {
    x = fmaxf(x, -80.0f);
    float n = rintf(x * 1.4426950408889634f);
    float r = fmaf(n, -0.693359375f, x);
    r = fmaf(n, 2.12194440e-4f, r);
    float p = 1.9875691500e-4f;
    p = fmaf(p, r, 1.3981999507e-3f);
    p = fmaf(p, r, 8.3334519073e-3f);
    p = fmaf(p, r, 4.1665795894e-2f);
    p = fmaf(p, r, 1.6666665459e-1f);
    p = fmaf(p, r, 5.0000001201e-1f);
    float q = fmaf(p, r * r, r) + 1.0f;
    return q * __int_as_float(((int)n + 127) << 23);
}
__device__ __forceinline__ float rcp_p(float x) {
    float r;
    asm("rcp.approx.f32 %0, %1;" : "=f"(r) : "f"(x));
    float e = fmaf(-x, r, 1.0f);
    return fmaf(r, e, r);
}
#define MBAR_INIT(a, c) asm volatile("mbarrier.init.shared.b64 [%0], %1;" :: "r"(a), "r"(c) : "memory")
#define MBAR_EXPECT(a, b) asm volatile("mbarrier.arrive.expect_tx.shared.b64 _, [%0], %1;" :: "r"(a), "r"(b) : "memory")
#define MBAR_ARRIVE(a) asm volatile("mbarrier.arrive.shared.b64 _, [%0];" :: "r"(a) : "memory")
#define BULK(dst, src, sz, mb) \
    asm volatile("cp.async.bulk.shared::cluster.global.mbarrier::complete_tx::bytes [%0], [%1], %2, [%3];" \
                 :: "r"(dst), "l"(src), "r"(sz), "r"(mb) : "memory")
__device__ __forceinline__ void mbar_wait(uint32_t a, uint32_t ph) {
    asm volatile(
        "{\n.reg .pred P;\n"
        "WL%=:\n"
        "mbarrier.try_wait.parity.acquire.cta.shared::cta.b64 P, [%0], %1, 0x989680;\n"
        "@P bra WD%=;\n"
        "bra WL%=;\n"
        "WD%=:\n}"
        :: "r"(a), "r"(ph) : "memory");
}

#define MMA_F16(c, a0, a1, a2, a3, b0, b1) \
    asm volatile("mma.sync.aligned.m16n8k16.row.col.f32.f16.f16.f32 " \
        "{%0,%1,%2,%3}, {%4,%5,%6,%7}, {%8,%9}, {%0,%1,%2,%3};" \
        : "+f"((c)[0]), "+f"((c)[1]), "+f"((c)[2]), "+f"((c)[3]) \
        : "r"(a0), "r"(a1), "r"(a2), "r"(a3), "r"(b0), "r"(b1))

// ---------------- fused prep kernel ----------------
// blocks [0,1024): conv_x ; [1024, 9216): tr_wp ; [9216, 9728): tr_wc
// All writes are 16B uint4 (8 contiguous halfs; swizzle is 8-half granular).
__global__ __launch_bounds__(256) void prep_all(const float* __restrict__ x,
                                                const float* __restrict__ Wp,
                                                const float* __restrict__ Wd,
                                                const float* __restrict__ Wa) {
    __shared__ float ts[2 * 64 * 33];
    const int bid = blockIdx.x, tid = threadIdx.x;
    if (bid == 0 && tid == 0) g_cnt = 0;

    if (bid < 1024) {
        // ---- conv_x: 8 consecutive k per thread ----
        int idx = bid * 2048 + tid * 8;
        int m = idx >> 10, k8 = idx & 1023;
        float4 v0 = *(const float4*)(x + idx);
        float4 v1 = *(const float4*)(x + idx + 4);
        float v[8] = {v0.x, v0.y, v0.z, v0.w, v1.x, v1.y, v1.z, v1.w};
        __half hh[8], hm[8], hl[8];
        #pragma unroll
        for (int u = 0; u < 8; u++) {
            hh[u] = __float2half_rn(v[u]);
            float hf = __half2float(hh[u]);
            hm[u] = __float2half_rn(hf * (1.0f / SC));
            hl[u] = __float2half_rn((v[u] - hf) * SC);
        }
        int row = m & 127;
        int col = (k8 & 63) ^ ((row & 7) << 3);
        size_t base = ((size_t)((m >> 7) * NKT + (k8 >> 6)) * 128 + row) * 64 + col;
        *(uint4*)(g_xc + base)          = *(uint4*)hh;   // slice0: hh
        *(uint4*)(g_xc + base + 131072) = *(uint4*)hm;   // slice1: hf/SC
        *(uint4*)(g_xc + base + 262144) = *(uint4*)hl;   // slice2: lo*SC
    } else if (bid < 9216) {
        // ---- tr_wp: 64k x 32n tile ----
        int b2 = bid - 1024;
        int k0 = (b2 & 15) * 64, n0 = (b2 >> 4) * 32, kb = b2 & 15;
        #pragma unroll
        for (int i = 0; i < 8; i++) {
            int kk = (tid >> 5) + i * 8, nn = tid & 31;
            ts[kk * 33 + nn] = Wp[(size_t)(k0 + kk) * (RNUM * 256) + n0 + nn];
        }
        __syncthreads();
        int n = tid >> 3, kg = tid & 7;
        int ng = n0 + n, r = ng >> 8, nr = ng & 255;
        __half hh[8], hl[8], hm[8];
        #pragma unroll
        for (int u = 0; u < 8; u++) {
            float v = ts[(kg * 8 + u) * 33 + n];
            hh[u] = __float2half_rn(v);
            float hf = __half2float(hh[u]);
            hl[u] = __float2half_rn((v - hf) * SC);
            hm[u] = __float2half_rn(hf * (1.0f / SC));
        }
        int col = (kg * 8) ^ ((nr & 7) << 3);
        size_t base = ((size_t)(r * NKT + kb) * 256 + nr) * 64 + col;
        *(uint4*)(g_wpc + base)          = *(uint4*)hh;  // slice0: hh
        *(uint4*)(g_wpc + base + 262144) = *(uint4*)hl;  // slice1: lo*SC
        *(uint4*)(g_wpc + base + 524288) = *(uint4*)hm;  // slice2: hf/SC
    } else {
        // ---- tr_wc: 64k x 32n tile, both Wd/Wa interleaved ----
        int b3 = bid - 9216;
        int k0 = (b3 & 15) * 64, n0 = (b3 >> 4) * 32, kb = b3 & 15;
        #pragma unroll
        for (int i = 0; i < 8; i++) {
            int kk = (tid >> 5) + i * 8, nn = tid & 31;
            ts[kk * 33 + nn]           = Wd[(size_t)(k0 + kk) * DM + n0 + nn];
            ts[64 * 33 + kk * 33 + nn] = Wa[(size_t)(k0 + kk) * DM + n0 + nn];
        }
        __syncthreads();
        int n = tid >> 3, kg = tid & 7;
        #pragma unroll
        for (int s = 0; s < 2; s++) {
            __half hh[8], hl[8], hm[8];
            #pragma unroll
            for (int u = 0; u < 8; u++) {
                float v = ts[s * 64 * 33 + (kg * 8 + u) * 33 + n];
                hh[u] = __float2half_rn(v);
                float hf = __half2float(hh[u]);
                hl[u] = __float2half_rn((v - hf) * SC);
                hm[u] = __float2half_rn(hf * (1.0f / SC));
            }
            int col2 = 2 * (n0 + n) + s;
            int nt = col2 >> 8, row = col2 & 255;
            int col = (kg * 8) ^ ((row & 7) << 3);
            size_t base = ((size_t)(nt * NKT + kb) * 256 + row) * 64 + col;
            *(uint4*)(g_wc + base)          = *(uint4*)hh;
            *(uint4*)(g_wc + base + 262144) = *(uint4*)hl;
            *(uint4*)(g_wc + base + 524288) = *(uint4*)hm;
        }
    }
}

// ---------------- GEMM core: 16 warps, 64x32 warp tile, ldmatrix.x4 ----------------
__device__ __forceinline__ void compute_tile(uint32_t sA, uint32_t sB,
                                             int wm, int wn, int lane,
                                             float acc[4][4][4]) {
    const uint32_t sz    = (uint32_t)(lane & 7) << 4;
    const uint32_t arow  = (uint32_t)(wm + (lane & 15));
    const uint32_t akoff = (uint32_t)(lane >> 4) << 4;
    const uint32_t brow  = (uint32_t)(wn + (lane & 7) + ((lane >> 4) << 3));
    const uint32_t bkoff = (uint32_t)((lane >> 3) & 1) << 4;
    const uint32_t aBase = sA + arow * 128;
    const uint32_t bBase = sB + brow * 128;

    #pragma unroll
    for (int ks = 0; ks < 4; ks++) {
        uint32_t ko = (uint32_t)ks * 32;
        uint32_t Af[4][4], Bf[2][4];
        #pragma unroll
        for (int fm = 0; fm < 4; fm++)
            ldsm4(Af[fm], aBase + fm * 2048 + ((ko + akoff) ^ sz));
        #pragma unroll
        for (int fp = 0; fp < 2; fp++)
            ldsm4(Bf[fp], bBase + fp * 2048 + ((ko + bkoff) ^ sz));
        #pragma unroll
        for (int fm = 0; fm < 4; fm++)
            #pragma unroll
            for (int fp = 0; fp < 2; fp++) {
                MMA_F16(acc[fm][2 * fp], Af[fm][0], Af[fm][1],
                        Af[fm][2], Af[fm][3], Bf[fp][0], Bf[fp][1]);
                MMA_F16(acc[fm][2 * fp + 1], Af[fm][0], Af[fm][1],
                        Af[fm][2], Af[fm][3], Bf[fp][2], Bf[fp][3]);
            }
    }
}

// 4-stage bulk-copy pipeline with per-stage full/empty mbarriers
// full[s] at sb+16+8s, empty[s] at sb+48+8s, data at sb+1024
#define GEMM_MAINLOOP(Ablocks, Bblocks)                                         \
    float acc[4][4][4] = {};                                                    \
    if (tid == 0) {                                                             \
        _Pragma("unroll")                                                       \
        for (int s = 0; s < NSTG; s++) {                                        \
            MBAR_INIT(sb + 16 + 8 * s, 1);                                      \
            MBAR_INIT(sb + 48 + 8 * s, 16);                                     \
        }                                                                       \
    }                                                                           \
    __syncthreads();                                                            \
    if (tid == 0) {                                                             \
        _Pragma("unroll")                                                       \
        for (int s = 0; s < 3; s++) {                                           \
            uint32_t mb = sb + 16 + 8 * s, st = sb + 1024 + s * STGB;           \
            MBAR_EXPECT(mb, STGB);                                              \
            BULK(st, (const char*)(Ablocks + (size_t)s * ABLK), 16384, mb);     \
            BULK(st + 16384, (const char*)(Bblocks + (size_t)s * BBLK), 32768, mb); \
        }                                                                       \
    }                                                                           \
    for (int kt = 0; kt < NKT; kt++) {                                          \
        int s = kt & 3;                                                         \
        mbar_wait(sb + 16 + 8 * s, (kt >> 2) & 1);                              \
        uint32_t st = sb + 1024 + s * STGB;                                     \
        compute_tile(st, st + 16384, wm, wn, lane, acc);                        \
        __syncwarp();                                                           \
        if (lane == 0) MBAR_ARRIVE(sb + 48 + 8 * s);                            \
        if (tid == 0 && kt + 3 < NKT) {                                         \
            int k2 = kt + 3, s2 = k2 & 3;                                       \
            if (k2 >= 4) mbar_wait(sb + 48 + 8 * s2, ((k2 >> 2) - 1) & 1);      \
            uint32_t mb = sb + 16 + 8 * s2, st2 = sb + 1024 + s2 * STGB;        \
            MBAR_EXPECT(mb, STGB);                                              \
            BULK(st2, (const char*)(Ablocks + (size_t)k2 * ABLK), 16384, mb);   \
            BULK(st2 + 16384, (const char*)(Bblocks + (size_t)k2 * BBLK), 32768, mb); \
        }                                                                       \
    }                                                                           \
    __syncthreads();

// ---------------- diag kernel (512 thr, 16 warps, 64x32 warp tiles) ----------------
__global__ __launch_bounds__(512, 1) void diag_mma() {
    extern __shared__ __align__(1024) char smem[];
    uint32_t sb = smem_u32(smem);
    const int tid = threadIdx.x, wid = tid >> 5, lane = tid & 31;
    const int m0 = blockIdx.x * 128, nt = blockIdx.y;
    const int wm = (wid & 1) * 64, wn = (wid >> 1) * 32;
    const int gid = lane >> 2, qc = lane & 3;
    const int n0 = nt * 256;

    const __half* Ab = g_xc + (size_t)blockIdx.x * NKT * ABLK;
    const __half* Bb = g_wc + (size_t)nt * NKT * BBLK;
    GEMM_MAINLOOP(Ab, Bb)

    #pragma unroll
    for (int fm = 0; fm < 4; fm++)
        #pragma unroll
        for (int fn = 0; fn < 4; fn++) {
            int mm = m0 + wm + fm * 16 + gid;
            int tcol = (n0 + wn + fn * 8 + 2 * qc) >> 1;
            float* c = acc[fm][fn];
            float s0 = 1.0f / (1.0f + expf(-c[1]));
            float s1 = 1.0f / (1.0f + expf(-c[3]));
            g_dv[(size_t)mm * DM + tcol]       = s0 * tanhf(c[0]);
            g_dv[(size_t)(mm + 8) * DM + tcol] = s1 * tanhf(c[2]);
        }
}

// ---------------- perm kernel (512 thr) ----------------
__global__ __launch_bounds__(512, 1) void perm_mma(const float* __restrict__ h,
                                                   float* __restrict__ out) {
    extern __shared__ __align__(1024) char smem[];
    uint32_t sb = smem_u32(smem);
    const int tid = threadIdx.x, wid = tid >> 5, lane = tid & 31;
    const int m0 = blockIdx.x * 128, r = blockIdx.y;
    const int wm = (wid & 1) * 64, wn = (wid >> 1) * 32;
    const int gid = lane >> 2, qc = lane & 3;

    const __half* Ab = g_xc + (size_t)blockIdx.x * NKT * ABLK;
    const __half* Bb = g_wpc + (size_t)r * NKT * BBLK;
    GEMM_MAINLOOP(Ab, Bb)

    float* Csm = (float*)smem;
    #pragma unroll
    for (int fm = 0; fm < 4; fm++)
        #pragma unroll
        for (int fn = 0; fn < 4; fn++) {
            int mm = wm + fm * 16 + gid, nn = wn + fn * 8 + 2 * qc;
            float* c = acc[fm][fn];
            Csm[mm * CSTR + nn]           = c[0];
            Csm[mm * CSTR + nn + 1]       = c[1];
            Csm[(mm + 8) * CSTR + nn]     = c[2];
            Csm[(mm + 8) * CSTR + nn + 1] = c[3];
        }
    __syncthreads();

    // ---- probability-domain sinkhorn + argmax (+ near-tie flag) + permute ----
    const int j = lane & 15, gb = (lane >> 4) << 4;
    const unsigned FULL = 0xffffffffu;

    #pragma unroll 1
    for (int pass = 0; pass < 4; pass++) {
        int m = pass * 32 + (tid >> 4);
        float p[16];
        #pragma unroll
        for (int i = 0; i < 16; i++) {
            float la = 2.0f * Csm[m * CSTR + i * 16 + j];
            float mx = la;
            mx = fmaxf(mx, __shfl_xor_sync(FULL, mx, 1));
            mx = fmaxf(mx, __shfl_xor_sync(FULL, mx, 2));
            mx = fmaxf(mx, __shfl_xor_sync(FULL, mx, 4));
            mx = fmaxf(mx, __shfl_xor_sync(FULL, mx, 8));
            p[i] = exp_p(la - mx);
        }

        #pragma unroll 1
        for (int it = 0; it < 5; it++) {
            #pragma unroll
            for (int i = 0; i < 16; i++) {
                float s = p[i];
                s += __shfl_xor_sync(FULL, s, 1);
                s += __shfl_xor_sync(FULL, s, 2);
                s += __shfl_xor_sync(FULL, s, 4);
                s += __shfl_xor_sync(FULL, s, 8);
                p[i] *= rcp_p(s);
            }
            if (it < 4) {
                float s = p[0];
                #pragma unroll
                for (int i = 1; i < 16; i++) s += p[i];
                float rc = rcp_p(s);
                #pragma unroll
                for (int i = 0; i < 16; i++) p[i] *= rc;
            }
        }

        int best = 0; float bv = p[0], sv = -1e30f;
        #pragma unroll
        for (int i = 1; i < 16; i++) {
            if (p[i] > bv) { sv = bv; bv = p[i]; best = i; }
            else if (p[i] > sv) sv = p[i];
        }

        int bg = m0 + m;

        unsigned bal = __ballot_sync(FULL, (bv - sv) < 4e-6f * bv);
        if (((bal >> gb) & 0xFFFFu) && lane == gb) {
            int idx = atomicAdd(&g_cnt, 1);
            if (idx < MAXF) g_flags[idx] = make_int2(bg, r);
        }

        float hv = h[(size_t)bg * DM + r * 16 + j];
        float hp = 0.f;
        #pragma unroll
        for (int jj = 0; jj < 16; jj++) {
            int   ib = __shfl_sync(FULL, best, gb + jj);
            float hj = __shfl_sync(FULL, hv,   gb + jj);
            if (ib == j) hp += hj;
        }
        int oi = bg * DM + r * 16 + j;
        out[oi] = g_dv[oi] * hp;
    }
}

// ---------------- exact fixup: smem-staged coalesced, fp64 accum ----------------
__global__ __launch_bounds__(256) void fixup(const float* __restrict__ x,
                                             const float* __restrict__ Wp,
                                             const float* __restrict__ h,
                                             float* __restrict__ out) {
    extern __shared__ char fsm[];
    float*  xs = (float*)fsm;                      // 1024 floats
    float*  ws = (float*)(fsm + 4096);             // 64 x 256 floats
    double* Ls = (double*)(fsm + 4096 + 65536);    // 256 doubles
    int n = g_cnt; if (n > MAXF) n = MAXF;
    const int tid = threadIdx.x;

    for (int f = blockIdx.x; f < n; f += gridDim.x) {
        int bg = g_flags[f].x, r = g_flags[f].y;
        __syncthreads();
        for (int k = tid; k < 1024; k += 256) xs[k] = x[(size_t)bg * DM + k];

        double s0 = 0, s1 = 0, s2 = 0, s3 = 0;
        #pragma unroll 1
        for (int kc = 0; kc < 1024; kc += 64) {
            __syncthreads();
            #pragma unroll
            for (int i = 0; i < 16; i++) {
                int idx = tid + i * 256;
                int row = idx >> 6, c4 = idx & 63;
                *(float4*)&ws[row * 256 + c4 * 4] =
                    *(const float4*)(Wp + (size_t)(kc + row) * (RNUM * 256) + r * 256 + c4 * 4);
            }
            __syncthreads();
            #pragma unroll
            for (int rr = 0; rr < 64; rr += 4) {
                s0 += (double)xs[kc + rr + 0] * (double)ws[(rr + 0) * 256 + tid];
                s1 += (double)xs[kc + rr + 1] * (double)ws[(rr + 1) * 256 + tid];
                s2 += (double)xs[kc + rr + 2] * (double)ws[(rr + 2) * 256 + tid];
                s3 += (double)xs[kc + rr + 3] * (double)ws[(rr + 3) * 256 + tid];
            }
        }
        Ls[tid] = 2.0 * ((s0 + s1) + (s2 + s3));
        __syncthreads();

        if (tid < 16) {
            const unsigned M16 = 0xFFFFu;
            int j = tid;
            double L[16];
            #pragma unroll
            for (int i = 0; i < 16; i++) L[i] = Ls[i * 16 + j];
            #pragma unroll 1
            for (int it = 0; it < 5; it++) {
                #pragma unroll 1
                for (int i = 0; i < 16; i++) {
                    double mx = L[i];
                    mx = fmax(mx, __shfl_xor_sync(M16, mx, 1));
                    mx = fmax(mx, __shfl_xor_sync(M16, mx, 2));
                    mx = fmax(mx, __shfl_xor_sync(M16, mx, 4));
                    mx = fmax(mx, __shfl_xor_sync(M16, mx, 8));
                    double e = exp(L[i] - mx);
                    e += __shfl_xor_sync(M16, e, 1);
                    e += __shfl_xor_sync(M16, e, 2);
                    e += __shfl_xor_sync(M16, e, 4);
                    e += __shfl_xor_sync(M16, e, 8);
                    L[i] -= mx + log(e);
                }
                if (it < 4) {
                    double mx = L[0];
                    #pragma unroll
                    for (int i = 1; i < 16; i++) mx = fmax(mx, L[i]);
                    double ss = 0.0;
                    #pragma unroll
                    for (int i = 0; i < 16; i++) ss += exp(L[i] - mx);
                    double sub = mx + log(ss);
                    #pragma unroll
                    for (int i = 0; i < 16; i++) L[i] -= sub;
                }
            }
            int best = 0; double bv = L[0];
            #pragma unroll
            for (int i = 1; i < 16; i++)
                if (L[i] > bv) { bv = L[i]; best = i; }

            float hv = h[(size_t)bg * DM + r * 16 + j];
            float hp = 0.f;
            #pragma unroll
            for (int jj = 0; jj < 16; jj++) {
                int   ib = __shfl_sync(M16, best, jj);
                float hj = __shfl_sync(M16, hv,   jj);
                if (ib == j) hp += hj;
            }
            int oi = bg * DM + r * 16 + j;
            out[oi] = g_dv[oi] * hp;
        }
    }
}

// ---------------- launch ----------------
extern "C" void kernel_launch(void* const* d_in, const int* in_sizes, int n_in,
                              void* d_out, int out_size) {
    const float* x  = (const float*)d_in[0];
    const float* h  = (const float*)d_in[1];
    const float* Wp = (const float*)d_in[2];
    const float* Wd = (const float*)d_in[3];
    const float* Wa = (const float*)d_in[4];
    float* out = (float*)d_out;

    cudaFuncSetAttribute(perm_mma, cudaFuncAttributeMaxDynamicSharedMemorySize, SMEMSZ);
    cudaFuncSetAttribute(diag_mma, cudaFuncAttributeMaxDynamicSharedMemorySize, SMEMSZ);
    cudaFuncSetAttribute(fixup,    cudaFuncAttributeMaxDynamicSharedMemorySize, FIXSMEM);

    prep_all<<<9728, 256>>>(x, Wp, Wd, Wa);
    diag_mma<<<dim3(16, 8), 512, SMEMSZ>>>();
    perm_mma<<<dim3(16, 64), 512, SMEMSZ>>>(h, out);
    fixup<<<512, 256, FIXSMEM>>>(x, Wp, h, out);
}

// round 15
// speedup vs baseline: 1.3933x; 1.1894x over previous
#include <cuda_runtime.h>
#include <cuda_fp16.h>
#include <cstdint>
#include <math.h>

#define BATCH 2048
#define DM    1024
#define RNUM  64
#define KH    3072          // concat K in halfs
#define KT    64            // k-tile in halfs (128 B rows)
#define NKT   (KH / KT)     // 48
#define ABLK  8192          // A tile block halfs (128 x 64) = 16 KB
#define BBLK  16384         // B tile block halfs (256 x 64) = 32 KB
#define STGB  49152         // stage bytes (A+B)
#define NSTG  4
#define CSTR  257
#define MAXF  16384
#define SMEMSZ (1024 + NSTG * STGB)
#define SC    64.0f
#define FIXSMEM (4096 + 65536 + 2048)

// ---------------- device scratch ----------------
__device__ float  g_dv[BATCH * DM];
__device__ __half g_xc[BATCH * KH];           // tiled [mtile][kt][row128][64] swizzled
__device__ __half g_wpc[RNUM * 256 * KH];     // tiled [r][kt][row256][64]
__device__ __half g_wc[2 * DM * KH];          // tiled [nt8][kt][row256][64]
__device__ int    g_cnt;
__device__ int2   g_flags[MAXF];

// ---------------- helpers ----------------
__device__ __forceinline__ uint32_t smem_u32(const void* p) {
    uint32_t a;
    asm("{ .reg .u64 t; cvta.to.shared.u64 t, %1; cvt.u32.u64 %0, t; }" : "=r"(a) : "l"(p));
    return a;
}
__device__ __forceinline__ void ldsm4(uint32_t* r, uint32_t a) {
    asm volatile("ldmatrix.sync.aligned.m8n8.x4.shared.b16 {%0,%1,%2,%3}, [%4];"
                 : "=r"(r[0]), "=r"(r[1]), "=r"(r[2]), "=r"(r[3]) : "r"(a));
}
// precise e^x via FMA-only polynomial
__device__ __forceinline__ float exp_p(float x) {
    x = fmaxf(x, -80.0f);
    float n = rintf(x * 1.4426950408889634f);
    float r = fmaf(n, -0.693359375f, x);
    r = fmaf(n, 2.12194440e-4f, r);
    float p = 1.9875691500e-4f;
    p = fmaf(p, r, 1.3981999507e-3f);
    p = fmaf(p, r, 8.3334519073e-3f);
    p = fmaf(p, r, 4.1665795894e-2f);
    p = fmaf(p, r, 1.6666665459e-1f);
    p = fmaf(p, r, 5.0000001201e-1f);
    float q = fmaf(p, r * r, r) + 1.0f;
    return q * __int_as_float(((int)n + 127) << 23);
}
__device__ __forceinline__ float rcp_p(float x) {
    float r;
    asm("rcp.approx.f32 %0, %1;" : "=f"(r) : "f"(x));
    float e = fmaf(-x, r, 1.0f);
    return fmaf(r, e, r);
}
#define MBAR_INIT(a, c) asm volatile("mbarrier.init.shared.b64 [%0], %1;" :: "r"(a), "r"(c) : "memory")
#define MBAR_EXPECT(a, b) asm volatile("mbarrier.arrive.expect_tx.shared.b64 _, [%0], %1;" :: "r"(a), "r"(b) : "memory")
#define MBAR_ARRIVE(a) asm volatile("mbarrier.arrive.shared.b64 _, [%0];" :: "r"(a) : "memory")
#define BULK(dst, src, sz, mb) \
    asm volatile("cp.async.bulk.shared::cluster.global.mbarrier::complete_tx::bytes [%0], [%1], %2, [%3];" \
                 :: "r"(dst), "l"(src), "r"(sz), "r"(mb) : "memory")
__device__ __forceinline__ void mbar_wait(uint32_t a, uint32_t ph) {
    asm volatile(
        "{\n.reg .pred P;\n"
        "WL%=:\n"
        "mbarrier.try_wait.parity.acquire.cta.shared::cta.b64 P, [%0], %1, 0x989680;\n"
        "@P bra WD%=;\n"
        "bra WL%=;\n"
        "WD%=:\n}"
        :: "r"(a), "r"(ph) : "memory");
}

#define MMA_F16(c, a0, a1, a2, a3, b0, b1) \
    asm volatile("mma.sync.aligned.m16n8k16.row.col.f32.f16.f16.f32 " \
        "{%0,%1,%2,%3}, {%4,%5,%6,%7}, {%8,%9}, {%0,%1,%2,%3};" \
        : "+f"((c)[0]), "+f"((c)[1]), "+f"((c)[2]), "+f"((c)[3]) \
        : "r"(a0), "r"(a1), "r"(a2), "r"(a3), "r"(b0), "r"(b1))

// ---------------- fused prep kernel ----------------
__global__ __launch_bounds__(256) void prep_all(const float* __restrict__ x,
                                                const float* __restrict__ Wp,
                                                const float* __restrict__ Wd,
                                                const float* __restrict__ Wa) {
    __shared__ float ts[2 * 64 * 33];
    const int bid = blockIdx.x, tid = threadIdx.x;
    if (bid == 0 && tid == 0) g_cnt = 0;

    if (bid < 1024) {
        int idx = bid * 2048 + tid * 8;
        int m = idx >> 10, k8 = idx & 1023;
        float4 v0 = *(const float4*)(x + idx);
        float4 v1 = *(const float4*)(x + idx + 4);
        float v[8] = {v0.x, v0.y, v0.z, v0.w, v1.x, v1.y, v1.z, v1.w};
        __half hh[8], hm[8], hl[8];
        #pragma unroll
        for (int u = 0; u < 8; u++) {
            hh[u] = __float2half_rn(v[u]);
            float hf = __half2float(hh[u]);
            hm[u] = __float2half_rn(hf * (1.0f / SC));
            hl[u] = __float2half_rn((v[u] - hf) * SC);
        }
        int row = m & 127;
        int col = (k8 & 63) ^ ((row & 7) << 3);
        size_t base = ((size_t)((m >> 7) * NKT + (k8 >> 6)) * 128 + row) * 64 + col;
        *(uint4*)(g_xc + base)          = *(uint4*)hh;
        *(uint4*)(g_xc + base + 131072) = *(uint4*)hm;
        *(uint4*)(g_xc + base + 262144) = *(uint4*)hl;
    } else if (bid < 9216) {
        int b2 = bid - 1024;
        int k0 = (b2 & 15) * 64, n0 = (b2 >> 4) * 32, kb = b2 & 15;
        #pragma unroll
        for (int i = 0; i < 8; i++) {
            int kk = (tid >> 5) + i * 8, nn = tid & 31;
            ts[kk * 33 + nn] = Wp[(size_t)(k0 + kk) * (RNUM * 256) + n0 + nn];
        }
        __syncthreads();
        int n = tid >> 3, kg = tid & 7;
        int ng = n0 + n, r = ng >> 8, nr = ng & 255;
        __half hh[8], hl[8], hm[8];
        #pragma unroll
        for (int u = 0; u < 8; u++) {
            float v = ts[(kg * 8 + u) * 33 + n];
            hh[u] = __float2half_rn(v);
            float hf = __half2float(hh[u]);
            hl[u] = __float2half_rn((v - hf) * SC);
            hm[u] = __float2half_rn(hf * (1.0f / SC));
        }
        int col = (kg * 8) ^ ((nr & 7) << 3);
        size_t base = ((size_t)(r * NKT + kb) * 256 + nr) * 64 + col;
        *(uint4*)(g_wpc + base)          = *(uint4*)hh;
        *(uint4*)(g_wpc + base + 262144) = *(uint4*)hl;
        *(uint4*)(g_wpc + base + 524288) = *(uint4*)hm;
    } else {
        int b3 = bid - 9216;
        int k0 = (b3 & 15) * 64, n0 = (b3 >> 4) * 32, kb = b3 & 15;
        #pragma unroll
        for (int i = 0; i < 8; i++) {
            int kk = (tid >> 5) + i * 8, nn = tid & 31;
            ts[kk * 33 + nn]           = Wd[(size_t)(k0 + kk) * DM + n0 + nn];
            ts[64 * 33 + kk * 33 + nn] = Wa[(size_t)(k0 + kk) * DM + n0 + nn];
        }
        __syncthreads();
        int n = tid >> 3, kg = tid & 7;
        #pragma unroll
        for (int s = 0; s < 2; s++) {
            __half hh[8], hl[8], hm[8];
            #pragma unroll
            for (int u = 0; u < 8; u++) {
                float v = ts[s * 64 * 33 + (kg * 8 + u) * 33 + n];
                hh[u] = __float2half_rn(v);
                float hf = __half2float(hh[u]);
                hl[u] = __float2half_rn((v - hf) * SC);
                hm[u] = __float2half_rn(hf * (1.0f / SC));
            }
            int col2 = 2 * (n0 + n) + s;
            int nt = col2 >> 8, row = col2 & 255;
            int col = (kg * 8) ^ ((row & 7) << 3);
            size_t base = ((size_t)(nt * NKT + kb) * 256 + row) * 64 + col;
            *(uint4*)(g_wc + base)          = *(uint4*)hh;
            *(uint4*)(g_wc + base + 262144) = *(uint4*)hl;
            *(uint4*)(g_wc + base + 524288) = *(uint4*)hm;
        }
    }
}

// ---------------- GEMM core: 16 warps, 64x32 warp tile, ldmatrix.x4 ----------------
__device__ __forceinline__ void compute_tile(uint32_t sA, uint32_t sB,
                                             int wm, int wn, int lane,
                                             float acc[4][4][4]) {
    const uint32_t sz    = (uint32_t)(lane & 7) << 4;
    const uint32_t arow  = (uint32_t)(wm + (lane & 15));
    const uint32_t akoff = (uint32_t)(lane >> 4) << 4;
    const uint32_t brow  = (uint32_t)(wn + (lane & 7) + ((lane >> 4) << 3));
    const uint32_t bkoff = (uint32_t)((lane >> 3) & 1) << 4;
    const uint32_t aBase = sA + arow * 128;
    const uint32_t bBase = sB + brow * 128;

    #pragma unroll
    for (int ks = 0; ks < 4; ks++) {
        uint32_t ko = (uint32_t)ks * 32;
        uint32_t Af[4][4], Bf[2][4];
        #pragma unroll
        for (int fm = 0; fm < 4; fm++)
            ldsm4(Af[fm], aBase + fm * 2048 + ((ko + akoff) ^ sz));
        #pragma unroll
        for (int fp = 0; fp < 2; fp++)
            ldsm4(Bf[fp], bBase + fp * 2048 + ((ko + bkoff) ^ sz));
        #pragma unroll
        for (int fm = 0; fm < 4; fm++)
            #pragma unroll
            for (int fp = 0; fp < 2; fp++) {
                MMA_F16(acc[fm][2 * fp], Af[fm][0], Af[fm][1],
                        Af[fm][2], Af[fm][3], Bf[fp][0], Bf[fp][1]);
                MMA_F16(acc[fm][2 * fp + 1], Af[fm][0], Af[fm][1],
                        Af[fm][2], Af[fm][3], Bf[fp][2], Bf[fp][3]);
            }
    }
}

// 4-stage bulk-copy pipeline with per-stage full/empty mbarriers
#define GEMM_MAINLOOP(Ablocks, Bblocks)                                         \
    float acc[4][4][4] = {};                                                    \
    if (tid == 0) {                                                             \
        _Pragma("unroll")                                                       \
        for (int s = 0; s < NSTG; s++) {                                        \
            MBAR_INIT(sb + 16 + 8 * s, 1);                                      \
            MBAR_INIT(sb + 48 + 8 * s, 16);                                     \
        }                                                                       \
    }                                                                           \
    __syncthreads();                                                            \
    if (tid == 0) {                                                             \
        _Pragma("unroll")                                                       \
        for (int s = 0; s < 3; s++) {                                           \
            uint32_t mb = sb + 16 + 8 * s, st = sb + 1024 + s * STGB;           \
            MBAR_EXPECT(mb, STGB);                                              \
            BULK(st, (const char*)(Ablocks + (size_t)s * ABLK), 16384, mb);     \
            BULK(st + 16384, (const char*)(Bblocks + (size_t)s * BBLK), 32768, mb); \
        }                                                                       \
    }                                                                           \
    for (int kt = 0; kt < NKT; kt++) {                                          \
        int s = kt & 3;                                                         \
        mbar_wait(sb + 16 + 8 * s, (kt >> 2) & 1);                              \
        uint32_t st = sb + 1024 + s * STGB;                                     \
        compute_tile(st, st + 16384, wm, wn, lane, acc);                        \
        __syncwarp();                                                           \
        if (lane == 0) MBAR_ARRIVE(sb + 48 + 8 * s);                            \
        if (tid == 0 && kt + 3 < NKT) {                                         \
            int k2 = kt + 3, s2 = k2 & 3;                                       \
            if (k2 >= 4) mbar_wait(sb + 48 + 8 * s2, ((k2 >> 2) - 1) & 1);      \
            uint32_t mb = sb + 16 + 8 * s2, st2 = sb + 1024 + s2 * STGB;        \
            MBAR_EXPECT(mb, STGB);                                              \
            BULK(st2, (const char*)(Ablocks + (size_t)k2 * ABLK), 16384, mb);   \
            BULK(st2 + 16384, (const char*)(Bblocks + (size_t)k2 * BBLK), 32768, mb); \
        }                                                                       \
    }                                                                           \
    __syncthreads();

// ---------------- diag kernel (512 thr, 16 warps, 64x32 warp tiles) ----------------
__global__ __launch_bounds__(512, 1) void diag_mma() {
    extern __shared__ __align__(1024) char smem[];
    uint32_t sb = smem_u32(smem);
    const int tid = threadIdx.x, wid = tid >> 5, lane = tid & 31;
    const int m0 = blockIdx.x * 128, nt = blockIdx.y;
    const int wm = (wid & 1) * 64, wn = (wid >> 1) * 32;
    const int gid = lane >> 2, qc = lane & 3;
    const int n0 = nt * 256;

    const __half* Ab = g_xc + (size_t)blockIdx.x * NKT * ABLK;
    const __half* Bb = g_wc + (size_t)nt * NKT * BBLK;
    GEMM_MAINLOOP(Ab, Bb)

    #pragma unroll
    for (int fm = 0; fm < 4; fm++)
        #pragma unroll
        for (int fn = 0; fn < 4; fn++) {
            int mm = m0 + wm + fm * 16 + gid;
            int tcol = (n0 + wn + fn * 8 + 2 * qc) >> 1;
            float* c = acc[fm][fn];
            float s0 = 1.0f / (1.0f + expf(-c[1]));
            float s1 = 1.0f / (1.0f + expf(-c[3]));
            g_dv[(size_t)mm * DM + tcol]       = s0 * tanhf(c[0]);
            g_dv[(size_t)(mm + 8) * DM + tcol] = s1 * tanhf(c[2]);
        }
}

// ---------------- perm kernel (512 thr) ----------------
__global__ __launch_bounds__(512, 1) void perm_mma(const float* __restrict__ h,
                                                   float* __restrict__ out) {
    extern __shared__ __align__(1024) char smem[];
    uint32_t sb = smem_u32(smem);
    const int tid = threadIdx.x, wid = tid >> 5, lane = tid & 31;
    const int m0 = blockIdx.x * 128, r = blockIdx.y;
    const int wm = (wid & 1) * 64, wn = (wid >> 1) * 32;
    const int gid = lane >> 2, qc = lane & 3;

    const __half* Ab = g_xc + (size_t)blockIdx.x * NKT * ABLK;
    const __half* Bb = g_wpc + (size_t)r * NKT * BBLK;
    GEMM_MAINLOOP(Ab, Bb)

    float* Csm = (float*)smem;
    #pragma unroll
    for (int fm = 0; fm < 4; fm++)
        #pragma unroll
        for (int fn = 0; fn < 4; fn++) {
            int mm = wm + fm * 16 + gid, nn = wn + fn * 8 + 2 * qc;
            float* c = acc[fm][fn];
            Csm[mm * CSTR + nn]           = c[0];
            Csm[mm * CSTR + nn + 1]       = c[1];
            Csm[(mm + 8) * CSTR + nn]     = c[2];
            Csm[(mm + 8) * CSTR + nn + 1] = c[3];
        }
    __syncthreads();

    // ---- probability-domain sinkhorn + argmax (+ near-tie flag) + permute ----
    const int j = lane & 15, gb = (lane >> 4) << 4;
    const unsigned FULL = 0xffffffffu;

    #pragma unroll 1
    for (int pass = 0; pass < 4; pass++) {
        int m = pass * 32 + (tid >> 4);
        float p[16];
        #pragma unroll
        for (int i = 0; i < 16; i++) {
            float la = 2.0f * Csm[m * CSTR + i * 16 + j];
            float mx = la;
            mx = fmaxf(mx, __shfl_xor_sync(FULL, mx, 1));
            mx = fmaxf(mx, __shfl_xor_sync(FULL, mx, 2));
            mx = fmaxf(mx, __shfl_xor_sync(FULL, mx, 4));
            mx = fmaxf(mx, __shfl_xor_sync(FULL, mx, 8));
            p[i] = exp_p(la - mx);
        }

        #pragma unroll 1
        for (int it = 0; it < 5; it++) {
            #pragma unroll
            for (int i = 0; i < 16; i++) {
                float s = p[i];
                s += __shfl_xor_sync(FULL, s, 1);
                s += __shfl_xor_sync(FULL, s, 2);
                s += __shfl_xor_sync(FULL, s, 4);
                s += __shfl_xor_sync(FULL, s, 8);
                p[i] *= rcp_p(s);
            }
            if (it < 4) {
                float s = p[0];
                #pragma unroll
                for (int i = 1; i < 16; i++) s += p[i];
                float rc = rcp_p(s);
                #pragma unroll
                for (int i = 0; i < 16; i++) p[i] *= rc;
            }
        }

        int best = 0; float bv = p[0], sv = -1e30f;
        #pragma unroll
        for (int i = 1; i < 16; i++) {
            if (p[i] > bv) { sv = bv; bv = p[i]; best = i; }
            else if (p[i] > sv) sv = p[i];
        }

        int bg = m0 + m;

        unsigned bal = __ballot_sync(FULL, (bv - sv) < 4e-6f * bv);
        if (((bal >> gb) & 0xFFFFu) && lane == gb) {
            int idx = atomicAdd(&g_cnt, 1);
            if (idx < MAXF) g_flags[idx] = make_int2(bg, r);
        }

        float hv = h[(size_t)bg * DM + r * 16 + j];
        float hp = 0.f;
        #pragma unroll
        for (int jj = 0; jj < 16; jj++) {
            int   ib = __shfl_sync(FULL, best, gb + jj);
            float hj = __shfl_sync(FULL, hv,   gb + jj);
            if (ib == j) hp += hj;
        }
        int oi = bg * DM + r * 16 + j;
        out[oi] = g_dv[oi] * hp;
    }
}

// ---------------- exact fixup: fp64 dot + PARALLEL prob-domain fp64 sinkhorn ----------------
__global__ __launch_bounds__(256) void fixup(const float* __restrict__ x,
                                             const float* __restrict__ Wp,
                                             const float* __restrict__ h,
                                             float* __restrict__ out) {
    extern __shared__ char fsm[];
    float*  xs = (float*)fsm;                      // 1024 floats
    float*  ws = (float*)(fsm + 4096);             // 64 x 256 floats
    double* Ls = (double*)(fsm + 4096 + 65536);    // 256 doubles
    int n = g_cnt; if (n > MAXF) n = MAXF;
    const int tid = threadIdx.x;
    const int jcol = tid & 15;
    const unsigned FULL = 0xffffffffu;

    for (int f = blockIdx.x; f < n; f += gridDim.x) {
        int bg = g_flags[f].x, r = g_flags[f].y;
        __syncthreads();
        for (int k = tid; k < 1024; k += 256) xs[k] = x[(size_t)bg * DM + k];

        double s0 = 0, s1 = 0, s2 = 0, s3 = 0;
        #pragma unroll 1
        for (int kc = 0; kc < 1024; kc += 64) {
            __syncthreads();
            #pragma unroll
            for (int i = 0; i < 16; i++) {
                int idx = tid + i * 256;
                int row = idx >> 6, c4 = idx & 63;
                *(float4*)&ws[row * 256 + c4 * 4] =
                    *(const float4*)(Wp + (size_t)(kc + row) * (RNUM * 256) + r * 256 + c4 * 4);
            }
            __syncthreads();
            #pragma unroll
            for (int rr = 0; rr < 64; rr += 4) {
                s0 += (double)xs[kc + rr + 0] * (double)ws[(rr + 0) * 256 + tid];
                s1 += (double)xs[kc + rr + 1] * (double)ws[(rr + 1) * 256 + tid];
                s2 += (double)xs[kc + rr + 2] * (double)ws[(rr + 2) * 256 + tid];
                s3 += (double)xs[kc + rr + 3] * (double)ws[(rr + 3) * 256 + tid];
            }
        }

        // thread t owns entry (i = t>>4, j = t&15); one exp each, prob-domain sinkhorn
        double p = exp(2.0 * ((s0 + s1) + (s2 + s3)));

        #pragma unroll 1
        for (int it = 0; it < 5; it++) {
            // row normalization: sum over j = lanes within each 16-group
            double s = p;
            s += __shfl_xor_sync(FULL, s, 1);
            s += __shfl_xor_sync(FULL, s, 2);
            s += __shfl_xor_sync(FULL, s, 4);
            s += __shfl_xor_sync(FULL, s, 8);
            p /= s;
            if (it < 4) {   // final col-norm is argmax-invariant per column: skip
                __syncthreads();
                Ls[tid] = p;
                __syncthreads();
                double cs = 0;
                #pragma unroll
                for (int i = 0; i < 16; i++) cs += Ls[i * 16 + jcol];
                p /= cs;
            }
        }
        __syncthreads();
        Ls[tid] = p;
        __syncthreads();

        if (tid < 16) {
            const unsigned M16 = 0xFFFFu;
            int j = tid;
            int best = 0; double bv = Ls[j];
            #pragma unroll
            for (int i = 1; i < 16; i++) {
                double v = Ls[i * 16 + j];
                if (v > bv) { bv = v; best = i; }
            }
            float hv = h[(size_t)bg * DM + r * 16 + j];
            float hp = 0.f;
            #pragma unroll
            for (int jj = 0; jj < 16; jj++) {
                int   ib = __shfl_sync(M16, best, jj);
                float hj = __shfl_sync(M16, hv,   jj);
                if (ib == j) hp += hj;
            }
            int oi = bg * DM + r * 16 + j;
            out[oi] = g_dv[oi] * hp;
        }
    }
}

// ---------------- launch ----------------
extern "C" void kernel_launch(void* const* d_in, const int* in_sizes, int n_in,
                              void* d_out, int out_size) {
    const float* x  = (const float*)d_in[0];
    const float* h  = (const float*)d_in[1];
    const float* Wp = (const float*)d_in[2];
    const float* Wd = (const float*)d_in[3];
    const float* Wa = (const float*)d_in[4];
    float* out = (float*)d_out;

    cudaFuncSetAttribute(perm_mma, cudaFuncAttributeMaxDynamicSharedMemorySize, SMEMSZ);
    cudaFuncSetAttribute(diag_mma, cudaFuncAttributeMaxDynamicSharedMemorySize, SMEMSZ);
    cudaFuncSetAttribute(fixup,    cudaFuncAttributeMaxDynamicSharedMemorySize, FIXSMEM);

    prep_all<<<9728, 256>>>(x, Wp, Wd, Wa);
    diag_mma<<<dim3(16, 8), 512, SMEMSZ>>>();
    perm_mma<<<dim3(16, 64), 512, SMEMSZ>>>(h, out);
    fixup<<<512, 256, FIXSMEM>>>(x, Wp, h, out);
}

// round 16
// speedup vs baseline: 1.7637x; 1.2658x over previous
#include <cuda_runtime.h>
#include <cuda_fp16.h>
#include <cstdint>
#include <math.h>

#define BATCH 2048
#define DM    1024
#define RNUM  64
#define KH    3072          // concat K in halfs
#define KT    64            // k-tile in halfs (128 B rows)
#define NKT   (KH / KT)     // 48
#define ABLK  8192          // A tile block halfs (128 x 64) = 16 KB
#define BBLK  16384         // B tile block halfs (256 x 64) = 32 KB
#define STGB  49152         // stage bytes (A+B)
#define NSTG  4
#define CSTR  257
#define MAXF  16384
#define SMEMSZ (1024 + NSTG * STGB)
#define SC    64.0f
#define FIXSMEM (4096 + 65536 + 2048)

// ---------------- device scratch ----------------
__device__ float  g_dv[BATCH * DM];
__device__ __half g_xc[BATCH * KH];           // tiled [mtile][kt][row128][64] swizzled
__device__ __half g_wpc[RNUM * 256 * KH];     // tiled [r][kt][row256][64]
__device__ __half g_wc[2 * DM * KH];          // tiled [nt8][kt][row256][64]
__device__ int    g_cnt;
__device__ int2   g_flags[MAXF];

// ---------------- helpers ----------------
__device__ __forceinline__ uint32_t smem_u32(const void* p) {
    uint32_t a;
    asm("{ .reg .u64 t; cvta.to.shared.u64 t, %1; cvt.u32.u64 %0, t; }" : "=r"(a) : "l"(p));
    return a;
}
__device__ __forceinline__ void ldsm4(uint32_t* r, uint32_t a) {
    asm volatile("ldmatrix.sync.aligned.m8n8.x4.shared.b16 {%0,%1,%2,%3}, [%4];"
                 : "=r"(r[0]), "=r"(r[1]), "=r"(r[2]), "=r"(r[3]) : "r"(a));
}
// precise e^x via FMA-only polynomial
__device__ __forceinline__ float exp_p(float x) {
    x = fmaxf(x, -80.0f);
    float n = rintf(x * 1.4426950408889634f);
    float r = fmaf(n, -0.693359375f, x);
    r = fmaf(n, 2.12194440e-4f, r);
    float p = 1.9875691500e-4f;
    p = fmaf(p, r, 1.3981999507e-3f);
    p = fmaf(p, r, 8.3334519073e-3f);
    p = fmaf(p, r, 4.1665795894e-2f);
    p = fmaf(p, r, 1.6666665459e-1f);
    p = fmaf(p, r, 5.0000001201e-1f);
    float q = fmaf(p, r * r, r) + 1.0f;
    return q * __int_as_float(((int)n + 127) << 23);
}
__device__ __forceinline__ float rcp_p(float x) {
    float r;
    asm("rcp.approx.f32 %0, %1;" : "=f"(r) : "f"(x));
    float e = fmaf(-x, r, 1.0f);
    return fmaf(r, e, r);
}
// double-single accumulate: (hi,lo) += a*b  (FMA 2-prod + Knuth two-sum)
#define DS_ACC(hi, lo, a, b) do {                    \
    float _p = (a) * (b);                            \
    float _e = fmaf((a), (b), -_p);                  \
    float _t = (hi) + _p;                            \
    float _bp = _t - (hi);                           \
    (lo) += (((hi) - (_t - _bp)) + (_p - _bp)) + _e; \
    (hi) = _t; } while (0)

#define MBAR_INIT(a, c) asm volatile("mbarrier.init.shared.b64 [%0], %1;" :: "r"(a), "r"(c) : "memory")
#define MBAR_EXPECT(a, b) asm volatile("mbarrier.arrive.expect_tx.shared.b64 _, [%0], %1;" :: "r"(a), "r"(b) : "memory")
#define MBAR_ARRIVE(a) asm volatile("mbarrier.arrive.shared.b64 _, [%0];" :: "r"(a) : "memory")
#define BULK(dst, src, sz, mb) \
    asm volatile("cp.async.bulk.shared::cluster.global.mbarrier::complete_tx::bytes [%0], [%1], %2, [%3];" \
                 :: "r"(dst), "l"(src), "r"(sz), "r"(mb) : "memory")
__device__ __forceinline__ void mbar_wait(uint32_t a, uint32_t ph) {
    asm volatile(
        "{\n.reg .pred P;\n"
        "WL%=:\n"
        "mbarrier.try_wait.parity.acquire.cta.shared::cta.b64 P, [%0], %1, 0x989680;\n"
        "@P bra WD%=;\n"
        "bra WL%=;\n"
        "WD%=:\n}"
        :: "r"(a), "r"(ph) : "memory");
}

#define MMA_F16(c, a0, a1, a2, a3, b0, b1) \
    asm volatile("mma.sync.aligned.m16n8k16.row.col.f32.f16.f16.f32 " \
        "{%0,%1,%2,%3}, {%4,%5,%6,%7}, {%8,%9}, {%0,%1,%2,%3};" \
        : "+f"((c)[0]), "+f"((c)[1]), "+f"((c)[2]), "+f"((c)[3]) \
        : "r"(a0), "r"(a1), "r"(a2), "r"(a3), "r"(b0), "r"(b1))

// ---------------- fused prep kernel ----------------
__global__ __launch_bounds__(256) void prep_all(const float* __restrict__ x,
                                                const float* __restrict__ Wp,
                                                const float* __restrict__ Wd,
                                                const float* __restrict__ Wa) {
    __shared__ float ts[2 * 64 * 33];
    const int bid = blockIdx.x, tid = threadIdx.x;
    if (bid == 0 && tid == 0) g_cnt = 0;

    if (bid < 1024) {
        int idx = bid * 2048 + tid * 8;
        int m = idx >> 10, k8 = idx & 1023;
        float4 v0 = *(const float4*)(x + idx);
        float4 v1 = *(const float4*)(x + idx + 4);
        float v[8] = {v0.x, v0.y, v0.z, v0.w, v1.x, v1.y, v1.z, v1.w};
        __half hh[8], hm[8], hl[8];
        #pragma unroll
        for (int u = 0; u < 8; u++) {
            hh[u] = __float2half_rn(v[u]);
            float hf = __half2float(hh[u]);
            hm[u] = __float2half_rn(hf * (1.0f / SC));
            hl[u] = __float2half_rn((v[u] - hf) * SC);
        }
        int row = m & 127;
        int col = (k8 & 63) ^ ((row & 7) << 3);
        size_t base = ((size_t)((m >> 7) * NKT + (k8 >> 6)) * 128 + row) * 64 + col;
        *(uint4*)(g_xc + base)          = *(uint4*)hh;
        *(uint4*)(g_xc + base + 131072) = *(uint4*)hm;
        *(uint4*)(g_xc + base + 262144) = *(uint4*)hl;
    } else if (bid < 9216) {
        int b2 = bid - 1024;
        int k0 = (b2 & 15) * 64, n0 = (b2 >> 4) * 32, kb = b2 & 15;
        #pragma unroll
        for (int i = 0; i < 8; i++) {
            int kk = (tid >> 5) + i * 8, nn = tid & 31;
            ts[kk * 33 + nn] = Wp[(size_t)(k0 + kk) * (RNUM * 256) + n0 + nn];
        }
        __syncthreads();
        int n = tid >> 3, kg = tid & 7;
        int ng = n0 + n, r = ng >> 8, nr = ng & 255;
        __half hh[8], hl[8], hm[8];
        #pragma unroll
        for (int u = 0; u < 8; u++) {
            float v = ts[(kg * 8 + u) * 33 + n];
            hh[u] = __float2half_rn(v);
            float hf = __half2float(hh[u]);
            hl[u] = __float2half_rn((v - hf) * SC);
            hm[u] = __float2half_rn(hf * (1.0f / SC));
        }
        int col = (kg * 8) ^ ((nr & 7) << 3);
        size_t base = ((size_t)(r * NKT + kb) * 256 + nr) * 64 + col;
        *(uint4*)(g_wpc + base)          = *(uint4*)hh;
        *(uint4*)(g_wpc + base + 262144) = *(uint4*)hl;
        *(uint4*)(g_wpc + base + 524288) = *(uint4*)hm;
    } else {
        int b3 = bid - 9216;
        int k0 = (b3 & 15) * 64, n0 = (b3 >> 4) * 32, kb = b3 & 15;
        #pragma unroll
        for (int i = 0; i < 8; i++) {
            int kk = (tid >> 5) + i * 8, nn = tid & 31;
            ts[kk * 33 + nn]           = Wd[(size_t)(k0 + kk) * DM + n0 + nn];
            ts[64 * 33 + kk * 33 + nn] = Wa[(size_t)(k0 + kk) * DM + n0 + nn];
        }
        __syncthreads();
        int n = tid >> 3, kg = tid & 7;
        #pragma unroll
        for (int s = 0; s < 2; s++) {
            __half hh[8], hl[8], hm[8];
            #pragma unroll
            for (int u = 0; u < 8; u++) {
                float v = ts[s * 64 * 33 + (kg * 8 + u) * 33 + n];
                hh[u] = __float2half_rn(v);
                float hf = __half2float(hh[u]);
                hl[u] = __float2half_rn((v - hf) * SC);
                hm[u] = __float2half_rn(hf * (1.0f / SC));
            }
            int col2 = 2 * (n0 + n) + s;
            int nt = col2 >> 8, row = col2 & 255;
            int col = (kg * 8) ^ ((row & 7) << 3);
            size_t base = ((size_t)(nt * NKT + kb) * 256 + row) * 64 + col;
            *(uint4*)(g_wc + base)          = *(uint4*)hh;
            *(uint4*)(g_wc + base + 262144) = *(uint4*)hl;
            *(uint4*)(g_wc + base + 524288) = *(uint4*)hm;
        }
    }
}

// ---------------- GEMM core: 16 warps, 64x32 warp tile, ldmatrix.x4 ----------------
__device__ __forceinline__ void compute_tile(uint32_t sA, uint32_t sB,
                                             int wm, int wn, int lane,
                                             float acc[4][4][4]) {
    const uint32_t sz    = (uint32_t)(lane & 7) << 4;
    const uint32_t arow  = (uint32_t)(wm + (lane & 15));
    const uint32_t akoff = (uint32_t)(lane >> 4) << 4;
    const uint32_t brow  = (uint32_t)(wn + (lane & 7) + ((lane >> 4) << 3));
    const uint32_t bkoff = (uint32_t)((lane >> 3) & 1) << 4;
    const uint32_t aBase = sA + arow * 128;
    const uint32_t bBase = sB + brow * 128;

    #pragma unroll
    for (int ks = 0; ks < 4; ks++) {
        uint32_t ko = (uint32_t)ks * 32;
        uint32_t Af[4][4], Bf[2][4];
        #pragma unroll
        for (int fm = 0; fm < 4; fm++)
            ldsm4(Af[fm], aBase + fm * 2048 + ((ko + akoff) ^ sz));
        #pragma unroll
        for (int fp = 0; fp < 2; fp++)
            ldsm4(Bf[fp], bBase + fp * 2048 + ((ko + bkoff) ^ sz));
        #pragma unroll
        for (int fm = 0; fm < 4; fm++)
            #pragma unroll
            for (int fp = 0; fp < 2; fp++) {
                MMA_F16(acc[fm][2 * fp], Af[fm][0], Af[fm][1],
                        Af[fm][2], Af[fm][3], Bf[fp][0], Bf[fp][1]);
                MMA_F16(acc[fm][2 * fp + 1], Af[fm][0], Af[fm][1],
                        Af[fm][2], Af[fm][3], Bf[fp][2], Bf[fp][3]);
            }
    }
}

// 4-stage bulk-copy pipeline with per-stage full/empty mbarriers
#define GEMM_MAINLOOP(Ablocks, Bblocks)                                         \
    float acc[4][4][4] = {};                                                    \
    if (tid == 0) {                                                             \
        _Pragma("unroll")                                                       \
        for (int s = 0; s < NSTG; s++) {                                        \
            MBAR_INIT(sb + 16 + 8 * s, 1);                                      \
            MBAR_INIT(sb + 48 + 8 * s, 16);                                     \
        }                                                                       \
    }                                                                           \
    __syncthreads();                                                            \
    if (tid == 0) {                                                             \
        _Pragma("unroll")                                                       \
        for (int s = 0; s < 3; s++) {                                           \
            uint32_t mb = sb + 16 + 8 * s, st = sb + 1024 + s * STGB;           \
            MBAR_EXPECT(mb, STGB);                                              \
            BULK(st, (const char*)(Ablocks + (size_t)s * ABLK), 16384, mb);     \
            BULK(st + 16384, (const char*)(Bblocks + (size_t)s * BBLK), 32768, mb); \
        }                                                                       \
    }                                                                           \
    for (int kt = 0; kt < NKT; kt++) {                                          \
        int s = kt & 3;                                                         \
        mbar_wait(sb + 16 + 8 * s, (kt >> 2) & 1);                              \
        uint32_t st = sb + 1024 + s * STGB;                                     \
        compute_tile(st, st + 16384, wm, wn, lane, acc);                        \
        __syncwarp();                                                           \
        if (lane == 0) MBAR_ARRIVE(sb + 48 + 8 * s);                            \
        if (tid == 0 && kt + 3 < NKT) {                                         \
            int k2 = kt + 3, s2 = k2 & 3;                                       \
            if (k2 >= 4) mbar_wait(sb + 48 + 8 * s2, ((k2 >> 2) - 1) & 1);      \
            uint32_t mb = sb + 16 + 8 * s2, st2 = sb + 1024 + s2 * STGB;        \
            MBAR_EXPECT(mb, STGB);                                              \
            BULK(st2, (const char*)(Ablocks + (size_t)k2 * ABLK), 16384, mb);   \
            BULK(st2 + 16384, (const char*)(Bblocks + (size_t)k2 * BBLK), 32768, mb); \
        }                                                                       \
    }                                                                           \
    __syncthreads();

// ---------------- diag kernel (512 thr, 16 warps, 64x32 warp tiles) ----------------
__global__ __launch_bounds__(512, 1) void diag_mma() {
    extern __shared__ __align__(1024) char smem[];
    uint32_t sb = smem_u32(smem);
    const int tid = threadIdx.x, wid = tid >> 5, lane = tid & 31;
    const int m0 = blockIdx.x * 128, nt = blockIdx.y;
    const int wm = (wid & 1) * 64, wn = (wid >> 1) * 32;
    const int gid = lane >> 2, qc = lane & 3;
    const int n0 = nt * 256;

    const __half* Ab = g_xc + (size_t)blockIdx.x * NKT * ABLK;
    const __half* Bb = g_wc + (size_t)nt * NKT * BBLK;
    GEMM_MAINLOOP(Ab, Bb)

    #pragma unroll
    for (int fm = 0; fm < 4; fm++)
        #pragma unroll
        for (int fn = 0; fn < 4; fn++) {
            int mm = m0 + wm + fm * 16 + gid;
            int tcol = (n0 + wn + fn * 8 + 2 * qc) >> 1;
            float* c = acc[fm][fn];
            float s0 = 1.0f / (1.0f + expf(-c[1]));
            float s1 = 1.0f / (1.0f + expf(-c[3]));
            g_dv[(size_t)mm * DM + tcol]       = s0 * tanhf(c[0]);
            g_dv[(size_t)(mm + 8) * DM + tcol] = s1 * tanhf(c[2]);
        }
}

// ---------------- perm kernel (512 thr) ----------------
__global__ __launch_bounds__(512, 1) void perm_mma(const float* __restrict__ h,
                                                   float* __restrict__ out) {
    extern __shared__ __align__(1024) char smem[];
    uint32_t sb = smem_u32(smem);
    const int tid = threadIdx.x, wid = tid >> 5, lane = tid & 31;
    const int m0 = blockIdx.x * 128, r = blockIdx.y;
    const int wm = (wid & 1) * 64, wn = (wid >> 1) * 32;
    const int gid = lane >> 2, qc = lane & 3;

    const __half* Ab = g_xc + (size_t)blockIdx.x * NKT * ABLK;
    const __half* Bb = g_wpc + (size_t)r * NKT * BBLK;
    GEMM_MAINLOOP(Ab, Bb)

    float* Csm = (float*)smem;
    #pragma unroll
    for (int fm = 0; fm < 4; fm++)
        #pragma unroll
        for (int fn = 0; fn < 4; fn++) {
            int mm = wm + fm * 16 + gid, nn = wn + fn * 8 + 2 * qc;
            float* c = acc[fm][fn];
            Csm[mm * CSTR + nn]           = c[0];
            Csm[mm * CSTR + nn + 1]       = c[1];
            Csm[(mm + 8) * CSTR + nn]     = c[2];
            Csm[(mm + 8) * CSTR + nn + 1] = c[3];
        }
    __syncthreads();

    // ---- probability-domain sinkhorn + argmax (+ near-tie flag) + permute ----
    const int j = lane & 15, gb = (lane >> 4) << 4;
    const unsigned FULL = 0xffffffffu;

    #pragma unroll 1
    for (int pass = 0; pass < 4; pass++) {
        int m = pass * 32 + (tid >> 4);
        float p[16];
        #pragma unroll
        for (int i = 0; i < 16; i++) {
            float la = 2.0f * Csm[m * CSTR + i * 16 + j];
            float mx = la;
            mx = fmaxf(mx, __shfl_xor_sync(FULL, mx, 1));
            mx = fmaxf(mx, __shfl_xor_sync(FULL, mx, 2));
            mx = fmaxf(mx, __shfl_xor_sync(FULL, mx, 4));
            mx = fmaxf(mx, __shfl_xor_sync(FULL, mx, 8));
            p[i] = exp_p(la - mx);
        }

        #pragma unroll 1
        for (int it = 0; it < 5; it++) {
            #pragma unroll
            for (int i = 0; i < 16; i++) {
                float s = p[i];
                s += __shfl_xor_sync(FULL, s, 1);
                s += __shfl_xor_sync(FULL, s, 2);
                s += __shfl_xor_sync(FULL, s, 4);
                s += __shfl_xor_sync(FULL, s, 8);
                p[i] *= rcp_p(s);
            }
            if (it < 4) {
                float s = p[0];
                #pragma unroll
                for (int i = 1; i < 16; i++) s += p[i];
                float rc = rcp_p(s);
                #pragma unroll
                for (int i = 0; i < 16; i++) p[i] *= rc;
            }
        }

        int best = 0; float bv = p[0], sv = -1e30f;
        #pragma unroll
        for (int i = 1; i < 16; i++) {
            if (p[i] > bv) { sv = bv; bv = p[i]; best = i; }
            else if (p[i] > sv) sv = p[i];
        }

        int bg = m0 + m;

        unsigned bal = __ballot_sync(FULL, (bv - sv) < 4e-6f * bv);
        if (((bal >> gb) & 0xFFFFu) && lane == gb) {
            int idx = atomicAdd(&g_cnt, 1);
            if (idx < MAXF) g_flags[idx] = make_int2(bg, r);
        }

        float hv = h[(size_t)bg * DM + r * 16 + j];
        float hp = 0.f;
        #pragma unroll
        for (int jj = 0; jj < 16; jj++) {
            int   ib = __shfl_sync(FULL, best, gb + jj);
            float hj = __shfl_sync(FULL, hv,   gb + jj);
            if (ib == j) hp += hj;
        }
        int oi = bg * DM + r * 16 + j;
        out[oi] = g_dv[oi] * hp;
    }
}

// ---------------- exact fixup: double-single fp32 dot + fp32 prob sinkhorn ----------------
__global__ __launch_bounds__(256) void fixup(const float* __restrict__ x,
                                             const float* __restrict__ Wp,
                                             const float* __restrict__ h,
                                             float* __restrict__ out) {
    extern __shared__ char fsm[];
    float* xs = (float*)fsm;                      // 1024 floats
    float* ws = (float*)(fsm + 4096);             // 64 x 256 floats
    float* Ls = (float*)(fsm + 4096 + 65536);     // 256 floats
    int n = g_cnt; if (n > MAXF) n = MAXF;
    const int tid = threadIdx.x;
    const int jcol = tid & 15;
    const unsigned FULL = 0xffffffffu;

    for (int f = blockIdx.x; f < n; f += gridDim.x) {
        int bg = g_flags[f].x, r = g_flags[f].y;
        __syncthreads();
        for (int k = tid; k < 1024; k += 256) xs[k] = x[(size_t)bg * DM + k];

        float h0 = 0, l0 = 0, h1 = 0, l1 = 0, h2 = 0, l2 = 0, h3 = 0, l3 = 0;
        #pragma unroll 1
        for (int kc = 0; kc < 1024; kc += 64) {
            __syncthreads();
            #pragma unroll
            for (int i = 0; i < 16; i++) {
                int idx = tid + i * 256;
                int row = idx >> 6, c4 = idx & 63;
                *(float4*)&ws[row * 256 + c4 * 4] =
                    *(const float4*)(Wp + (size_t)(kc + row) * (RNUM * 256) + r * 256 + c4 * 4);
            }
            __syncthreads();
            #pragma unroll
            for (int rr = 0; rr < 64; rr += 4) {
                DS_ACC(h0, l0, xs[kc + rr + 0], ws[(rr + 0) * 256 + tid]);
                DS_ACC(h1, l1, xs[kc + rr + 1], ws[(rr + 1) * 256 + tid]);
                DS_ACC(h2, l2, xs[kc + rr + 2], ws[(rr + 2) * 256 + tid]);
                DS_ACC(h3, l3, xs[kc + rr + 3], ws[(rr + 3) * 256 + tid]);
            }
        }
        // combine the 4 DS accumulators (hi exactly, lo to rounding)
        float hi = h0, lo = l0 + l1 + l2 + l3;
        { float t = hi + h1; float bp = t - hi; lo += (hi - (t - bp)) + (h1 - bp); hi = t; }
        { float t = hi + h2; float bp = t - hi; lo += (hi - (t - bp)) + (h2 - bp); hi = t; }
        { float t = hi + h3; float bp = t - hi; lo += (hi - (t - bp)) + (h3 - bp); hi = t; }
        float L = 2.0f * (hi + lo);

        // row max over j (16-lane half of this warp)
        float mx = L;
        mx = fmaxf(mx, __shfl_xor_sync(FULL, mx, 1));
        mx = fmaxf(mx, __shfl_xor_sync(FULL, mx, 2));
        mx = fmaxf(mx, __shfl_xor_sync(FULL, mx, 4));
        mx = fmaxf(mx, __shfl_xor_sync(FULL, mx, 8));
        float p = exp_p(L - mx);

        #pragma unroll 1
        for (int it = 0; it < 5; it++) {
            float s = p;
            s += __shfl_xor_sync(FULL, s, 1);
            s += __shfl_xor_sync(FULL, s, 2);
            s += __shfl_xor_sync(FULL, s, 4);
            s += __shfl_xor_sync(FULL, s, 8);
            p *= rcp_p(s);
            if (it < 4) {   // final col-norm is argmax-invariant: skip
                __syncthreads();
                Ls[tid] = p;
                __syncthreads();
                float cs = 0;
                #pragma unroll
                for (int i = 0; i < 16; i++) cs += Ls[i * 16 + jcol];
                p *= rcp_p(cs);
            }
        }
        __syncthreads();
        Ls[tid] = p;
        __syncthreads();

        if (tid < 16) {
            const unsigned M16 = 0xFFFFu;
            int j = tid;
            int best = 0; float bv = Ls[j];
            #pragma unroll
            for (int i = 1; i < 16; i++) {
                float v = Ls[i * 16 + j];
                if (v > bv) { bv = v; best = i; }
            }
            float hv = h[(size_t)bg * DM + r * 16 + j];
            float hp = 0.f;
            #pragma unroll
            for (int jj = 0; jj < 16; jj++) {
                int   ib = __shfl_sync(M16, best, jj);
                float hj = __shfl_sync(M16, hv,   jj);
                if (ib == j) hp += hj;
            }
            int oi = bg * DM + r * 16 + j;
            out[oi] = g_dv[oi] * hp;
        }
    }
}

// ---------------- launch ----------------
extern "C" void kernel_launch(void* const* d_in, const int* in_sizes, int n_in,
                              void* d_out, int out_size) {
    const float* x  = (const float*)d_in[0];
    const float* h  = (const float*)d_in[1];
    const float* Wp = (const float*)d_in[2];
    const float* Wd = (const float*)d_in[3];
    const float* Wa = (const float*)d_in[4];
    float* out = (float*)d_out;

    cudaFuncSetAttribute(perm_mma, cudaFuncAttributeMaxDynamicSharedMemorySize, SMEMSZ);
    cudaFuncSetAttribute(diag_mma, cudaFuncAttributeMaxDynamicSharedMemorySize, SMEMSZ);
    cudaFuncSetAttribute(fixup,    cudaFuncAttributeMaxDynamicSharedMemorySize, FIXSMEM);

    prep_all<<<9728, 256>>>(x, Wp, Wd, Wa);
    diag_mma<<<dim3(16, 8), 512, SMEMSZ>>>();
    perm_mma<<<dim3(16, 64), 512, SMEMSZ>>>(h, out);
    fixup<<<512, 256, FIXSMEM>>>(x, Wp, h, out);
}

// round 17
// speedup vs baseline: 1.8531x; 1.0507x over previous
#include <cuda_runtime.h>
#include <cuda_fp16.h>
#include <cstdint>
#include <math.h>

#define BATCH 2048
#define DM    1024
#define RNUM  64
#define KH    3072          // concat K in halfs
#define KT    64            // k-tile in halfs (128 B rows)
#define NKT   (KH / KT)     // 48
#define ABLK  8192          // A tile block halfs (128 x 64) = 16 KB
#define BBLK  16384         // B tile block halfs (256 x 64) = 32 KB
#define STGB  49152         // stage bytes (A+B)
#define NSTG  4
#define CSTR  257
#define MAXF  16384
#define SMEMSZ (1024 + NSTG * STGB)
#define SC    64.0f
#define FIXSMEM (4096 + 3 * 65536 + 1024)

// ---------------- device scratch ----------------
__device__ float  g_dv[BATCH * DM];
__device__ __half g_xc[BATCH * KH];           // tiled [mtile][kt][row128][64] swizzled
__device__ __half g_wpc[RNUM * 256 * KH];     // tiled [r][kt][row256][64]
__device__ __half g_wc[2 * DM * KH];          // tiled [nt8][kt][row256][64]
__device__ int    g_cnt;
__device__ int2   g_flags[MAXF];

// ---------------- helpers ----------------
__device__ __forceinline__ uint32_t smem_u32(const void* p) {
    uint32_t a;
    asm("{ .reg .u64 t; cvta.to.shared.u64 t, %1; cvt.u32.u64 %0, t; }" : "=r"(a) : "l"(p));
    return a;
}
__device__ __forceinline__ void ldsm4(uint32_t* r, uint32_t a) {
    asm volatile("ldmatrix.sync.aligned.m8n8.x4.shared.b16 {%0,%1,%2,%3}, [%4];"
                 : "=r"(r[0]), "=r"(r[1]), "=r"(r[2]), "=r"(r[3]) : "r"(a));
}
// precise e^x via FMA-only polynomial
__device__ __forceinline__ float exp_p(float x) {
    x = fmaxf(x, -80.0f);
    float n = rintf(x * 1.4426950408889634f);
    float r = fmaf(n, -0.693359375f, x);
    r = fmaf(n, 2.12194440e-4f, r);
    float p = 1.9875691500e-4f;
    p = fmaf(p, r, 1.3981999507e-3f);
    p = fmaf(p, r, 8.3334519073e-3f);
    p = fmaf(p, r, 4.1665795894e-2f);
    p = fmaf(p, r, 1.6666665459e-1f);
    p = fmaf(p, r, 5.0000001201e-1f);
    float q = fmaf(p, r * r, r) + 1.0f;
    return q * __int_as_float(((int)n + 127) << 23);
}
__device__ __forceinline__ float rcp_p(float x) {
    float r;
    asm("rcp.approx.f32 %0, %1;" : "=f"(r) : "f"(x));
    float e = fmaf(-x, r, 1.0f);
    return fmaf(r, e, r);
}
// double-single accumulate: (hi,lo) += a*b  (FMA 2-prod + Knuth two-sum)
#define DS_ACC(hi, lo, a, b) do {                    \
    float _p = (a) * (b);                            \
    float _e = fmaf((a), (b), -_p);                  \
    float _t = (hi) + _p;                            \
    float _bp = _t - (hi);                           \
    (lo) += (((hi) - (_t - _bp)) + (_p - _bp)) + _e; \
    (hi) = _t; } while (0)

#define MBAR_INIT(a, c) asm volatile("mbarrier.init.shared.b64 [%0], %1;" :: "r"(a), "r"(c) : "memory")
#define MBAR_EXPECT(a, b) asm volatile("mbarrier.arrive.expect_tx.shared.b64 _, [%0], %1;" :: "r"(a), "r"(b) : "memory")
#define MBAR_ARRIVE(a) asm volatile("mbarrier.arrive.shared.b64 _, [%0];" :: "r"(a) : "memory")
#define BULK(dst, src, sz, mb) \
    asm volatile("cp.async.bulk.shared::cluster.global.mbarrier::complete_tx::bytes [%0], [%1], %2, [%3];" \
                 :: "r"(dst), "l"(src), "r"(sz), "r"(mb) : "memory")
#define CPA16(dst, src) asm volatile("cp.async.cg.shared.global [%0], [%1], 16;" :: "r"(dst), "l"(src))
#define CP_COMMIT() asm volatile("cp.async.commit_group;" ::: "memory")
#define CP_WAIT(N)  asm volatile("cp.async.wait_group %0;" :: "n"(N) : "memory")
__device__ __forceinline__ void mbar_wait(uint32_t a, uint32_t ph) {
    asm volatile(
        "{\n.reg .pred P;\n"
        "WL%=:\n"
        "mbarrier.try_wait.parity.acquire.cta.shared::cta.b64 P, [%0], %1, 0x989680;\n"
        "@P bra WD%=;\n"
        "bra WL%=;\n"
        "WD%=:\n}"
        :: "r"(a), "r"(ph) : "memory");
}

#define MMA_F16(c, a0, a1, a2, a3, b0, b1) \
    asm volatile("mma.sync.aligned.m16n8k16.row.col.f32.f16.f16.f32 " \
        "{%0,%1,%2,%3}, {%4,%5,%6,%7}, {%8,%9}, {%0,%1,%2,%3};" \
        : "+f"((c)[0]), "+f"((c)[1]), "+f"((c)[2]), "+f"((c)[3]) \
        : "r"(a0), "r"(a1), "r"(a2), "r"(a3), "r"(b0), "r"(b1))

// ---------------- fused prep kernel ----------------
__global__ __launch_bounds__(256) void prep_all(const float* __restrict__ x,
                                                const float* __restrict__ Wp,
                                                const float* __restrict__ Wd,
                                                const float* __restrict__ Wa) {
    __shared__ float ts[2 * 64 * 33];
    const int bid = blockIdx.x, tid = threadIdx.x;
    if (bid == 0 && tid == 0) g_cnt = 0;

    if (bid < 1024) {
        int idx = bid * 2048 + tid * 8;
        int m = idx >> 10, k8 = idx & 1023;
        float4 v0 = *(const float4*)(x + idx);
        float4 v1 = *(const float4*)(x + idx + 4);
        float v[8] = {v0.x, v0.y, v0.z, v0.w, v1.x, v1.y, v1.z, v1.w};
        __half hh[8], hm[8], hl[8];
        #pragma unroll
        for (int u = 0; u < 8; u++) {
            hh[u] = __float2half_rn(v[u]);
            float hf = __half2float(hh[u]);
            hm[u] = __float2half_rn(hf * (1.0f / SC));
            hl[u] = __float2half_rn((v[u] - hf) * SC);
        }
        int row = m & 127;
        int col = (k8 & 63) ^ ((row & 7) << 3);
        size_t base = ((size_t)((m >> 7) * NKT + (k8 >> 6)) * 128 + row) * 64 + col;
        *(uint4*)(g_xc + base)          = *(uint4*)hh;
        *(uint4*)(g_xc + base + 131072) = *(uint4*)hm;
        *(uint4*)(g_xc + base + 262144) = *(uint4*)hl;
    } else if (bid < 9216) {
        int b2 = bid - 1024;
        int k0 = (b2 & 15) * 64, n0 = (b2 >> 4) * 32, kb = b2 & 15;
        #pragma unroll
        for (int i = 0; i < 8; i++) {
            int kk = (tid >> 5) + i * 8, nn = tid & 31;
            ts[kk * 33 + nn] = Wp[(size_t)(k0 + kk) * (RNUM * 256) + n0 + nn];
        }
        __syncthreads();
        int n = tid >> 3, kg = tid & 7;
        int ng = n0 + n, r = ng >> 8, nr = ng & 255;
        __half hh[8], hl[8], hm[8];
        #pragma unroll
        for (int u = 0; u < 8; u++) {
            float v = ts[(kg * 8 + u) * 33 + n];
            hh[u] = __float2half_rn(v);
            float hf = __half2float(hh[u]);
            hl[u] = __float2half_rn((v - hf) * SC);
            hm[u] = __float2half_rn(hf * (1.0f / SC));
        }
        int col = (kg * 8) ^ ((nr & 7) << 3);
        size_t base = ((size_t)(r * NKT + kb) * 256 + nr) * 64 + col;
        *(uint4*)(g_wpc + base)          = *(uint4*)hh;
        *(uint4*)(g_wpc + base + 262144) = *(uint4*)hl;
        *(uint4*)(g_wpc + base + 524288) = *(uint4*)hm;
    } else {
        int b3 = bid - 9216;
        int k0 = (b3 & 15) * 64, n0 = (b3 >> 4) * 32, kb = b3 & 15;
        #pragma unroll
        for (int i = 0; i < 8; i++) {
            int kk = (tid >> 5) + i * 8, nn = tid & 31;
            ts[kk * 33 + nn]           = Wd[(size_t)(k0 + kk) * DM + n0 + nn];
            ts[64 * 33 + kk * 33 + nn] = Wa[(size_t)(k0 + kk) * DM + n0 + nn];
        }
        __syncthreads();
        int n = tid >> 3, kg = tid & 7;
        #pragma unroll
        for (int s = 0; s < 2; s++) {
            __half hh[8], hl[8], hm[8];
            #pragma unroll
            for (int u = 0; u < 8; u++) {
                float v = ts[s * 64 * 33 + (kg * 8 + u) * 33 + n];
                hh[u] = __float2half_rn(v);
                float hf = __half2float(hh[u]);
                hl[u] = __float2half_rn((v - hf) * SC);
                hm[u] = __float2half_rn(hf * (1.0f / SC));
            }
            int col2 = 2 * (n0 + n) + s;
            int nt = col2 >> 8, row = col2 & 255;
            int col = (kg * 8) ^ ((row & 7) << 3);
            size_t base = ((size_t)(nt * NKT + kb) * 256 + row) * 64 + col;
            *(uint4*)(g_wc + base)          = *(uint4*)hh;
            *(uint4*)(g_wc + base + 262144) = *(uint4*)hl;
            *(uint4*)(g_wc + base + 524288) = *(uint4*)hm;
        }
    }
}

// ---------------- GEMM core: 16 warps, 64x32 warp tile, ldmatrix.x4 ----------------
__device__ __forceinline__ void compute_tile(uint32_t sA, uint32_t sB,
                                             int wm, int wn, int lane,
                                             float acc[4][4][4]) {
    const uint32_t sz    = (uint32_t)(lane & 7) << 4;
    const uint32_t arow  = (uint32_t)(wm + (lane & 15));
    const uint32_t akoff = (uint32_t)(lane >> 4) << 4;
    const uint32_t brow  = (uint32_t)(wn + (lane & 7) + ((lane >> 4) << 3));
    const uint32_t bkoff = (uint32_t)((lane >> 3) & 1) << 4;
    const uint32_t aBase = sA + arow * 128;
    const uint32_t bBase = sB + brow * 128;

    #pragma unroll
    for (int ks = 0; ks < 4; ks++) {
        uint32_t ko = (uint32_t)ks * 32;
        uint32_t Af[4][4], Bf[2][4];
        #pragma unroll
        for (int fm = 0; fm < 4; fm++)
            ldsm4(Af[fm], aBase + fm * 2048 + ((ko + akoff) ^ sz));
        #pragma unroll
        for (int fp = 0; fp < 2; fp++)
            ldsm4(Bf[fp], bBase + fp * 2048 + ((ko + bkoff) ^ sz));
        #pragma unroll
        for (int fm = 0; fm < 4; fm++)
            #pragma unroll
            for (int fp = 0; fp < 2; fp++) {
                MMA_F16(acc[fm][2 * fp], Af[fm][0], Af[fm][1],
                        Af[fm][2], Af[fm][3], Bf[fp][0], Bf[fp][1]);
                MMA_F16(acc[fm][2 * fp + 1], Af[fm][0], Af[fm][1],
                        Af[fm][2], Af[fm][3], Bf[fp][2], Bf[fp][3]);
            }
    }
}

// 4-stage bulk-copy pipeline with per-stage full/empty mbarriers
#define GEMM_MAINLOOP(Ablocks, Bblocks)                                         \
    if (tid == 0) {                                                             \
        _Pragma("unroll")                                                       \
        for (int s = 0; s < NSTG; s++) {                                        \
            MBAR_INIT(sb + 16 + 8 * s, 1);                                      \
            MBAR_INIT(sb + 48 + 8 * s, 16);                                     \
        }                                                                       \
    }                                                                           \
    __syncthreads();                                                            \
    if (tid == 0) {                                                             \
        _Pragma("unroll")                                                       \
        for (int s = 0; s < 3; s++) {                                           \
            uint32_t mb = sb + 16 + 8 * s, st = sb + 1024 + s * STGB;           \
            MBAR_EXPECT(mb, STGB);                                              \
            BULK(st, (const char*)(Ablocks + (size_t)s * ABLK), 16384, mb);     \
            BULK(st + 16384, (const char*)(Bblocks + (size_t)s * BBLK), 32768, mb); \
        }                                                                       \
    }                                                                           \
    for (int kt = 0; kt < NKT; kt++) {                                          \
        int s = kt & 3;                                                         \
        mbar_wait(sb + 16 + 8 * s, (kt >> 2) & 1);                              \
        uint32_t st = sb + 1024 + s * STGB;                                     \
        compute_tile(st, st + 16384, wm, wn, lane, acc);                        \
        __syncwarp();                                                           \
        if (lane == 0) MBAR_ARRIVE(sb + 48 + 8 * s);                            \
        if (tid == 0 && kt + 3 < NKT) {                                         \
            int k2 = kt + 3, s2 = k2 & 3;                                       \
            if (k2 >= 4) mbar_wait(sb + 48 + 8 * s2, ((k2 >> 2) - 1) & 1);      \
            uint32_t mb = sb + 16 + 8 * s2, st2 = sb + 1024 + s2 * STGB;        \
            MBAR_EXPECT(mb, STGB);                                              \
            BULK(st2, (const char*)(Ablocks + (size_t)k2 * ABLK), 16384, mb);   \
            BULK(st2 + 16384, (const char*)(Bblocks + (size_t)k2 * BBLK), 32768, mb); \
        }                                                                       \
    }                                                                           \
    __syncthreads();

// ---------------- merged GEMM kernel: bids [0,1024) = perm, [1024,1152) = diag ----------------
__global__ __launch_bounds__(512, 1) void gemm_all(const float* __restrict__ h,
                                                   float* __restrict__ out) {
    extern __shared__ __align__(1024) char smem[];
    uint32_t sb = smem_u32(smem);
    const int bid = blockIdx.x;
    const int tid = threadIdx.x, wid = tid >> 5, lane = tid & 31;
    const int wm = (wid & 1) * 64, wn = (wid >> 1) * 32;
    const int gid = lane >> 2, qc = lane & 3;
    float acc[4][4][4] = {};

    if (bid >= 1024) {
        // ---------------- diag part ----------------
        const int b = bid - 1024;
        const int m0 = (b & 15) * 128, nt = b >> 4;
        const int n0 = nt * 256;
        const __half* Ab = g_xc + (size_t)(b & 15) * NKT * ABLK;
        const __half* Bb = g_wc + (size_t)nt * NKT * BBLK;
        GEMM_MAINLOOP(Ab, Bb)

        #pragma unroll
        for (int fm = 0; fm < 4; fm++)
            #pragma unroll
            for (int fn = 0; fn < 4; fn++) {
                int mm = m0 + wm + fm * 16 + gid;
                int tcol = (n0 + wn + fn * 8 + 2 * qc) >> 1;
                float* c = acc[fm][fn];
                float s0 = 1.0f / (1.0f + expf(-c[1]));
                float s1 = 1.0f / (1.0f + expf(-c[3]));
                g_dv[(size_t)mm * DM + tcol]       = s0 * tanhf(c[0]);
                g_dv[(size_t)(mm + 8) * DM + tcol] = s1 * tanhf(c[2]);
            }
        return;
    }

    // ---------------- perm part ----------------
    const int m0 = (bid & 15) * 128, r = bid >> 4;
    const __half* Ab = g_xc + (size_t)(bid & 15) * NKT * ABLK;
    const __half* Bb = g_wpc + (size_t)r * NKT * BBLK;
    GEMM_MAINLOOP(Ab, Bb)

    float* Csm = (float*)smem;
    #pragma unroll
    for (int fm = 0; fm < 4; fm++)
        #pragma unroll
        for (int fn = 0; fn < 4; fn++) {
            int mm = wm + fm * 16 + gid, nn = wn + fn * 8 + 2 * qc;
            float* c = acc[fm][fn];
            Csm[mm * CSTR + nn]           = c[0];
            Csm[mm * CSTR + nn + 1]       = c[1];
            Csm[(mm + 8) * CSTR + nn]     = c[2];
            Csm[(mm + 8) * CSTR + nn + 1] = c[3];
        }
    __syncthreads();

    // ---- probability-domain sinkhorn + argmax (+ near-tie flag) + permute ----
    const int j = lane & 15, gb = (lane >> 4) << 4;
    const unsigned FULL = 0xffffffffu;

    #pragma unroll 1
    for (int pass = 0; pass < 4; pass++) {
        int m = pass * 32 + (tid >> 4);
        float p[16];
        #pragma unroll
        for (int i = 0; i < 16; i++) {
            float la = 2.0f * Csm[m * CSTR + i * 16 + j];
            float mx = la;
            mx = fmaxf(mx, __shfl_xor_sync(FULL, mx, 1));
            mx = fmaxf(mx, __shfl_xor_sync(FULL, mx, 2));
            mx = fmaxf(mx, __shfl_xor_sync(FULL, mx, 4));
            mx = fmaxf(mx, __shfl_xor_sync(FULL, mx, 8));
            p[i] = exp_p(la - mx);
        }

        #pragma unroll 1
        for (int it = 0; it < 5; it++) {
            #pragma unroll
            for (int i = 0; i < 16; i++) {
                float s = p[i];
                s += __shfl_xor_sync(FULL, s, 1);
                s += __shfl_xor_sync(FULL, s, 2);
                s += __shfl_xor_sync(FULL, s, 4);
                s += __shfl_xor_sync(FULL, s, 8);
                p[i] *= rcp_p(s);
            }
            if (it < 4) {
                float s = p[0];
                #pragma unroll
                for (int i = 1; i < 16; i++) s += p[i];
                float rc = rcp_p(s);
                #pragma unroll
                for (int i = 0; i < 16; i++) p[i] *= rc;
            }
        }

        int best = 0; float bv = p[0], sv = -1e30f;
        #pragma unroll
        for (int i = 1; i < 16; i++) {
            if (p[i] > bv) { sv = bv; bv = p[i]; best = i; }
            else if (p[i] > sv) sv = p[i];
        }

        int bg = m0 + m;

        unsigned bal = __ballot_sync(FULL, (bv - sv) < 4e-6f * bv);
        if (((bal >> gb) & 0xFFFFu) && lane == gb) {
            int idx = atomicAdd(&g_cnt, 1);
            if (idx < MAXF) g_flags[idx] = make_int2(bg, r);
        }

        float hv = h[(size_t)bg * DM + r * 16 + j];
        float hp = 0.f;
        #pragma unroll
        for (int jj = 0; jj < 16; jj++) {
            int   ib = __shfl_sync(FULL, best, gb + jj);
            float hj = __shfl_sync(FULL, hv,   gb + jj);
            if (ib == j) hp += hj;
        }
        out[bg * DM + r * 16 + j] = hp;     // g_dv applied in finalize
    }
}

// ---------------- exact fixup: cp.async-pipelined DS-fp32 dot + fp32 sinkhorn ----------------
__global__ __launch_bounds__(256) void fixup(const float* __restrict__ x,
                                             const float* __restrict__ Wp,
                                             const float* __restrict__ h,
                                             float* __restrict__ out) {
    extern __shared__ char fsm[];
    float* xs = (float*)fsm;                      // 1024 floats
    float* ws = (float*)(fsm + 4096);             // 3 x 64 x 256 floats
    float* Ls = (float*)(fsm + 4096 + 3 * 65536); // 256 floats
    uint32_t wsb = smem_u32(ws);
    int n = g_cnt; if (n > MAXF) n = MAXF;
    const int tid = threadIdx.x;
    const int jcol = tid & 15;
    const unsigned FULL = 0xffffffffu;

    for (int f = blockIdx.x; f < n; f += gridDim.x) {
        int bg = g_flags[f].x, r = g_flags[f].y;
        __syncthreads();
        for (int k = tid; k < 1024; k += 256) xs[k] = x[(size_t)bg * DM + k];

        // prologue: stage chunks 0..2 via cp.async (chunk = 64 rows of Wp block-col)
        #pragma unroll
        for (int pc = 0; pc < 3; pc++) {
            #pragma unroll
            for (int i = 0; i < 16; i++) {
                int idx = tid + i * 256;
                int row = idx >> 6, c4 = idx & 63;
                CPA16(wsb + pc * 65536 + row * 1024 + c4 * 16,
                      Wp + (size_t)(pc * 64 + row) * (RNUM * 256) + r * 256 + c4 * 4);
            }
            CP_COMMIT();
        }

        float h0 = 0, l0 = 0, h1 = 0, l1 = 0, h2 = 0, l2 = 0, h3 = 0, l3 = 0;
        #pragma unroll 1
        for (int c = 0; c < 16; c++) {
            if (c <= 12) { CP_WAIT(2); } else { CP_WAIT(0); }
            __syncthreads();
            const float* wb = ws + (c % 3) * 16384;
            int kc = c * 64;
            #pragma unroll
            for (int rr = 0; rr < 64; rr += 4) {
                DS_ACC(h0, l0, xs[kc + rr + 0], wb[(rr + 0) * 256 + tid]);
                DS_ACC(h1, l1, xs[kc + rr + 1], wb[(rr + 1) * 256 + tid]);
                DS_ACC(h2, l2, xs[kc + rr + 2], wb[(rr + 2) * 256 + tid]);
                DS_ACC(h3, l3, xs[kc + rr + 3], wb[(rr + 3) * 256 + tid]);
            }
            __syncthreads();
            if (c + 3 < 16) {
                int c2 = c + 3;
                #pragma unroll
                for (int i = 0; i < 16; i++) {
                    int idx = tid + i * 256;
                    int row = idx >> 6, c4 = idx & 63;
                    CPA16(wsb + (c2 % 3) * 65536 + row * 1024 + c4 * 16,
                          Wp + (size_t)(c2 * 64 + row) * (RNUM * 256) + r * 256 + c4 * 4);
                }
                CP_COMMIT();
            }
        }
        // combine the 4 DS accumulators
        float hi = h0, lo = l0 + l1 + l2 + l3;
        { float t = hi + h1; float bp = t - hi; lo += (hi - (t - bp)) + (h1 - bp); hi = t; }
        { float t = hi + h2; float bp = t - hi; lo += (hi - (t - bp)) + (h2 - bp); hi = t; }
        { float t = hi + h3; float bp = t - hi; lo += (hi - (t - bp)) + (h3 - bp); hi = t; }
        float L = 2.0f * (hi + lo);

        float mx = L;
        mx = fmaxf(mx, __shfl_xor_sync(FULL, mx, 1));
        mx = fmaxf(mx, __shfl_xor_sync(FULL, mx, 2));
        mx = fmaxf(mx, __shfl_xor_sync(FULL, mx, 4));
        mx = fmaxf(mx, __shfl_xor_sync(FULL, mx, 8));
        float p = exp_p(L - mx);

        #pragma unroll 1
        for (int it = 0; it < 5; it++) {
            float s = p;
            s += __shfl_xor_sync(FULL, s, 1);
            s += __shfl_xor_sync(FULL, s, 2);
            s += __shfl_xor_sync(FULL, s, 4);
            s += __shfl_xor_sync(FULL, s, 8);
            p *= rcp_p(s);
            if (it < 4) {
                __syncthreads();
                Ls[tid] = p;
                __syncthreads();
                float cs = 0;
                #pragma unroll
                for (int i = 0; i < 16; i++) cs += Ls[i * 16 + jcol];
                p *= rcp_p(cs);
            }
        }
        __syncthreads();
        Ls[tid] = p;
        __syncthreads();

        if (tid < 16) {
            const unsigned M16 = 0xFFFFu;
            int j = tid;
            int best = 0; float bv = Ls[j];
            #pragma unroll
            for (int i = 1; i < 16; i++) {
                float v = Ls[i * 16 + j];
                if (v > bv) { bv = v; best = i; }
            }
            float hv = h[(size_t)bg * DM + r * 16 + j];
            float hp = 0.f;
            #pragma unroll
            for (int jj = 0; jj < 16; jj++) {
                int   ib = __shfl_sync(M16, best, jj);
                float hj = __shfl_sync(M16, hv,   jj);
                if (ib == j) hp += hj;
            }
            out[bg * DM + r * 16 + j] = hp;   // g_dv applied in finalize
        }
    }
}

// ---------------- finalize: out *= g_dv ----------------
__global__ __launch_bounds__(256) void finalize(float* __restrict__ out) {
    int i = (blockIdx.x * 256 + threadIdx.x) * 4;
    float4 o = *(float4*)(out + i);
    float4 d = *(const float4*)(g_dv + i);
    o.x *= d.x; o.y *= d.y; o.z *= d.z; o.w *= d.w;
    *(float4*)(out + i) = o;
}

// ---------------- launch ----------------
extern "C" void kernel_launch(void* const* d_in, const int* in_sizes, int n_in,
                              void* d_out, int out_size) {
    const float* x  = (const float*)d_in[0];
    const float* h  = (const float*)d_in[1];
    const float* Wp = (const float*)d_in[2];
    const float* Wd = (const float*)d_in[3];
    const float* Wa = (const float*)d_in[4];
    float* out = (float*)d_out;

    cudaFuncSetAttribute(gemm_all, cudaFuncAttributeMaxDynamicSharedMemorySize, SMEMSZ);
    cudaFuncSetAttribute(fixup,    cudaFuncAttributeMaxDynamicSharedMemorySize, FIXSMEM);

    prep_all<<<9728, 256>>>(x, Wp, Wd, Wa);
    gemm_all<<<1152, 512, SMEMSZ>>>(h, out);
    fixup<<<512, 256, FIXSMEM>>>(x, Wp, h, out);
    finalize<<<2048, 256>>>(out);
}